// round 2
// baseline (speedup 1.0000x reference)
#include <cuda_runtime.h>

#define FC0   784
#define FCH   2048
#define FCOUT 10

// ---------------- scratch (static device globals; no allocation) ----------------
__device__ float g_x0[FC0], g_l0[FC0], g_h0[FC0];
__device__ float g_z[FCH], g_act[FCH];
__device__ float g_low[FCH], g_high[FCH];
__device__ float g_wl[4 * FCH], g_wh[4 * FCH], g_bhr[4 * FCH];
__device__ float g_Ph[FCH * FCH], g_Qh[FCH * FCH];
__device__ float g_Pl[FCH * FCH], g_Ql[FCH * FCH];
__device__ float g_bh[FCH], g_bl[FCH];
__device__ float g_sPh[FCOUT * FCH], g_sQh[FCOUT * FCH];
__device__ float g_sPl[FCOUT * FCH], g_sQl[FCOUT * FCH];
__device__ float g_part[16 * FCOUT * FCH];

// ---------------- block reduce ----------------
__device__ __forceinline__ float blockReduceSum(float v) {
    __shared__ float sh[32];
    int lane = threadIdx.x & 31;
    int wid  = threadIdx.x >> 5;
#pragma unroll
    for (int o = 16; o > 0; o >>= 1) v += __shfl_down_sync(0xffffffffu, v, o);
    if (lane == 0) sh[wid] = v;
    __syncthreads();
    int nw = blockDim.x >> 5;
    v = (threadIdx.x < nw) ? sh[threadIdx.x] : 0.f;
    if (wid == 0) {
#pragma unroll
        for (int o = 16; o > 0; o >>= 1) v += __shfl_down_sync(0xffffffffu, v, o);
    }
    return v;  // valid on thread 0
}

// ---------------- normalize ----------------
__global__ void norm_k(const float* __restrict__ x, const float* __restrict__ lo,
                       const float* __restrict__ hi, float* __restrict__ x0,
                       float* __restrict__ l0, float* __restrict__ h0) {
    int i = blockIdx.x * blockDim.x + threadIdx.x;
    if (i < FC0) {
        const float mean = 0.1307f, std = 0.3081f;
        x0[i] = (x[i] - mean) / std;
        l0[i] = (lo[i] - mean) / std;
        h0[i] = (hi[i] - mean) / std;
    }
}

// ---------------- forward GEMV: z = W @ x + b ----------------
__global__ void gemv_fwd(const float* __restrict__ W, const float* __restrict__ xin,
                         const float* __restrict__ b, float* __restrict__ z, int K) {
    int row = blockIdx.x;
    const float4* Wr = (const float4*)(W + (size_t)row * K);
    const float4* X4 = (const float4*)xin;
    float s = 0.f;
    for (int k = threadIdx.x; k < (K >> 2); k += blockDim.x) {
        float4 w = Wr[k], xv = X4[k];
        s += w.x * xv.x + w.y * xv.y + w.z * xv.z + w.w * xv.w;
    }
    s = blockReduceSum(s);
    if (threadIdx.x == 0) z[row] = s + b[row];
}

// ---------------- concretize bounds via forward_boxes over input box ----------------
__global__ void bounds_k(const float* __restrict__ M, const float* __restrict__ bias,
                         const float* __restrict__ l0, const float* __restrict__ h0,
                         float* __restrict__ out, int K, int is_high) {
    int row = blockIdx.x;
    const float* Mr = M + (size_t)row * K;
    float s = 0.f;
    for (int k = threadIdx.x; k < K; k += blockDim.x) {
        float m = Mr[k];
        float mn = fminf(m, 0.f), mp = fmaxf(m, 0.f);
        float lv = l0[k], hv = h0[k];
        s += is_high ? (mn * lv + mp * hv) : (mn * hv + mp * lv);
    }
    s = blockReduceSum(s);
    if (threadIdx.x == 0) out[row] = s + bias[row];
}

// ---------------- ReLU relaxation diagonals + forward activation ----------------
__global__ void relu_k(const float* __restrict__ z, const float* __restrict__ low,
                       const float* __restrict__ high, float* __restrict__ act,
                       float* __restrict__ wl, float* __restrict__ wh,
                       float* __restrict__ bhr, int n) {
    int i = blockIdx.x * blockDim.x + threadIdx.x;
    if (i >= n) return;
    float lo = low[i], hi = high[i];
    float w_h, w_l, b_h;
    if (lo < 0.f && hi > 0.f) {
        float d = hi - lo;
        w_h = hi / d;
        b_h = -(lo * hi) / d;
        w_l = (lo * lo > hi * hi) ? 0.f : 1.f;
    } else {
        float keep = (hi <= 0.f) ? 0.f : 1.f;
        w_h = keep; w_l = keep; b_h = 0.f;
    }
    wl[i] = w_l; wh[i] = w_h; bhr[i] = b_h;
    act[i] = fmaxf(z[i], 0.f);
}

// ------- fused (relu backsub transform + relu bias + linear bias) pass -------
// TA[i,k] = mask_k * ( M>0 ? M*s_pos : M*s_neg ), s_pos/s_neg per is_high
// bias_out[i] = bias_in[i] + sum_k [ mask*posneg(M)*bhr[k] + TA[i,k]*blin[k] ]
__global__ void transform_bias_k(const float* __restrict__ Mraw, float* __restrict__ TA,
                                 const float* __restrict__ whv, const float* __restrict__ wlv,
                                 const float* __restrict__ bhrv, const float* __restrict__ blin,
                                 const float* __restrict__ bias_in, float* __restrict__ bias_out,
                                 int K, int is_high) {
    int row = blockIdx.x;
    const float4* Mr  = (const float4*)(Mraw + (size_t)row * K);
    float4*       Tr  = (float4*)(TA + (size_t)row * K);
    const float4* wh4 = (const float4*)whv;
    const float4* wl4 = (const float4*)wlv;
    const float4* bb4 = (const float4*)bhrv;
    const float4* bn4 = (const float4*)blin;
    float s = 0.f;
#define TB_ELEM(mm, hh, ll, bbv, bnv, tout)                          \
    {                                                                \
        float tv = 0.f;                                              \
        if (hh != 0.f) {                                             \
            float spos = is_high ? hh : ll;                          \
            float sneg = is_high ? ll : hh;                          \
            tv = (mm > 0.f) ? mm * spos : mm * sneg;                 \
            float p = is_high ? fmaxf(mm, 0.f) : fminf(mm, 0.f);     \
            s += p * bbv;                                            \
        }                                                            \
        s += tv * bnv;                                               \
        tout = tv;                                                   \
    }
    for (int k = threadIdx.x; k < (K >> 2); k += blockDim.x) {
        float4 m = Mr[k], h = wh4[k], l = wl4[k], bb = bb4[k], bn = bn4[k];
        float4 t;
        TB_ELEM(m.x, h.x, l.x, bb.x, bn.x, t.x);
        TB_ELEM(m.y, h.y, l.y, bb.y, bn.y, t.y);
        TB_ELEM(m.z, h.z, l.z, bb.z, bn.z, t.z);
        TB_ELEM(m.w, h.w, l.w, bb.w, bn.w, t.w);
        Tr[k] = t;
    }
#undef TB_ELEM
    s = blockReduceSum(s);
    if (threadIdx.x == 0) bias_out[row] = bias_in[row] + s;
}

// ---------------- big fp32 GEMM: C[M,N] = A[M,K] @ B[K,N], row-major ----------------
// BM=BN=128, BK=16, 256 threads, 8x8 microtile. M%128==0, K%16==0; N guarded.
__global__ __launch_bounds__(256, 2) void sgemm(const float* __restrict__ A,
                                                const float* __restrict__ B,
                                                float* __restrict__ C,
                                                int M, int N, int K) {
    __shared__ float As[16][132];
    __shared__ float Bs[16][128];
    int tid  = threadIdx.x;
    int arow = tid >> 2;
    int acol = (tid & 3) << 2;
    int brow = tid >> 5;
    int bcol = (tid & 31) << 2;
    int tx = tid & 15, ty = tid >> 4;

    const float* Ab = A + (size_t)(blockIdx.y * 128) * K;
    int n0 = blockIdx.x * 128;

    float acc[8][8];
#pragma unroll
    for (int i = 0; i < 8; i++)
#pragma unroll
        for (int j = 0; j < 8; j++) acc[i][j] = 0.f;

    for (int k0 = 0; k0 < K; k0 += 16) {
        float4 a0 = *(const float4*)(Ab + (size_t)arow * K + k0 + acol);
        float4 a1 = *(const float4*)(Ab + (size_t)(arow + 64) * K + k0 + acol);
        float4 b0 = make_float4(0.f, 0.f, 0.f, 0.f), b1 = b0;
        int gc = n0 + bcol;
        if (gc < N) {
            b0 = *(const float4*)(B + (size_t)(k0 + brow) * N + gc);
            b1 = *(const float4*)(B + (size_t)(k0 + brow + 8) * N + gc);
        }
        __syncthreads();
        As[acol + 0][arow] = a0.x; As[acol + 1][arow] = a0.y;
        As[acol + 2][arow] = a0.z; As[acol + 3][arow] = a0.w;
        As[acol + 0][arow + 64] = a1.x; As[acol + 1][arow + 64] = a1.y;
        As[acol + 2][arow + 64] = a1.z; As[acol + 3][arow + 64] = a1.w;
        *(float4*)&Bs[brow][bcol]     = b0;
        *(float4*)&Bs[brow + 8][bcol] = b1;
        __syncthreads();
#pragma unroll
        for (int kk = 0; kk < 16; kk++) {
            float ar[8], br[8];
            *(float4*)&ar[0] = *(const float4*)&As[kk][ty * 8];
            *(float4*)&ar[4] = *(const float4*)&As[kk][ty * 8 + 4];
            *(float4*)&br[0] = *(const float4*)&Bs[kk][tx * 8];
            *(float4*)&br[4] = *(const float4*)&Bs[kk][tx * 8 + 4];
#pragma unroll
            for (int i = 0; i < 8; i++)
#pragma unroll
                for (int j = 0; j < 8; j++) acc[i][j] += ar[i] * br[j];
        }
    }
    int row0 = blockIdx.y * 128 + ty * 8;
#pragma unroll
    for (int i = 0; i < 8; i++) {
        float* Cr = C + (size_t)(row0 + i) * N;
        int c0 = n0 + tx * 8;
        if (c0 < N)
            *(float4*)(Cr + c0) = make_float4(acc[i][0], acc[i][1], acc[i][2], acc[i][3]);
        if (c0 + 4 < N)
            *(float4*)(Cr + c0 + 4) = make_float4(acc[i][4], acc[i][5], acc[i][6], acc[i][7]);
    }
}

// ------------- skinny GEMM (10 rows): C[10,N] = TA[10,K] @ B[K,N], K==2048 -------------
// grid (ceil(N/256), 16 k-splits), block 64; deterministic 2-stage reduction.
__global__ void sk_gemm(const float* __restrict__ TA, const float* __restrict__ B,
                        float* __restrict__ part, int K, int N) {
    __shared__ float sTA[FCOUT][128];
    int tid   = threadIdx.x;        // 64
    int kb    = blockIdx.y;         // 0..15
    int kbase = kb * 128;           // K == 2048
    int col0  = blockIdx.x * 256 + tid * 4;
    for (int idx = tid; idx < FCOUT * 128; idx += 64) {
        int r = idx >> 7, k = idx & 127;
        sTA[r][k] = TA[(size_t)r * K + kbase + k];
    }
    __syncthreads();
    if (col0 >= N) return;
    float4 acc[FCOUT];
#pragma unroll
    for (int r = 0; r < FCOUT; r++) acc[r] = make_float4(0.f, 0.f, 0.f, 0.f);
    for (int k = 0; k < 128; k++) {
        float4 bv = *(const float4*)(B + (size_t)(kbase + k) * N + col0);
#pragma unroll
        for (int r = 0; r < FCOUT; r++) {
            float sv = sTA[r][k];
            acc[r].x += sv * bv.x; acc[r].y += sv * bv.y;
            acc[r].z += sv * bv.z; acc[r].w += sv * bv.w;
        }
    }
#pragma unroll
    for (int r = 0; r < FCOUT; r++)
        *(float4*)(part + (size_t)(kb * FCOUT + r) * N + col0) = acc[r];
}

__global__ void sk_reduce(const float* __restrict__ part, float* __restrict__ C, int N) {
    int i = blockIdx.x * blockDim.x + threadIdx.x;
    if (i >= FCOUT * N) return;
    int r = i / N, c = i - r * N;
    float s = 0.f;
#pragma unroll
    for (int ks = 0; ks < 16; ks++) s += part[(size_t)(ks * FCOUT + r) * N + c];
    C[(size_t)r * N + c] = s;
}

// ---------------- final output: [x(10), low(10), high(10)] ----------------
__global__ void assemble_k(const float* __restrict__ z, const float* __restrict__ low,
                           const float* __restrict__ high, float* __restrict__ out) {
    int i = threadIdx.x;
    if (i < FCOUT) {
        out[i]      = z[i];
        out[10 + i] = low[i];
        out[20 + i] = high[i];
    }
}

// =======================================================================
extern "C" void kernel_launch(void* const* d_in, const int* in_sizes, int n_in,
                              void* d_out, int out_size) {
    (void)in_sizes; (void)n_in; (void)out_size;
    const float* X  = (const float*)d_in[0];
    const float* LO = (const float*)d_in[1];
    const float* HI = (const float*)d_in[2];
    const float* W[5];
    const float* Bv[5];
    for (int i = 0; i < 5; i++) {
        W[i]  = (const float*)d_in[3 + 2 * i];
        Bv[i] = (const float*)d_in[4 + 2 * i];
    }
    float* out = (float*)d_out;

    float *x0, *l0, *h0, *z, *act, *low, *high, *bh, *bl;
    float *Ph, *Qh, *Pl, *Ql, *sPh, *sQh, *sPl, *sQl, *part;
    float *wlv, *whv, *bhrv;
    cudaGetSymbolAddress((void**)&x0, g_x0);
    cudaGetSymbolAddress((void**)&l0, g_l0);
    cudaGetSymbolAddress((void**)&h0, g_h0);
    cudaGetSymbolAddress((void**)&z, g_z);
    cudaGetSymbolAddress((void**)&act, g_act);
    cudaGetSymbolAddress((void**)&low, g_low);
    cudaGetSymbolAddress((void**)&high, g_high);
    cudaGetSymbolAddress((void**)&bh, g_bh);
    cudaGetSymbolAddress((void**)&bl, g_bl);
    cudaGetSymbolAddress((void**)&Ph, g_Ph);
    cudaGetSymbolAddress((void**)&Qh, g_Qh);
    cudaGetSymbolAddress((void**)&Pl, g_Pl);
    cudaGetSymbolAddress((void**)&Ql, g_Ql);
    cudaGetSymbolAddress((void**)&sPh, g_sPh);
    cudaGetSymbolAddress((void**)&sQh, g_sQh);
    cudaGetSymbolAddress((void**)&sPl, g_sPl);
    cudaGetSymbolAddress((void**)&sQl, g_sQl);
    cudaGetSymbolAddress((void**)&part, g_part);
    cudaGetSymbolAddress((void**)&wlv, g_wl);
    cudaGetSymbolAddress((void**)&whv, g_wh);
    cudaGetSymbolAddress((void**)&bhrv, g_bhr);

    norm_k<<<4, 256>>>(X, LO, HI, x0, l0, h0);

    // ---- layer 1 (i=0): bounds directly from W1 ----
    gemv_fwd<<<FCH, 128>>>(W[0], x0, Bv[0], z, FC0);
    bounds_k<<<FCH, 128>>>(W[0], Bv[0], l0, h0, low, FC0, 0);
    bounds_k<<<FCH, 128>>>(W[0], Bv[0], l0, h0, high, FC0, 1);
    relu_k<<<8, 256>>>(z, low, high, act, wlv, whv, bhrv, FCH);

    // ---- layers 2..4 (i=1..3): full 2048-row backsub chains ----
    for (int i = 1; i <= 3; i++) {
        gemv_fwd<<<FCH, 128>>>(W[i], act, Bv[i], z, FCH);
        for (int hs = 0; hs < 2; hs++) {
            float* P = hs ? Ph : Pl;
            float* Q = hs ? Qh : Ql;
            float* bias = hs ? bh : bl;
            float* outB = hs ? high : low;
            const float* cur = W[i];
            const float* bin = Bv[i];
            int curK = FCH;
            for (int j = i - 1; j >= 0; j--) {
                transform_bias_k<<<FCH, 128>>>(cur, Q, whv + j * FCH, wlv + j * FCH,
                                               bhrv + j * FCH, Bv[j], bin, bias, curK, hs);
                int Nn = (j == 0) ? FC0 : FCH;
                dim3 grid((Nn + 127) / 128, FCH / 128);
                sgemm<<<grid, 256>>>(Q, W[j], P, FCH, Nn, curK);
                cur = P; curK = Nn; bin = bias;
            }
            bounds_k<<<FCH, 128>>>(cur, bias, l0, h0, outB, FC0, hs);
        }
        relu_k<<<8, 256>>>(z, low, high, act, wlv + i * FCH, whv + i * FCH,
                           bhrv + i * FCH, FCH);
    }

    // ---- layer 5 (i=4, 10 rows): skinny chains ----
    gemv_fwd<<<FCOUT, 128>>>(W[4], act, Bv[4], z, FCH);
    for (int hs = 0; hs < 2; hs++) {
        float* P = hs ? sPh : sPl;
        float* Q = hs ? sQh : sQl;
        float* bias = hs ? bh : bl;
        float* outB = hs ? high : low;
        const float* cur = W[4];
        const float* bin = Bv[4];
        int curK = FCH;
        for (int j = 3; j >= 0; j--) {
            transform_bias_k<<<FCOUT, 128>>>(cur, Q, whv + j * FCH, wlv + j * FCH,
                                             bhrv + j * FCH, Bv[j], bin, bias, curK, hs);
            int Nn = (j == 0) ? FC0 : FCH;
            dim3 grid((Nn + 255) / 256, 16);
            sk_gemm<<<grid, 64>>>(Q, W[j], part, curK, Nn);
            sk_reduce<<<(FCOUT * Nn + 255) / 256, 256>>>(part, P, Nn);
            cur = P; curK = Nn; bin = bias;
        }
        bounds_k<<<FCOUT, 128>>>(cur, bias, l0, h0, outB, FC0, hs);
    }

    assemble_k<<<1, 32>>>(z, low, high, out);
}

// round 6
// speedup vs baseline: 2.1429x; 2.1429x over previous
#include <cuda_runtime.h>
#include <cuda_bf16.h>
#include <cstdint>

#define FC0   784
#define FCH   2048
#define FCOUT 10

// ======================= helpers =======================
__device__ __forceinline__ uint32_t smem_u32(const void* p) {
    uint32_t a;
    asm("{ .reg .u64 t; cvta.to.shared.u64 t, %1; cvt.u32.u64 %0, t; }" : "=r"(a) : "l"(p));
    return a;
}

__device__ __forceinline__ void ldmatrix_x4(uint32_t* r, uint32_t addr) {
    asm volatile("ldmatrix.sync.aligned.m8n8.x4.shared.b16 {%0,%1,%2,%3}, [%4];"
                 : "=r"(r[0]), "=r"(r[1]), "=r"(r[2]), "=r"(r[3]) : "r"(addr));
}

__device__ __forceinline__ void mma16816(float* d, const uint32_t* a, const uint32_t* b) {
    asm volatile("mma.sync.aligned.m16n8k16.row.col.f32.bf16.bf16.f32 "
                 "{%0,%1,%2,%3}, {%4,%5,%6,%7}, {%8,%9}, {%0,%1,%2,%3};"
                 : "+f"(d[0]), "+f"(d[1]), "+f"(d[2]), "+f"(d[3])
                 : "r"(a[0]), "r"(a[1]), "r"(a[2]), "r"(a[3]), "r"(b[0]), "r"(b[1]));
}

__device__ __forceinline__ void cp_async16(uint32_t dst, const void* src, int sz) {
    asm volatile("cp.async.cg.shared.global [%0], [%1], 16, %2;"
                 :: "r"(dst), "l"(src), "r"(sz) : "memory");
}
#define CP_COMMIT() asm volatile("cp.async.commit_group;" ::: "memory")
#define CP_WAIT1()  asm volatile("cp.async.wait_group 1;" ::: "memory")

// ======================= scratch (static device globals) =======================
__device__ float g_x0[FC0], g_l0[FC0], g_h0[FC0];
__device__ float g_z[FCH], g_act[FCH];
__device__ float g_low[FCH], g_high[FCH];
__device__ float g_wl[4 * FCH], g_wh[4 * FCH], g_bhr[4 * FCH];
__device__ float g_bh[FCH], g_bl[FCH];
__device__ float g_P[FCH * FCH];
__device__ unsigned short g_TAh[FCH * FCH], g_TAl[FCH * FCH];
__device__ unsigned short g_Wt0h[FC0 * FCH], g_Wt0l[FC0 * FCH];
__device__ unsigned short g_Wt1h[FCH * FCH], g_Wt1l[FCH * FCH];
__device__ unsigned short g_Wt2h[FCH * FCH], g_Wt2l[FCH * FCH];
__device__ unsigned short g_Wt3h[FCH * FCH], g_Wt3l[FCH * FCH];
__device__ float g_sP[FCOUT * FCH], g_sQ[FCOUT * FCH];
__device__ float g_part[16 * FCOUT * FCH];

// ======================= small helper kernels =======================
__device__ __forceinline__ float blockReduceSum(float v) {
    __shared__ float sh[32];
    int lane = threadIdx.x & 31, wid = threadIdx.x >> 5;
#pragma unroll
    for (int o = 16; o > 0; o >>= 1) v += __shfl_down_sync(0xffffffffu, v, o);
    if (lane == 0) sh[wid] = v;
    __syncthreads();
    int nw = blockDim.x >> 5;
    v = (threadIdx.x < nw) ? sh[threadIdx.x] : 0.f;
    if (wid == 0) {
#pragma unroll
        for (int o = 16; o > 0; o >>= 1) v += __shfl_down_sync(0xffffffffu, v, o);
    }
    return v;
}

__global__ void norm_k(const float* __restrict__ x, const float* __restrict__ lo,
                       const float* __restrict__ hi, float* __restrict__ x0,
                       float* __restrict__ l0, float* __restrict__ h0) {
    int i = blockIdx.x * blockDim.x + threadIdx.x;
    if (i < FC0) {
        const float mean = 0.1307f, stdv = 0.3081f;
        x0[i] = (x[i] - mean) / stdv;
        l0[i] = (lo[i] - mean) / stdv;
        h0[i] = (hi[i] - mean) / stdv;
    }
}

__global__ void gemv_fwd(const float* __restrict__ W, const float* __restrict__ xin,
                         const float* __restrict__ b, float* __restrict__ z, int K) {
    int row = blockIdx.x;
    const float4* Wr = (const float4*)(W + (size_t)row * K);
    const float4* X4 = (const float4*)xin;
    float s = 0.f;
    for (int k = threadIdx.x; k < (K >> 2); k += blockDim.x) {
        float4 w = Wr[k], xv = X4[k];
        s += w.x * xv.x + w.y * xv.y + w.z * xv.z + w.w * xv.w;
    }
    s = blockReduceSum(s);
    if (threadIdx.x == 0) z[row] = s + b[row];
}

__global__ void bounds_k(const float* __restrict__ M, const float* __restrict__ bias,
                         const float* __restrict__ l0, const float* __restrict__ h0,
                         float* __restrict__ out, int K, int is_high) {
    int row = blockIdx.x;
    const float* Mr = M + (size_t)row * K;
    float s = 0.f;
    for (int k = threadIdx.x; k < K; k += blockDim.x) {
        float m = Mr[k];
        float mn = fminf(m, 0.f), mp = fmaxf(m, 0.f);
        float lv = l0[k], hv = h0[k];
        s += is_high ? (mn * lv + mp * hv) : (mn * hv + mp * lv);
    }
    s = blockReduceSum(s);
    if (threadIdx.x == 0) out[row] = s + bias[row];
}

__global__ void relu_k(const float* __restrict__ z, const float* __restrict__ low,
                       const float* __restrict__ high, float* __restrict__ act,
                       float* __restrict__ wl, float* __restrict__ wh,
                       float* __restrict__ bhr, int n) {
    int i = blockIdx.x * blockDim.x + threadIdx.x;
    if (i >= n) return;
    float lo = low[i], hi = high[i];
    float w_h, w_l, b_h;
    if (lo < 0.f && hi > 0.f) {
        float d = hi - lo;
        w_h = hi / d;
        b_h = -(lo * hi) / d;
        w_l = (lo * lo > hi * hi) ? 0.f : 1.f;
    } else {
        float keep = (hi <= 0.f) ? 0.f : 1.f;
        w_h = keep; w_l = keep; b_h = 0.f;
    }
    wl[i] = w_l; wh[i] = w_h; bhr[i] = b_h;
    act[i] = fmaxf(z[i], 0.f);
}

// weight transpose + bf16 hi/lo split: W[K,N] fp32 -> Bt_hi/lo[N,K] bf16
__global__ void wt_split(const float* __restrict__ W, unsigned short* __restrict__ Bh,
                         unsigned short* __restrict__ Bl, int K, int N) {
    __shared__ float t[32][33];
    int k0 = blockIdx.y * 32, n0 = blockIdx.x * 32;
    int tx = threadIdx.x, ty = threadIdx.y;  // 32 x 8
#pragma unroll
    for (int i = 0; i < 32; i += 8) {
        int n = n0 + tx;
        t[ty + i][tx] = (n < N) ? W[(size_t)(k0 + ty + i) * N + n] : 0.f;
    }
    __syncthreads();
#pragma unroll
    for (int i = 0; i < 32; i += 8) {
        int n = n0 + ty + i, k = k0 + tx;
        if (n < N) {
            float v = t[tx][ty + i];
            __nv_bfloat16 h = __float2bfloat16(v);
            __nv_bfloat16 l = __float2bfloat16(v - __bfloat162float(h));
            Bh[(size_t)n * K + k] = __bfloat16_as_ushort(h);
            Bl[(size_t)n * K + k] = __bfloat16_as_ushort(l);
        }
    }
}

// fused relu-backsub transform + bias + bf16 hi/lo split output
__global__ void transform_split_k(const float* __restrict__ Mraw,
                                  unsigned short* __restrict__ TAh,
                                  unsigned short* __restrict__ TAl,
                                  const float* __restrict__ whv, const float* __restrict__ wlv,
                                  const float* __restrict__ bhrv, const float* __restrict__ blin,
                                  const float* __restrict__ bias_in, float* __restrict__ bias_out,
                                  int K, int is_high) {
    int row = blockIdx.x;
    const float4* Mr  = (const float4*)(Mraw + (size_t)row * K);
    const float4* wh4 = (const float4*)whv;
    const float4* wl4 = (const float4*)wlv;
    const float4* bb4 = (const float4*)bhrv;
    const float4* bn4 = (const float4*)blin;
    uint2* TH = (uint2*)(TAh + (size_t)row * K);
    uint2* TL = (uint2*)(TAl + (size_t)row * K);
    float s = 0.f;
#define TB_ELEM(mm, hh, ll, bbv, bnv, tout)                          \
    {                                                                \
        float tv = 0.f;                                              \
        if (hh != 0.f) {                                             \
            float spos = is_high ? hh : ll;                          \
            float sneg = is_high ? ll : hh;                          \
            tv = (mm > 0.f) ? mm * spos : mm * sneg;                 \
            float p = is_high ? fmaxf(mm, 0.f) : fminf(mm, 0.f);     \
            s += p * bbv;                                            \
        }                                                            \
        s += tv * bnv;                                               \
        tout = tv;                                                   \
    }
    for (int k = threadIdx.x; k < (K >> 2); k += blockDim.x) {
        float4 m = Mr[k], h = wh4[k], l = wl4[k], bb = bb4[k], bn = bn4[k];
        float4 t;
        TB_ELEM(m.x, h.x, l.x, bb.x, bn.x, t.x);
        TB_ELEM(m.y, h.y, l.y, bb.y, bn.y, t.y);
        TB_ELEM(m.z, h.z, l.z, bb.z, bn.z, t.z);
        TB_ELEM(m.w, h.w, l.w, bb.w, bn.w, t.w);
        __nv_bfloat16 h0 = __float2bfloat16(t.x), h1 = __float2bfloat16(t.y);
        __nv_bfloat16 h2 = __float2bfloat16(t.z), h3 = __float2bfloat16(t.w);
        __nv_bfloat16 l0 = __float2bfloat16(t.x - __bfloat162float(h0));
        __nv_bfloat16 l1 = __float2bfloat16(t.y - __bfloat162float(h1));
        __nv_bfloat16 l2 = __float2bfloat16(t.z - __bfloat162float(h2));
        __nv_bfloat16 l3 = __float2bfloat16(t.w - __bfloat162float(h3));
        uint2 uh, ul;
        uh.x = (uint32_t)__bfloat16_as_ushort(h0) | ((uint32_t)__bfloat16_as_ushort(h1) << 16);
        uh.y = (uint32_t)__bfloat16_as_ushort(h2) | ((uint32_t)__bfloat16_as_ushort(h3) << 16);
        ul.x = (uint32_t)__bfloat16_as_ushort(l0) | ((uint32_t)__bfloat16_as_ushort(l1) << 16);
        ul.y = (uint32_t)__bfloat16_as_ushort(l2) | ((uint32_t)__bfloat16_as_ushort(l3) << 16);
        TH[k] = uh;
        TL[k] = ul;
    }
#undef TB_ELEM
    s = blockReduceSum(s);
    if (threadIdx.x == 0) bias_out[row] = bias_in[row] + s;
}

// fp32 transform for the skinny (10-row) chain
__global__ void transform_f32_k(const float* __restrict__ Mraw, float* __restrict__ TA,
                                const float* __restrict__ whv, const float* __restrict__ wlv,
                                const float* __restrict__ bhrv, const float* __restrict__ blin,
                                const float* __restrict__ bias_in, float* __restrict__ bias_out,
                                int K, int is_high) {
    int row = blockIdx.x;
    const float4* Mr  = (const float4*)(Mraw + (size_t)row * K);
    float4*       Tr  = (float4*)(TA + (size_t)row * K);
    const float4* wh4 = (const float4*)whv;
    const float4* wl4 = (const float4*)wlv;
    const float4* bb4 = (const float4*)bhrv;
    const float4* bn4 = (const float4*)blin;
    float s = 0.f;
#define TB_ELEM(mm, hh, ll, bbv, bnv, tout)                          \
    {                                                                \
        float tv = 0.f;                                              \
        if (hh != 0.f) {                                             \
            float spos = is_high ? hh : ll;                          \
            float sneg = is_high ? ll : hh;                          \
            tv = (mm > 0.f) ? mm * spos : mm * sneg;                 \
            float p = is_high ? fmaxf(mm, 0.f) : fminf(mm, 0.f);     \
            s += p * bbv;                                            \
        }                                                            \
        s += tv * bnv;                                               \
        tout = tv;                                                   \
    }
    for (int k = threadIdx.x; k < (K >> 2); k += blockDim.x) {
        float4 m = Mr[k], h = wh4[k], l = wl4[k], bb = bb4[k], bn = bn4[k];
        float4 t;
        TB_ELEM(m.x, h.x, l.x, bb.x, bn.x, t.x);
        TB_ELEM(m.y, h.y, l.y, bb.y, bn.y, t.y);
        TB_ELEM(m.z, h.z, l.z, bb.z, bn.z, t.z);
        TB_ELEM(m.w, h.w, l.w, bb.w, bn.w, t.w);
        Tr[k] = t;
    }
#undef TB_ELEM
    s = blockReduceSum(s);
    if (threadIdx.x == 0) bias_out[row] = bias_in[row] + s;
}

// ======================= mma.sync bf16-split GEMM =======================
// C[M,N] fp32 = (Ah+Al)[M,K] @ (Bh+Bl)[N,K]^T  (3 bf16 products, fp32 accum)
// Tile 128x128xBK32, 256 threads (8 warps, 2x4), warp tile 64x32.
// SMEM rows padded to 80B -> conflict-free ldmatrix (verified bank math).
#define ROWB   80
#define MATB   (128 * ROWB)         // 10240 B per matrix tile
#define STAGEB (4 * MATB)           // Ah, Al, Bh, Bl
#define TCG_SMEM (2 * STAGEB)       // 81920 B, 2 stages

__global__ __launch_bounds__(256, 1) void tc_gemm(
    const unsigned short* __restrict__ Ah, const unsigned short* __restrict__ Al,
    const unsigned short* __restrict__ Bh, const unsigned short* __restrict__ Bl,
    float* __restrict__ C, int M, int N, int K) {
    extern __shared__ char smem[];
    const uint32_t sbase = smem_u32(smem);
    const int tid = threadIdx.x, lane = tid & 31, wid = tid >> 5;
    const int wm = wid & 1, wn = wid >> 1;          // 2 x 4 warp grid
    const int m0 = blockIdx.y * 128, n0 = blockIdx.x * 128;

    const unsigned short* mats[4] = {Ah, Al, Bh, Bl};

    auto fill = [&](int stage, int kc) {
        int k0 = kc * 32;
        uint32_t sb = sbase + stage * STAGEB;
#pragma unroll
        for (int i = 0; i < 8; i++) {
            int c = tid + i * 256;          // 0..2047
            int mat = c >> 9;               // 0..3
            int rem = c & 511;
            int row = rem >> 2, seg = rem & 3;
            uint32_t dst = sb + mat * MATB + row * ROWB + seg * 16;
            bool isA = (mat < 2);
            int gr = isA ? (m0 + row) : (n0 + row);
            bool valid = isA || (gr < N);
            int rc = valid ? gr : 0;
            const unsigned short* src = mats[mat] + (size_t)rc * K + k0 + seg * 8;
            cp_async16(dst, src, valid ? 16 : 0);
        }
    };

    float acc[4][4][4];
#pragma unroll
    for (int a = 0; a < 4; a++)
#pragma unroll
        for (int b = 0; b < 4; b++)
#pragma unroll
            for (int q = 0; q < 4; q++) acc[a][b][q] = 0.f;

    const int NCH = K >> 5;     // K/32 chunks
    fill(0, 0); CP_COMMIT();
    fill(1, 1); CP_COMMIT();

    // ldmatrix lane addressing (constant per thread)
    const int a_r  = (lane & 7) + ((lane >> 3) & 1) * 8;  // row within 16-row tile
    const int a_s  = lane >> 4;                           // seg half (0/1)
    const int b_r  = ((lane >> 4) << 3) + (lane & 7);     // row within 16-n pair
    const int b_s  = (lane >> 3) & 1;

    for (int t = 0; t < NCH; t++) {
        CP_WAIT1();
        __syncthreads();
        int st = t & 1;
        uint32_t sb = sbase + st * STAGEB;
        uint32_t aH = sb, aL = sb + MATB, bH = sb + 2 * MATB, bL = sb + 3 * MATB;
#pragma unroll
        for (int kk = 0; kk < 2; kk++) {
            uint32_t ah[4][4], al[4][4], bh[4][2], bl[4][2];
#pragma unroll
            for (int mt = 0; mt < 4; mt++) {
                int row = wm * 64 + mt * 16 + a_r;
                uint32_t off = (uint32_t)row * ROWB + (kk * 2 + a_s) * 16;
                ldmatrix_x4(ah[mt], aH + off);
                ldmatrix_x4(al[mt], aL + off);
            }
#pragma unroll
            for (int p = 0; p < 2; p++) {
                int row = wn * 32 + p * 16 + b_r;
                uint32_t off = (uint32_t)row * ROWB + (kk * 2 + b_s) * 16;
                uint32_t r4[4];
                ldmatrix_x4(r4, bH + off);
                bh[2 * p][0] = r4[0]; bh[2 * p][1] = r4[1];
                bh[2 * p + 1][0] = r4[2]; bh[2 * p + 1][1] = r4[3];
                ldmatrix_x4(r4, bL + off);
                bl[2 * p][0] = r4[0]; bl[2 * p][1] = r4[1];
                bl[2 * p + 1][0] = r4[2]; bl[2 * p + 1][1] = r4[3];
            }
#pragma unroll
            for (int mt = 0; mt < 4; mt++)
#pragma unroll
                for (int nt = 0; nt < 4; nt++) {
                    mma16816(acc[mt][nt], ah[mt], bh[nt]);
                    mma16816(acc[mt][nt], ah[mt], bl[nt]);
                    mma16816(acc[mt][nt], al[mt], bh[nt]);
                }
        }
        __syncthreads();
        if (t + 2 < NCH) fill(st, t + 2);
        CP_COMMIT();
    }

    // epilogue: direct global stores (col guard for N=784 tiles)
    int rbase = m0 + wm * 64 + (lane >> 2);
    int cbase = n0 + wn * 32 + (lane & 3) * 2;
#pragma unroll
    for (int mt = 0; mt < 4; mt++) {
#pragma unroll
        for (int nt = 0; nt < 4; nt++) {
            int c = cbase + nt * 8;
            if (c < N) {
                int r = rbase + mt * 16;
                float2* p0 = (float2*)(C + (size_t)r * N + c);
                float2* p1 = (float2*)(C + (size_t)(r + 8) * N + c);
                *p0 = make_float2(acc[mt][nt][0], acc[mt][nt][1]);
                *p1 = make_float2(acc[mt][nt][2], acc[mt][nt][3]);
            }
        }
    }
}

// ------------- skinny GEMM (10 rows) -------------
__global__ void sk_gemm(const float* __restrict__ TA, const float* __restrict__ B,
                        float* __restrict__ part, int K, int N) {
    __shared__ float sTA[FCOUT][128];
    int tid = threadIdx.x;
    int kb = blockIdx.y;
    int kbase = kb * 128;
    int col0 = blockIdx.x * 256 + tid * 4;
    for (int idx = tid; idx < FCOUT * 128; idx += 64) {
        int r = idx >> 7, k = idx & 127;
        sTA[r][k] = TA[(size_t)r * K + kbase + k];
    }
    __syncthreads();
    if (col0 >= N) return;
    float4 acc[FCOUT];
#pragma unroll
    for (int r = 0; r < FCOUT; r++) acc[r] = make_float4(0.f, 0.f, 0.f, 0.f);
    for (int k = 0; k < 128; k++) {
        float4 bv = *(const float4*)(B + (size_t)(kbase + k) * N + col0);
#pragma unroll
        for (int r = 0; r < FCOUT; r++) {
            float sv = sTA[r][k];
            acc[r].x += sv * bv.x; acc[r].y += sv * bv.y;
            acc[r].z += sv * bv.z; acc[r].w += sv * bv.w;
        }
    }
#pragma unroll
    for (int r = 0; r < FCOUT; r++)
        *(float4*)(part + (size_t)(kb * FCOUT + r) * N + col0) = acc[r];
}

__global__ void sk_reduce(const float* __restrict__ part, float* __restrict__ C, int N) {
    int i = blockIdx.x * blockDim.x + threadIdx.x;
    if (i >= FCOUT * N) return;
    int r = i / N, c = i - r * N;
    float s = 0.f;
#pragma unroll
    for (int ks = 0; ks < 16; ks++) s += part[(size_t)(ks * FCOUT + r) * N + c];
    C[(size_t)r * N + c] = s;
}

__global__ void assemble_k(const float* __restrict__ z, const float* __restrict__ low,
                           const float* __restrict__ high, float* __restrict__ out) {
    int i = threadIdx.x;
    if (i < FCOUT) {
        out[i]      = z[i];
        out[10 + i] = low[i];
        out[20 + i] = high[i];
    }
}

// =======================================================================
extern "C" void kernel_launch(void* const* d_in, const int* in_sizes, int n_in,
                              void* d_out, int out_size) {
    (void)in_sizes; (void)n_in; (void)out_size;
    const float* X  = (const float*)d_in[0];
    const float* LO = (const float*)d_in[1];
    const float* HI = (const float*)d_in[2];
    const float* W[5];
    const float* Bv[5];
    for (int i = 0; i < 5; i++) {
        W[i]  = (const float*)d_in[3 + 2 * i];
        Bv[i] = (const float*)d_in[4 + 2 * i];
    }
    float* out = (float*)d_out;

    float *x0, *l0, *h0, *z, *act, *low, *high, *bh, *bl, *P, *sP, *sQ, *part;
    float *wlv, *whv, *bhrv;
    unsigned short *TAh, *TAl;
    unsigned short *Wth[4], *Wtl[4];
    cudaGetSymbolAddress((void**)&x0, g_x0);
    cudaGetSymbolAddress((void**)&l0, g_l0);
    cudaGetSymbolAddress((void**)&h0, g_h0);
    cudaGetSymbolAddress((void**)&z, g_z);
    cudaGetSymbolAddress((void**)&act, g_act);
    cudaGetSymbolAddress((void**)&low, g_low);
    cudaGetSymbolAddress((void**)&high, g_high);
    cudaGetSymbolAddress((void**)&bh, g_bh);
    cudaGetSymbolAddress((void**)&bl, g_bl);
    cudaGetSymbolAddress((void**)&P, g_P);
    cudaGetSymbolAddress((void**)&sP, g_sP);
    cudaGetSymbolAddress((void**)&sQ, g_sQ);
    cudaGetSymbolAddress((void**)&part, g_part);
    cudaGetSymbolAddress((void**)&wlv, g_wl);
    cudaGetSymbolAddress((void**)&whv, g_wh);
    cudaGetSymbolAddress((void**)&bhrv, g_bhr);
    cudaGetSymbolAddress((void**)&TAh, g_TAh);
    cudaGetSymbolAddress((void**)&TAl, g_TAl);
    cudaGetSymbolAddress((void**)&Wth[0], g_Wt0h);
    cudaGetSymbolAddress((void**)&Wtl[0], g_Wt0l);
    cudaGetSymbolAddress((void**)&Wth[1], g_Wt1h);
    cudaGetSymbolAddress((void**)&Wtl[1], g_Wt1l);
    cudaGetSymbolAddress((void**)&Wth[2], g_Wt2h);
    cudaGetSymbolAddress((void**)&Wtl[2], g_Wt2l);
    cudaGetSymbolAddress((void**)&Wth[3], g_Wt3h);
    cudaGetSymbolAddress((void**)&Wtl[3], g_Wt3l);

    cudaFuncSetAttribute(tc_gemm, cudaFuncAttributeMaxDynamicSharedMemorySize, TCG_SMEM);

    // weight transpose + bf16 split (graph-capturable, no allocation)
    {
        dim3 blk(32, 8);
        wt_split<<<dim3((FC0 + 31) / 32, FCH / 32), blk>>>(W[0], Wth[0], Wtl[0], FCH, FC0);
        for (int j = 1; j <= 3; j++)
            wt_split<<<dim3(FCH / 32, FCH / 32), blk>>>(W[j], Wth[j], Wtl[j], FCH, FCH);
    }

    norm_k<<<4, 256>>>(X, LO, HI, x0, l0, h0);

    // ---- layer 1 ----
    gemv_fwd<<<FCH, 128>>>(W[0], x0, Bv[0], z, FC0);
    bounds_k<<<FCH, 128>>>(W[0], Bv[0], l0, h0, low, FC0, 0);
    bounds_k<<<FCH, 128>>>(W[0], Bv[0], l0, h0, high, FC0, 1);
    relu_k<<<8, 256>>>(z, low, high, act, wlv, whv, bhrv, FCH);

    // ---- layers 2..4: 2048-row backsub chains on tensor pipe ----
    for (int i = 1; i <= 3; i++) {
        gemv_fwd<<<FCH, 128>>>(W[i], act, Bv[i], z, FCH);
        for (int hs = 0; hs < 2; hs++) {
            float* bias = hs ? bh : bl;
            float* outB = hs ? high : low;
            const float* cur = W[i];
            const float* bin = Bv[i];
            for (int j = i - 1; j >= 0; j--) {
                transform_split_k<<<FCH, 128>>>(cur, TAh, TAl, whv + j * FCH, wlv + j * FCH,
                                                bhrv + j * FCH, Bv[j], bin, bias, FCH, hs);
                int Nn = (j == 0) ? FC0 : FCH;
                dim3 grid((Nn + 127) / 128, FCH / 128);
                tc_gemm<<<grid, 256, TCG_SMEM>>>(TAh, TAl, Wth[j], Wtl[j], P, FCH, Nn, FCH);
                cur = P; bin = bias;
            }
            bounds_k<<<FCH, 128>>>(cur, bias, l0, h0, outB, FC0, hs);
        }
        relu_k<<<8, 256>>>(z, low, high, act, wlv + i * FCH, whv + i * FCH,
                           bhrv + i * FCH, FCH);
    }

    // ---- layer 5 (10 rows): skinny SIMT chains ----
    gemv_fwd<<<FCOUT, 128>>>(W[4], act, Bv[4], z, FCH);
    for (int hs = 0; hs < 2; hs++) {
        float* bias = hs ? bh : bl;
        float* outB = hs ? high : low;
        const float* cur = W[4];
        const float* bin = Bv[4];
        int curK = FCH;
        for (int j = 3; j >= 0; j--) {
            transform_f32_k<<<FCOUT, 128>>>(cur, sQ, whv + j * FCH, wlv + j * FCH,
                                            bhrv + j * FCH, Bv[j], bin, bias, curK, hs);
            int Nn = (j == 0) ? FC0 : FCH;
            dim3 grid((Nn + 255) / 256, 16);
            sk_gemm<<<grid, 64>>>(sQ, W[j], part, curK, Nn);
            sk_reduce<<<(FCOUT * Nn + 255) / 256, 256>>>(part, sP, Nn);
            cur = sP; curK = Nn; bin = bias;
        }
        bounds_k<<<FCOUT, 128>>>(cur, bias, l0, h0, outB, FC0, hs);
    }

    assemble_k<<<1, 32>>>(z, low, high, out);
}

// round 7
// speedup vs baseline: 2.1524x; 1.0044x over previous
#include <cuda_runtime.h>
#include <cuda_bf16.h>
#include <cstdint>

#define FC0   784
#define FCH   2048
#define FCOUT 10

// ======================= helpers =======================
__device__ __forceinline__ uint32_t smem_u32(const void* p) {
    uint32_t a;
    asm("{ .reg .u64 t; cvta.to.shared.u64 t, %1; cvt.u32.u64 %0, t; }" : "=r"(a) : "l"(p));
    return a;
}

__device__ __forceinline__ void ldmatrix_x4(uint32_t* r, uint32_t addr) {
    asm volatile("ldmatrix.sync.aligned.m8n8.x4.shared.b16 {%0,%1,%2,%3}, [%4];"
                 : "=r"(r[0]), "=r"(r[1]), "=r"(r[2]), "=r"(r[3]) : "r"(addr));
}

__device__ __forceinline__ void mma16816(float* d, const uint32_t* a, const uint32_t* b) {
    asm volatile("mma.sync.aligned.m16n8k16.row.col.f32.bf16.bf16.f32 "
                 "{%0,%1,%2,%3}, {%4,%5,%6,%7}, {%8,%9}, {%0,%1,%2,%3};"
                 : "+f"(d[0]), "+f"(d[1]), "+f"(d[2]), "+f"(d[3])
                 : "r"(a[0]), "r"(a[1]), "r"(a[2]), "r"(a[3]), "r"(b[0]), "r"(b[1]));
}

__device__ __forceinline__ void cp_async16(uint32_t dst, const void* src, int sz) {
    asm volatile("cp.async.cg.shared.global [%0], [%1], 16, %2;"
                 :: "r"(dst), "l"(src), "r"(sz) : "memory");
}
#define CP_COMMIT() asm volatile("cp.async.commit_group;" ::: "memory")
#define CP_WAIT2()  asm volatile("cp.async.wait_group 2;" ::: "memory")

// ======================= scratch (static device globals) =======================
__device__ float g_x0[FC0], g_l0[FC0], g_h0[FC0];
__device__ float g_z[FCH], g_act[FCH];
__device__ float g_low[FCH], g_high[FCH];
__device__ float g_wl[4 * FCH], g_wh[4 * FCH], g_bhr[4 * FCH];
__device__ float g_b2[2 * FCH];
__device__ float g_P[2 * FCH * FCH];
__device__ unsigned short g_TAh[2 * FCH * FCH], g_TAl[2 * FCH * FCH];
__device__ unsigned short g_Wt0h[FC0 * FCH], g_Wt0l[FC0 * FCH];
__device__ unsigned short g_Wt1h[FCH * FCH], g_Wt1l[FCH * FCH];
__device__ unsigned short g_Wt2h[FCH * FCH], g_Wt2l[FCH * FCH];
__device__ unsigned short g_Wt3h[FCH * FCH], g_Wt3l[FCH * FCH];
__device__ float g_sP[20 * FCH], g_sQ[20 * FCH], g_sb2[20];
__device__ float g_part[16 * 20 * FCH];

// ======================= small helper kernels =======================
__device__ __forceinline__ float blockReduceSum(float v) {
    __shared__ float sh[32];
    int lane = threadIdx.x & 31, wid = threadIdx.x >> 5;
#pragma unroll
    for (int o = 16; o > 0; o >>= 1) v += __shfl_down_sync(0xffffffffu, v, o);
    if (lane == 0) sh[wid] = v;
    __syncthreads();
    int nw = blockDim.x >> 5;
    v = (threadIdx.x < nw) ? sh[threadIdx.x] : 0.f;
    if (wid == 0) {
#pragma unroll
        for (int o = 16; o > 0; o >>= 1) v += __shfl_down_sync(0xffffffffu, v, o);
    }
    return v;
}

__global__ void norm_k(const float* __restrict__ x, const float* __restrict__ lo,
                       const float* __restrict__ hi, float* __restrict__ x0,
                       float* __restrict__ l0, float* __restrict__ h0) {
    int i = blockIdx.x * blockDim.x + threadIdx.x;
    if (i < FC0) {
        const float mean = 0.1307f, stdv = 0.3081f;
        x0[i] = (x[i] - mean) / stdv;
        l0[i] = (lo[i] - mean) / stdv;
        h0[i] = (hi[i] - mean) / stdv;
    }
}

__global__ void gemv_fwd(const float* __restrict__ W, const float* __restrict__ xin,
                         const float* __restrict__ b, float* __restrict__ z, int K) {
    int row = blockIdx.x;
    const float4* Wr = (const float4*)(W + (size_t)row * K);
    const float4* X4 = (const float4*)xin;
    float s = 0.f;
    for (int k = threadIdx.x; k < (K >> 2); k += blockDim.x) {
        float4 w = Wr[k], xv = X4[k];
        s += w.x * xv.x + w.y * xv.y + w.z * xv.z + w.w * xv.w;
    }
    s = blockReduceSum(s);
    if (threadIdx.x == 0) z[row] = s + b[row];
}

// single-matrix bounds (layer 1, uses W directly)
__global__ void bounds_k(const float* __restrict__ M, const float* __restrict__ bias,
                         const float* __restrict__ l0, const float* __restrict__ h0,
                         float* __restrict__ out, int K, int is_high) {
    int row = blockIdx.x;
    const float* Mr = M + (size_t)row * K;
    float s = 0.f;
    for (int k = threadIdx.x; k < K; k += blockDim.x) {
        float m = Mr[k];
        float mn = fminf(m, 0.f), mp = fmaxf(m, 0.f);
        float lv = l0[k], hv = h0[k];
        s += is_high ? (mn * lv + mp * hv) : (mn * hv + mp * lv);
    }
    s = blockReduceSum(s);
    if (threadIdx.x == 0) out[row] = s + bias[row];
}

// stacked bounds: rows [0,half) -> low, rows [half,2*half) -> high
__global__ void bounds2_k(const float* __restrict__ M, const float* __restrict__ bias,
                          const float* __restrict__ l0, const float* __restrict__ h0,
                          float* __restrict__ lowv, float* __restrict__ highv,
                          int K, int half) {
    int row = blockIdx.x;
    int is_high = row >= half;
    int r = is_high ? row - half : row;
    const float* Mr = M + (size_t)row * K;
    float s = 0.f;
    for (int k = threadIdx.x; k < K; k += blockDim.x) {
        float m = Mr[k];
        float mn = fminf(m, 0.f), mp = fmaxf(m, 0.f);
        float lv = l0[k], hv = h0[k];
        s += is_high ? (mn * lv + mp * hv) : (mn * hv + mp * lv);
    }
    s = blockReduceSum(s);
    if (threadIdx.x == 0) {
        float* dst = is_high ? highv : lowv;
        dst[r] = s + bias[row];
    }
}

__global__ void relu_k(const float* __restrict__ z, const float* __restrict__ low,
                       const float* __restrict__ high, float* __restrict__ act,
                       float* __restrict__ wl, float* __restrict__ wh,
                       float* __restrict__ bhr, int n) {
    int i = blockIdx.x * blockDim.x + threadIdx.x;
    if (i >= n) return;
    float lo = low[i], hi = high[i];
    float w_h, w_l, b_h;
    if (lo < 0.f && hi > 0.f) {
        float d = hi - lo;
        w_h = hi / d;
        b_h = -(lo * hi) / d;
        w_l = (lo * lo > hi * hi) ? 0.f : 1.f;
    } else {
        float keep = (hi <= 0.f) ? 0.f : 1.f;
        w_h = keep; w_l = keep; b_h = 0.f;
    }
    wl[i] = w_l; wh[i] = w_h; bhr[i] = b_h;
    act[i] = fmaxf(z[i], 0.f);
}

// weight transpose + bf16 hi/lo split: W[K,N] fp32 -> Bt_hi/lo[N,K] bf16
__global__ void wt_split(const float* __restrict__ W, unsigned short* __restrict__ Bh,
                         unsigned short* __restrict__ Bl, int K, int N) {
    __shared__ float t[32][33];
    int k0 = blockIdx.y * 32, n0 = blockIdx.x * 32;
    int tx = threadIdx.x, ty = threadIdx.y;  // 32 x 8
#pragma unroll
    for (int i = 0; i < 32; i += 8) {
        int n = n0 + tx;
        t[ty + i][tx] = (n < N) ? W[(size_t)(k0 + ty + i) * N + n] : 0.f;
    }
    __syncthreads();
#pragma unroll
    for (int i = 0; i < 32; i += 8) {
        int n = n0 + ty + i, k = k0 + tx;
        if (n < N) {
            float v = t[tx][ty + i];
            __nv_bfloat16 h = __float2bfloat16(v);
            __nv_bfloat16 l = __float2bfloat16(v - __bfloat162float(h));
            Bh[(size_t)n * K + k] = __bfloat16_as_ushort(h);
            Bl[(size_t)n * K + k] = __bfloat16_as_ushort(l);
        }
    }
}

#define TB_ELEM(mm, hh, ll, bbv, bnv, tout)                          \
    {                                                                \
        float tv = 0.f;                                              \
        if (hh != 0.f) {                                             \
            float spos = is_high ? hh : ll;                          \
            float sneg = is_high ? ll : hh;                          \
            tv = (mm > 0.f) ? mm * spos : mm * sneg;                 \
            float p = is_high ? fmaxf(mm, 0.f) : fminf(mm, 0.f);     \
            s += p * bbv;                                            \
        }                                                            \
        s += tv * bnv;                                               \
        tout = tv;                                                   \
    }

// stacked fused transform + bias + bf16 hi/lo split. rows [0,half)=low, [half,2h)=high
__global__ void transform_split2_k(const float* __restrict__ Mraw, int shared_src,
                                   unsigned short* __restrict__ TAh,
                                   unsigned short* __restrict__ TAl,
                                   const float* __restrict__ whv, const float* __restrict__ wlv,
                                   const float* __restrict__ bhrv, const float* __restrict__ blin,
                                   const float* __restrict__ biasL, const float* __restrict__ biasH,
                                   float* __restrict__ bias_out, int K, int half) {
    int row = blockIdx.x;
    int is_high = row >= half;
    int r = is_high ? row - half : row;
    int srow = shared_src ? r : row;
    const float4* Mr  = (const float4*)(Mraw + (size_t)srow * K);
    const float4* wh4 = (const float4*)whv;
    const float4* wl4 = (const float4*)wlv;
    const float4* bb4 = (const float4*)bhrv;
    const float4* bn4 = (const float4*)blin;
    uint2* TH = (uint2*)(TAh + (size_t)row * K);
    uint2* TL = (uint2*)(TAl + (size_t)row * K);
    float s = 0.f;
    for (int k = threadIdx.x; k < (K >> 2); k += blockDim.x) {
        float4 m = Mr[k], h = wh4[k], l = wl4[k], bb = bb4[k], bn = bn4[k];
        float4 t;
        TB_ELEM(m.x, h.x, l.x, bb.x, bn.x, t.x);
        TB_ELEM(m.y, h.y, l.y, bb.y, bn.y, t.y);
        TB_ELEM(m.z, h.z, l.z, bb.z, bn.z, t.z);
        TB_ELEM(m.w, h.w, l.w, bb.w, bn.w, t.w);
        __nv_bfloat16 h0 = __float2bfloat16(t.x), h1 = __float2bfloat16(t.y);
        __nv_bfloat16 h2 = __float2bfloat16(t.z), h3 = __float2bfloat16(t.w);
        __nv_bfloat16 q0 = __float2bfloat16(t.x - __bfloat162float(h0));
        __nv_bfloat16 q1 = __float2bfloat16(t.y - __bfloat162float(h1));
        __nv_bfloat16 q2 = __float2bfloat16(t.z - __bfloat162float(h2));
        __nv_bfloat16 q3 = __float2bfloat16(t.w - __bfloat162float(h3));
        uint2 uh, ul;
        uh.x = (uint32_t)__bfloat16_as_ushort(h0) | ((uint32_t)__bfloat16_as_ushort(h1) << 16);
        uh.y = (uint32_t)__bfloat16_as_ushort(h2) | ((uint32_t)__bfloat16_as_ushort(h3) << 16);
        ul.x = (uint32_t)__bfloat16_as_ushort(q0) | ((uint32_t)__bfloat16_as_ushort(q1) << 16);
        ul.y = (uint32_t)__bfloat16_as_ushort(q2) | ((uint32_t)__bfloat16_as_ushort(q3) << 16);
        TH[k] = uh;
        TL[k] = ul;
    }
    s = blockReduceSum(s);
    if (threadIdx.x == 0)
        bias_out[row] = (is_high ? biasH[r] : biasL[r]) + s;
}

// stacked fp32 transform for skinny (20-row) chain
__global__ void transform20_k(const float* __restrict__ Mraw, int shared_src,
                              float* __restrict__ TA,
                              const float* __restrict__ whv, const float* __restrict__ wlv,
                              const float* __restrict__ bhrv, const float* __restrict__ blin,
                              const float* __restrict__ biasL, const float* __restrict__ biasH,
                              float* __restrict__ bias_out, int K, int half) {
    int row = blockIdx.x;
    int is_high = row >= half;
    int r = is_high ? row - half : row;
    int srow = shared_src ? r : row;
    const float4* Mr  = (const float4*)(Mraw + (size_t)srow * K);
    float4*       Tr  = (float4*)(TA + (size_t)row * K);
    const float4* wh4 = (const float4*)whv;
    const float4* wl4 = (const float4*)wlv;
    const float4* bb4 = (const float4*)bhrv;
    const float4* bn4 = (const float4*)blin;
    float s = 0.f;
    for (int k = threadIdx.x; k < (K >> 2); k += blockDim.x) {
        float4 m = Mr[k], h = wh4[k], l = wl4[k], bb = bb4[k], bn = bn4[k];
        float4 t;
        TB_ELEM(m.x, h.x, l.x, bb.x, bn.x, t.x);
        TB_ELEM(m.y, h.y, l.y, bb.y, bn.y, t.y);
        TB_ELEM(m.z, h.z, l.z, bb.z, bn.z, t.z);
        TB_ELEM(m.w, h.w, l.w, bb.w, bn.w, t.w);
        Tr[k] = t;
    }
    s = blockReduceSum(s);
    if (threadIdx.x == 0)
        bias_out[row] = (is_high ? biasH[r] : biasL[r]) + s;
}
#undef TB_ELEM

// ======================= mma.sync bf16-split GEMM =======================
// C[M,N] fp32 = (Ah+Al)[M,K] @ (Bh+Bl)[N,K]^T  (3 bf16 products, fp32 accum)
// Tile 128x128x32, 256 threads (2x4 warps), 3-stage cp.async pipeline.
#define ROWB   80
#define MATB   (128 * ROWB)         // 10240 B per matrix tile
#define STAGEB (4 * MATB)           // Ah, Al, Bh, Bl
#define TCG_SMEM (3 * STAGEB)       // 122880 B, 3 stages

__global__ __launch_bounds__(256, 1) void tc_gemm(
    const unsigned short* __restrict__ Ah, const unsigned short* __restrict__ Al,
    const unsigned short* __restrict__ Bh, const unsigned short* __restrict__ Bl,
    float* __restrict__ C, int M, int N, int K) {
    extern __shared__ char smem[];
    const uint32_t sbase = smem_u32(smem);
    const int tid = threadIdx.x, lane = tid & 31, wid = tid >> 5;
    const int wm = wid & 1, wn = wid >> 1;          // 2 x 4 warp grid
    const int m0 = blockIdx.y * 128, n0 = blockIdx.x * 128;

    const unsigned short* mats[4] = {Ah, Al, Bh, Bl};

    auto fill = [&](int stage, int kc) {
        int k0 = kc * 32;
        uint32_t sb = sbase + stage * STAGEB;
#pragma unroll
        for (int i = 0; i < 8; i++) {
            int c = tid + i * 256;          // 0..2047
            int mat = c >> 9;               // 0..3
            int rem = c & 511;
            int row = rem >> 2, seg = rem & 3;
            uint32_t dst = sb + mat * MATB + row * ROWB + seg * 16;
            bool isA = (mat < 2);
            int gr = isA ? (m0 + row) : (n0 + row);
            bool valid = isA || (gr < N);
            int rc = valid ? gr : 0;
            const unsigned short* src = mats[mat] + (size_t)rc * K + k0 + seg * 8;
            cp_async16(dst, src, valid ? 16 : 0);
        }
    };

    float acc[4][4][4];
#pragma unroll
    for (int a = 0; a < 4; a++)
#pragma unroll
        for (int b = 0; b < 4; b++)
#pragma unroll
            for (int q = 0; q < 4; q++) acc[a][b][q] = 0.f;

    const int NCH = K >> 5;     // K/32 chunks (64 for K=2048)
    fill(0, 0); CP_COMMIT();
    fill(1, 1); CP_COMMIT();
    fill(2, 2); CP_COMMIT();

    const int a_r  = (lane & 7) + ((lane >> 3) & 1) * 8;
    const int a_s  = lane >> 4;
    const int b_r  = ((lane >> 4) << 3) + (lane & 7);
    const int b_s  = (lane >> 3) & 1;

    int st = 0;
    for (int t = 0; t < NCH; t++) {
        CP_WAIT2();
        __syncthreads();
        uint32_t sb = sbase + st * STAGEB;
        uint32_t aH = sb, aL = sb + MATB, bH = sb + 2 * MATB, bL = sb + 3 * MATB;
#pragma unroll
        for (int kk = 0; kk < 2; kk++) {
            uint32_t ah[4][4], al[4][4], bh[4][2], bl[4][2];
#pragma unroll
            for (int mt = 0; mt < 4; mt++) {
                int row = wm * 64 + mt * 16 + a_r;
                uint32_t off = (uint32_t)row * ROWB + (kk * 2 + a_s) * 16;
                ldmatrix_x4(ah[mt], aH + off);
                ldmatrix_x4(al[mt], aL + off);
            }
#pragma unroll
            for (int p = 0; p < 2; p++) {
                int row = wn * 32 + p * 16 + b_r;
                uint32_t off = (uint32_t)row * ROWB + (kk * 2 + b_s) * 16;
                uint32_t r4[4];
                ldmatrix_x4(r4, bH + off);
                bh[2 * p][0] = r4[0]; bh[2 * p][1] = r4[1];
                bh[2 * p + 1][0] = r4[2]; bh[2 * p + 1][1] = r4[3];
                ldmatrix_x4(r4, bL + off);
                bl[2 * p][0] = r4[0]; bl[2 * p][1] = r4[1];
                bl[2 * p + 1][0] = r4[2]; bl[2 * p + 1][1] = r4[3];
            }
#pragma unroll
            for (int mt = 0; mt < 4; mt++)
#pragma unroll
                for (int nt = 0; nt < 4; nt++) {
                    mma16816(acc[mt][nt], ah[mt], bh[nt]);
                    mma16816(acc[mt][nt], ah[mt], bl[nt]);
                    mma16816(acc[mt][nt], al[mt], bh[nt]);
                }
        }
        __syncthreads();
        if (t + 3 < NCH) fill(st, t + 3);
        CP_COMMIT();
        st = (st == 2) ? 0 : st + 1;
    }

    int rbase = m0 + wm * 64 + (lane >> 2);
    int cbase = n0 + wn * 32 + (lane & 3) * 2;
#pragma unroll
    for (int mt = 0; mt < 4; mt++) {
#pragma unroll
        for (int nt = 0; nt < 4; nt++) {
            int c = cbase + nt * 8;
            if (c < N) {
                int r = rbase + mt * 16;
                float2* p0 = (float2*)(C + (size_t)r * N + c);
                float2* p1 = (float2*)(C + (size_t)(r + 8) * N + c);
                *p0 = make_float2(acc[mt][nt][0], acc[mt][nt][1]);
                *p1 = make_float2(acc[mt][nt][2], acc[mt][nt][3]);
            }
        }
    }
}

// ------------- skinny GEMM (20 rows stacked low/high) -------------
__global__ void sk_gemm20(const float* __restrict__ TA, const float* __restrict__ B,
                          float* __restrict__ part, int K, int N) {
    __shared__ float sTA[20][128];
    int tid = threadIdx.x;           // 128
    int kb = blockIdx.y;             // 0..15
    int kbase = kb * 128;
    int col0 = blockIdx.x * 256 + tid * 2;
    for (int idx = tid; idx < 20 * 128; idx += 128) {
        int r = idx >> 7, k = idx & 127;
        sTA[r][k] = TA[(size_t)r * K + kbase + k];
    }
    __syncthreads();
    if (col0 >= N) return;
    float2 acc[20];
#pragma unroll
    for (int r = 0; r < 20; r++) acc[r] = make_float2(0.f, 0.f);
    for (int k = 0; k < 128; k++) {
        float2 bv = *(const float2*)(B + (size_t)(kbase + k) * N + col0);
#pragma unroll
        for (int r = 0; r < 20; r++) {
            float sv = sTA[r][k];
            acc[r].x += sv * bv.x;
            acc[r].y += sv * bv.y;
        }
    }
#pragma unroll
    for (int r = 0; r < 20; r++)
        *(float2*)(part + (size_t)(kb * 20 + r) * N + col0) = acc[r];
}

__global__ void sk_reduce20(const float* __restrict__ part, float* __restrict__ C, int N) {
    int i = blockIdx.x * blockDim.x + threadIdx.x;
    if (i >= 20 * N) return;
    int r = i / N, c = i - r * N;
    float s = 0.f;
#pragma unroll
    for (int ks = 0; ks < 16; ks++) s += part[(size_t)(ks * 20 + r) * N + c];
    C[(size_t)r * N + c] = s;
}

__global__ void assemble_k(const float* __restrict__ z, const float* __restrict__ low,
                           const float* __restrict__ high, float* __restrict__ out) {
    int i = threadIdx.x;
    if (i < FCOUT) {
        out[i]      = z[i];
        out[10 + i] = low[i];
        out[20 + i] = high[i];
    }
}

// =======================================================================
extern "C" void kernel_launch(void* const* d_in, const int* in_sizes, int n_in,
                              void* d_out, int out_size) {
    (void)in_sizes; (void)n_in; (void)out_size;
    const float* X  = (const float*)d_in[0];
    const float* LO = (const float*)d_in[1];
    const float* HI = (const float*)d_in[2];
    const float* W[5];
    const float* Bv[5];
    for (int i = 0; i < 5; i++) {
        W[i]  = (const float*)d_in[3 + 2 * i];
        Bv[i] = (const float*)d_in[4 + 2 * i];
    }
    float* out = (float*)d_out;

    float *x0, *l0, *h0, *z, *act, *low, *high, *b2, *P, *sP, *sQ, *sb2, *part;
    float *wlv, *whv, *bhrv;
    unsigned short *TAh, *TAl;
    unsigned short *Wth[4], *Wtl[4];
    cudaGetSymbolAddress((void**)&x0, g_x0);
    cudaGetSymbolAddress((void**)&l0, g_l0);
    cudaGetSymbolAddress((void**)&h0, g_h0);
    cudaGetSymbolAddress((void**)&z, g_z);
    cudaGetSymbolAddress((void**)&act, g_act);
    cudaGetSymbolAddress((void**)&low, g_low);
    cudaGetSymbolAddress((void**)&high, g_high);
    cudaGetSymbolAddress((void**)&b2, g_b2);
    cudaGetSymbolAddress((void**)&P, g_P);
    cudaGetSymbolAddress((void**)&sP, g_sP);
    cudaGetSymbolAddress((void**)&sQ, g_sQ);
    cudaGetSymbolAddress((void**)&sb2, g_sb2);
    cudaGetSymbolAddress((void**)&part, g_part);
    cudaGetSymbolAddress((void**)&wlv, g_wl);
    cudaGetSymbolAddress((void**)&whv, g_wh);
    cudaGetSymbolAddress((void**)&bhrv, g_bhr);
    cudaGetSymbolAddress((void**)&TAh, g_TAh);
    cudaGetSymbolAddress((void**)&TAl, g_TAl);
    cudaGetSymbolAddress((void**)&Wth[0], g_Wt0h);
    cudaGetSymbolAddress((void**)&Wtl[0], g_Wt0l);
    cudaGetSymbolAddress((void**)&Wth[1], g_Wt1h);
    cudaGetSymbolAddress((void**)&Wtl[1], g_Wt1l);
    cudaGetSymbolAddress((void**)&Wth[2], g_Wt2h);
    cudaGetSymbolAddress((void**)&Wtl[2], g_Wt2l);
    cudaGetSymbolAddress((void**)&Wth[3], g_Wt3h);
    cudaGetSymbolAddress((void**)&Wtl[3], g_Wt3l);

    cudaFuncSetAttribute(tc_gemm, cudaFuncAttributeMaxDynamicSharedMemorySize, TCG_SMEM);

    // weight transpose + bf16 split
    {
        dim3 blk(32, 8);
        wt_split<<<dim3((FC0 + 31) / 32, FCH / 32), blk>>>(W[0], Wth[0], Wtl[0], FCH, FC0);
        for (int j = 1; j <= 3; j++)
            wt_split<<<dim3(FCH / 32, FCH / 32), blk>>>(W[j], Wth[j], Wtl[j], FCH, FCH);
    }

    norm_k<<<4, 256>>>(X, LO, HI, x0, l0, h0);

    // ---- layer 1 ----
    gemv_fwd<<<FCH, 128>>>(W[0], x0, Bv[0], z, FC0);
    bounds_k<<<FCH, 128>>>(W[0], Bv[0], l0, h0, low, FC0, 0);
    bounds_k<<<FCH, 128>>>(W[0], Bv[0], l0, h0, high, FC0, 1);
    relu_k<<<8, 256>>>(z, low, high, act, wlv, whv, bhrv, FCH);

    // ---- layers 2..4: stacked low/high backsub chains (M = 4096) ----
    for (int i = 1; i <= 3; i++) {
        gemv_fwd<<<FCH, 128>>>(W[i], act, Bv[i], z, FCH);
        const float* cur = W[i];
        const float* bL = Bv[i];
        const float* bH = Bv[i];
        int shared = 1;
        for (int j = i - 1; j >= 0; j--) {
            transform_split2_k<<<2 * FCH, 128>>>(cur, shared, TAh, TAl,
                                                 whv + j * FCH, wlv + j * FCH,
                                                 bhrv + j * FCH, Bv[j], bL, bH, b2, FCH, FCH);
            int Nn = (j == 0) ? FC0 : FCH;
            dim3 grid((Nn + 127) / 128, 2 * FCH / 128);
            tc_gemm<<<grid, 256, TCG_SMEM>>>(TAh, TAl, Wth[j], Wtl[j], P, 2 * FCH, Nn, FCH);
            cur = P; shared = 0; bL = b2; bH = b2 + FCH;
        }
        bounds2_k<<<2 * FCH, 128>>>(P, b2, l0, h0, low, high, FC0, FCH);
        relu_k<<<8, 256>>>(z, low, high, act, wlv + i * FCH, whv + i * FCH,
                           bhrv + i * FCH, FCH);
    }

    // ---- layer 5: stacked 20-row skinny chain ----
    gemv_fwd<<<FCOUT, 128>>>(W[4], act, Bv[4], z, FCH);
    {
        const float* cur = W[4];
        const float* bL = Bv[4];
        const float* bH = Bv[4];
        int shared = 1;
        for (int j = 3; j >= 0; j--) {
            transform20_k<<<20, 128>>>(cur, shared, sQ, whv + j * FCH, wlv + j * FCH,
                                       bhrv + j * FCH, Bv[j], bL, bH, sb2, FCH, 10);
            int Nn = (j == 0) ? FC0 : FCH;
            dim3 grid((Nn + 255) / 256, 16);
            sk_gemm20<<<grid, 128>>>(sQ, W[j], part, FCH, Nn);
            sk_reduce20<<<(20 * Nn + 255) / 256, 256>>>(part, sP, Nn);
            cur = sP; shared = 0; bL = sb2; bH = sb2 + 10;
        }
        bounds2_k<<<20, 128>>>(sP, sb2, l0, h0, low, high, FC0, 10);
    }

    assemble_k<<<1, 32>>>(z, low, high, out);
}

// round 8
// speedup vs baseline: 2.1536x; 1.0005x over previous
#include <cuda_runtime.h>
#include <cuda_bf16.h>
#include <cstdint>

#define FC0   784
#define FCH   2048
#define FCOUT 10

// ======================= helpers =======================
__device__ __forceinline__ uint32_t smem_u32(const void* p) {
    uint32_t a;
    asm("{ .reg .u64 t; cvta.to.shared.u64 t, %1; cvt.u32.u64 %0, t; }" : "=r"(a) : "l"(p));
    return a;
}

__device__ __forceinline__ void ldmatrix_x4(uint32_t* r, uint32_t addr) {
    asm volatile("ldmatrix.sync.aligned.m8n8.x4.shared.b16 {%0,%1,%2,%3}, [%4];"
                 : "=r"(r[0]), "=r"(r[1]), "=r"(r[2]), "=r"(r[3]) : "r"(addr));
}
__device__ __forceinline__ void ldmatrix_x4_trans(uint32_t* r, uint32_t addr) {
    asm volatile("ldmatrix.sync.aligned.m8n8.x4.trans.shared.b16 {%0,%1,%2,%3}, [%4];"
                 : "=r"(r[0]), "=r"(r[1]), "=r"(r[2]), "=r"(r[3]) : "r"(addr));
}

__device__ __forceinline__ void mma16816(float* d, const uint32_t* a, const uint32_t* b) {
    asm volatile("mma.sync.aligned.m16n8k16.row.col.f32.bf16.bf16.f32 "
                 "{%0,%1,%2,%3}, {%4,%5,%6,%7}, {%8,%9}, {%0,%1,%2,%3};"
                 : "+f"(d[0]), "+f"(d[1]), "+f"(d[2]), "+f"(d[3])
                 : "r"(a[0]), "r"(a[1]), "r"(a[2]), "r"(a[3]), "r"(b[0]), "r"(b[1]));
}

__device__ __forceinline__ void cp_async16(uint32_t dst, const void* src, int sz) {
    asm volatile("cp.async.cg.shared.global [%0], [%1], 16, %2;"
                 :: "r"(dst), "l"(src), "r"(sz) : "memory");
}
#define CP_COMMIT() asm volatile("cp.async.commit_group;" ::: "memory")
#define CP_WAIT2()  asm volatile("cp.async.wait_group 2;" ::: "memory")

// ======================= scratch (static device globals) =======================
__device__ float g_x0[FC0], g_l0[FC0], g_h0[FC0];
__device__ float g_z[FCH], g_act[FCH];
__device__ float g_low[FCH], g_high[FCH];
__device__ float g_wl[4 * FCH], g_wh[4 * FCH], g_bhr[4 * FCH];
__device__ int   g_idx[4 * FCH];
__device__ int   g_cnt[8];                  // per level: [2j]=count, [2j+1]=NCH
__device__ float g_b2[2 * FCH];
__device__ float g_P[2 * FCH * FCH];
__device__ unsigned short g_TAh[2 * FCH * FCH], g_TAl[2 * FCH * FCH];
__device__ unsigned short g_Wt0h[FCH * FC0], g_Wt0l[FCH * FC0];   // [K=2048, N=784]
__device__ unsigned short g_Wt1h[FCH * FCH], g_Wt1l[FCH * FCH];
__device__ unsigned short g_Wt2h[FCH * FCH], g_Wt2l[FCH * FCH];
__device__ unsigned short g_Wt3h[FCH * FCH], g_Wt3l[FCH * FCH];
__device__ float g_sP[20 * FCH], g_sQ[20 * FCH], g_sb2[20];
__device__ float g_part[16 * 20 * FCH];

// ======================= small helper kernels =======================
__device__ __forceinline__ float blockReduceSum(float v) {
    __shared__ float sh[32];
    int lane = threadIdx.x & 31, wid = threadIdx.x >> 5;
#pragma unroll
    for (int o = 16; o > 0; o >>= 1) v += __shfl_down_sync(0xffffffffu, v, o);
    if (lane == 0) sh[wid] = v;
    __syncthreads();
    int nw = blockDim.x >> 5;
    v = (threadIdx.x < nw) ? sh[threadIdx.x] : 0.f;
    if (wid == 0) {
#pragma unroll
        for (int o = 16; o > 0; o >>= 1) v += __shfl_down_sync(0xffffffffu, v, o);
    }
    return v;
}

__global__ void norm_k(const float* __restrict__ x, const float* __restrict__ lo,
                       const float* __restrict__ hi, float* __restrict__ x0,
                       float* __restrict__ l0, float* __restrict__ h0) {
    int i = blockIdx.x * blockDim.x + threadIdx.x;
    if (i < FC0) {
        const float mean = 0.1307f, stdv = 0.3081f;
        x0[i] = (x[i] - mean) / stdv;
        l0[i] = (lo[i] - mean) / stdv;
        h0[i] = (hi[i] - mean) / stdv;
    }
}

__global__ void gemv_fwd(const float* __restrict__ W, const float* __restrict__ xin,
                         const float* __restrict__ b, float* __restrict__ z, int K) {
    int row = blockIdx.x;
    const float4* Wr = (const float4*)(W + (size_t)row * K);
    const float4* X4 = (const float4*)xin;
    float s = 0.f;
    for (int k = threadIdx.x; k < (K >> 2); k += blockDim.x) {
        float4 w = Wr[k], xv = X4[k];
        s += w.x * xv.x + w.y * xv.y + w.z * xv.z + w.w * xv.w;
    }
    s = blockReduceSum(s);
    if (threadIdx.x == 0) z[row] = s + b[row];
}

__global__ void bounds_k(const float* __restrict__ M, const float* __restrict__ bias,
                         const float* __restrict__ l0, const float* __restrict__ h0,
                         float* __restrict__ out, int K, int is_high) {
    int row = blockIdx.x;
    const float* Mr = M + (size_t)row * K;
    float s = 0.f;
    for (int k = threadIdx.x; k < K; k += blockDim.x) {
        float m = Mr[k];
        float mn = fminf(m, 0.f), mp = fmaxf(m, 0.f);
        float lv = l0[k], hv = h0[k];
        s += is_high ? (mn * lv + mp * hv) : (mn * hv + mp * lv);
    }
    s = blockReduceSum(s);
    if (threadIdx.x == 0) out[row] = s + bias[row];
}

// stacked bounds: rows [0,half) -> low, rows [half,2*half) -> high
__global__ void bounds2_k(const float* __restrict__ M, const float* __restrict__ bias,
                          const float* __restrict__ l0, const float* __restrict__ h0,
                          float* __restrict__ lowv, float* __restrict__ highv,
                          int K, int half) {
    int row = blockIdx.x;
    int is_high = row >= half;
    int r = is_high ? row - half : row;
    const float* Mr = M + (size_t)row * K;
    float s = 0.f;
    for (int k = threadIdx.x; k < K; k += blockDim.x) {
        float m = Mr[k];
        float mn = fminf(m, 0.f), mp = fmaxf(m, 0.f);
        float lv = l0[k], hv = h0[k];
        s += is_high ? (mn * lv + mp * hv) : (mn * hv + mp * lv);
    }
    s = blockReduceSum(s);
    if (threadIdx.x == 0) {
        float* dst = is_high ? highv : lowv;
        dst[r] = s + bias[row];
    }
}

// ---- relu relaxation + deterministic column compaction (single block, 1024 thr) ----
__global__ void relu_scan_k(const float* __restrict__ z, const float* __restrict__ low,
                            const float* __restrict__ high, float* __restrict__ act,
                            float* __restrict__ wl, float* __restrict__ wh,
                            float* __restrict__ bhr, int* __restrict__ idx,
                            int* __restrict__ cnt) {
    int tid = threadIdx.x;  // 1024; 2 elements each
    __shared__ int wsum[32];
    __shared__ int stotal;
    int m[2];
#pragma unroll
    for (int e = 0; e < 2; e++) {
        int i = tid * 2 + e;
        float lo = low[i], hi = high[i];
        float w_h, w_l, b_h;
        if (lo < 0.f && hi > 0.f) {
            float d = hi - lo;
            w_h = hi / d;
            b_h = -(lo * hi) / d;
            w_l = (lo * lo > hi * hi) ? 0.f : 1.f;
        } else {
            float keep = (hi <= 0.f) ? 0.f : 1.f;
            w_h = keep; w_l = keep; b_h = 0.f;
        }
        wl[i] = w_l; wh[i] = w_h; bhr[i] = b_h;
        act[i] = fmaxf(z[i], 0.f);
        m[e] = (w_h != 0.f) ? 1 : 0;
    }
    int tsum = m[0] + m[1];
    int lane = tid & 31, wrp = tid >> 5;
    int incl = tsum;
#pragma unroll
    for (int o = 1; o < 32; o <<= 1) {
        int v = __shfl_up_sync(0xffffffffu, incl, o);
        if (lane >= o) incl += v;
    }
    if (lane == 31) wsum[wrp] = incl;
    __syncthreads();
    if (wrp == 0) {
        int v = wsum[lane], iv = v;
#pragma unroll
        for (int o = 1; o < 32; o <<= 1) {
            int u = __shfl_up_sync(0xffffffffu, iv, o);
            if (lane >= o) iv += u;
        }
        wsum[lane] = iv - v;  // exclusive warp bases
    }
    __syncthreads();
    int excl = wsum[wrp] + incl - tsum;
    if (m[0]) idx[excl] = tid * 2;
    if (m[1]) idx[excl + m[0]] = tid * 2 + 1;
    if (tid == 1023) stotal = excl + tsum;
    __syncthreads();
    int total = stotal;
    for (int p = total + tid; p < FCH; p += 1024) idx[p] = 0;  // safe pad rows
    if (tid == 0) { cnt[0] = total; cnt[1] = (total + 31) >> 5; }
}

// elementwise bf16 hi/lo split, NO transpose: W [K,N] fp32 -> same-layout bf16
__global__ void wt_split_nt(const float* __restrict__ W, unsigned short* __restrict__ Bh,
                            unsigned short* __restrict__ Bl, int total4) {
    int i = blockIdx.x * blockDim.x + threadIdx.x;
    if (i >= total4) return;
    float4 v = ((const float4*)W)[i];
    __nv_bfloat16 h0 = __float2bfloat16(v.x), h1 = __float2bfloat16(v.y);
    __nv_bfloat16 h2 = __float2bfloat16(v.z), h3 = __float2bfloat16(v.w);
    __nv_bfloat16 q0 = __float2bfloat16(v.x - __bfloat162float(h0));
    __nv_bfloat16 q1 = __float2bfloat16(v.y - __bfloat162float(h1));
    __nv_bfloat16 q2 = __float2bfloat16(v.z - __bfloat162float(h2));
    __nv_bfloat16 q3 = __float2bfloat16(v.w - __bfloat162float(h3));
    uint2 uh, ul;
    uh.x = (uint32_t)__bfloat16_as_ushort(h0) | ((uint32_t)__bfloat16_as_ushort(h1) << 16);
    uh.y = (uint32_t)__bfloat16_as_ushort(h2) | ((uint32_t)__bfloat16_as_ushort(h3) << 16);
    ul.x = (uint32_t)__bfloat16_as_ushort(q0) | ((uint32_t)__bfloat16_as_ushort(q1) << 16);
    ul.y = (uint32_t)__bfloat16_as_ushort(q2) | ((uint32_t)__bfloat16_as_ushort(q3) << 16);
    ((uint2*)Bh)[i] = uh;
    ((uint2*)Bl)[i] = ul;
}

// ---- gathered stacked transform + bias + bf16 split (compacted K columns) ----
__global__ void transform_g_k(const float* __restrict__ Mraw, int shared_src,
                              unsigned short* __restrict__ TAh, unsigned short* __restrict__ TAl,
                              const float* __restrict__ whv, const float* __restrict__ wlv,
                              const float* __restrict__ bhrv, const float* __restrict__ blin,
                              const float* __restrict__ biasL, const float* __restrict__ biasH,
                              float* __restrict__ bias_out,
                              const int* __restrict__ idx, const int* __restrict__ cnt,
                              int half) {
    int row = blockIdx.x;
    int is_high = row >= half;
    int r = is_high ? row - half : row;
    int srow = shared_src ? r : row;
    const float* Mr = Mraw + (size_t)srow * FCH;
    int Kact = cnt[0], K32 = cnt[1] * 32;
    uint32_t* TH = (uint32_t*)(TAh + (size_t)row * FCH);
    uint32_t* TL = (uint32_t*)(TAl + (size_t)row * FCH);
    float s = 0.f;
    for (int kk = threadIdx.x * 2; kk < K32; kk += 256) {
        float t0 = 0.f, t1 = 0.f;
#pragma unroll
        for (int e = 0; e < 2; e++) {
            int kke = kk + e;
            if (kke < Kact) {
                int k = idx[kke];
                float mm = Mr[k];
                float hh = whv[k], ll = wlv[k];
                float spos = is_high ? hh : ll, sneg = is_high ? ll : hh;
                float tv = (mm > 0.f) ? mm * spos : mm * sneg;
                float p = is_high ? fmaxf(mm, 0.f) : fminf(mm, 0.f);
                s += p * bhrv[k] + tv * blin[k];
                if (e) t1 = tv; else t0 = tv;
            }
        }
        __nv_bfloat16 h0 = __float2bfloat16(t0), h1 = __float2bfloat16(t1);
        __nv_bfloat16 q0 = __float2bfloat16(t0 - __bfloat162float(h0));
        __nv_bfloat16 q1 = __float2bfloat16(t1 - __bfloat162float(h1));
        TH[kk >> 1] = (uint32_t)__bfloat16_as_ushort(h0) | ((uint32_t)__bfloat16_as_ushort(h1) << 16);
        TL[kk >> 1] = (uint32_t)__bfloat16_as_ushort(q0) | ((uint32_t)__bfloat16_as_ushort(q1) << 16);
    }
    s = blockReduceSum(s);
    if (threadIdx.x == 0)
        bias_out[row] = (is_high ? biasH[r] : biasL[r]) + s;
}

// gathered fp32 transform for skinny (20-row) chain; zero-pads full 2048
__global__ void transform20g_k(const float* __restrict__ Mraw, int shared_src,
                               float* __restrict__ TA,
                               const float* __restrict__ whv, const float* __restrict__ wlv,
                               const float* __restrict__ bhrv, const float* __restrict__ blin,
                               const float* __restrict__ biasL, const float* __restrict__ biasH,
                               float* __restrict__ bias_out,
                               const int* __restrict__ idx, const int* __restrict__ cnt,
                               int half) {
    int row = blockIdx.x;
    int is_high = row >= half;
    int r = is_high ? row - half : row;
    int srow = shared_src ? r : row;
    const float* Mr = Mraw + (size_t)srow * FCH;
    int Kact = cnt[0];
    float s = 0.f;
    for (int kk = threadIdx.x; kk < FCH; kk += 128) {
        float tv = 0.f;
        if (kk < Kact) {
            int k = idx[kk];
            float mm = Mr[k];
            float hh = whv[k], ll = wlv[k];
            float spos = is_high ? hh : ll, sneg = is_high ? ll : hh;
            tv = (mm > 0.f) ? mm * spos : mm * sneg;
            float p = is_high ? fmaxf(mm, 0.f) : fminf(mm, 0.f);
            s += p * bhrv[k] + tv * blin[k];
        }
        TA[(size_t)row * FCH + kk] = tv;
    }
    s = blockReduceSum(s);
    if (threadIdx.x == 0)
        bias_out[row] = (is_high ? biasH[r] : biasL[r]) + s;
}

// ======================= dynamic-K gathered bf16-split GEMM =======================
// C[4096,N] += (Ah+Al)[4096,K'] @ gatherRows(Wh+Wl)[K',N]
// A compacted K-major bf16 (stride FCH); W natural [2048,N] bf16; B tiles via ldmatrix.trans.
#define ROWB   80
#define A_MATB (128 * ROWB)               // 10240
#define ROWN   272
#define B_MATB (32 * ROWN)                // 8704
#define STAGEB (2 * A_MATB + 2 * B_MATB)  // 37888
#define TCG_SMEM (3 * STAGEB)             // 113664

__global__ __launch_bounds__(256, 1) void tc_gemm_g(
    const unsigned short* __restrict__ Ah, const unsigned short* __restrict__ Al,
    const unsigned short* __restrict__ Wh, const unsigned short* __restrict__ Wl,
    const int* __restrict__ idx, const int* __restrict__ cnt,
    float* __restrict__ C, int N) {
    extern __shared__ char smem[];
    const uint32_t sbase = smem_u32(smem);
    const int tid = threadIdx.x, lane = tid & 31, wid = tid >> 5;
    const int wm = wid & 1, wn = wid >> 1;
    const int m0 = blockIdx.y * 128, n0 = blockIdx.x * 128;
    const int NCH = cnt[1];

    auto fill = [&](int stage, int kc) {
        int k0 = kc * 32;
        uint32_t sb = sbase + stage * STAGEB;
#pragma unroll
        for (int i = 0; i < 8; i++) {
            int c = tid + i * 256;
            if (c < 1024) {  // A: 128 rows x 32 k (x2 mats)
                int mat = c >> 9, rem = c & 511, row = rem >> 2, seg = rem & 3;
                uint32_t dst = sb + mat * A_MATB + row * ROWB + seg * 16;
                const unsigned short* src =
                    (mat ? Al : Ah) + (size_t)(m0 + row) * FCH + k0 + seg * 8;
                cp_async16(dst, src, 16);
            } else {         // B: 32 gathered k-rows x 128 n (x2 mats)
                int d = c - 1024, mat = d >> 9, rem = d & 511, r = rem >> 4, seg = rem & 15;
                uint32_t dst = sb + 2 * A_MATB + mat * B_MATB + r * ROWN + seg * 16;
                int gc = n0 + seg * 8;
                int krow = idx[k0 + r];
                const unsigned short* src = (mat ? Wl : Wh) + (size_t)krow * N + gc;
                cp_async16(dst, src, (gc < N) ? 16 : 0);
            }
        }
    };

    float acc[4][4][4];
#pragma unroll
    for (int a = 0; a < 4; a++)
#pragma unroll
        for (int b = 0; b < 4; b++)
#pragma unroll
            for (int q = 0; q < 4; q++) acc[a][b][q] = 0.f;

    for (int p = 0; p < 3; p++) {
        if (p < NCH) fill(p, p);
        CP_COMMIT();
    }

    const int a_r = (lane & 7) + ((lane >> 3) & 1) * 8;
    const int a_s = lane >> 4;
    const int b_g = lane >> 3, b_r = lane & 7;   // trans-ldmatrix group/row

    int st = 0;
    for (int t = 0; t < NCH; t++) {
        CP_WAIT2();
        __syncthreads();
        uint32_t sb = sbase + st * STAGEB;
        uint32_t aH = sb, aL = sb + A_MATB;
        uint32_t bHb = sb + 2 * A_MATB, bLb = bHb + B_MATB;
#pragma unroll
        for (int kk = 0; kk < 2; kk++) {
            uint32_t ah[4][4], al[4][4], bh[4][2], bl[4][2];
#pragma unroll
            for (int mt = 0; mt < 4; mt++) {
                int row = wm * 64 + mt * 16 + a_r;
                uint32_t off = (uint32_t)row * ROWB + (kk * 2 + a_s) * 16;
                ldmatrix_x4(ah[mt], aH + off);
                ldmatrix_x4(al[mt], aL + off);
            }
#pragma unroll
            for (int p = 0; p < 2; p++) {
                int nw = wn * 32 + p * 16;
                uint32_t off = (uint32_t)(kk * 16 + (b_g & 1) * 8 + b_r) * ROWN
                             + (uint32_t)(nw + (b_g >> 1) * 8) * 2;
                uint32_t r4[4];
                ldmatrix_x4_trans(r4, bHb + off);
                bh[2 * p][0] = r4[0]; bh[2 * p][1] = r4[1];
                bh[2 * p + 1][0] = r4[2]; bh[2 * p + 1][1] = r4[3];
                ldmatrix_x4_trans(r4, bLb + off);
                bl[2 * p][0] = r4[0]; bl[2 * p][1] = r4[1];
                bl[2 * p + 1][0] = r4[2]; bl[2 * p + 1][1] = r4[3];
            }
#pragma unroll
            for (int mt = 0; mt < 4; mt++)
#pragma unroll
                for (int nt = 0; nt < 4; nt++) {
                    mma16816(acc[mt][nt], ah[mt], bh[nt]);
                    mma16816(acc[mt][nt], ah[mt], bl[nt]);
                    mma16816(acc[mt][nt], al[mt], bh[nt]);
                }
        }
        __syncthreads();
        if (t + 3 < NCH) fill(st, t + 3);
        CP_COMMIT();
        st = (st == 2) ? 0 : st + 1;
    }

    int rbase = m0 + wm * 64 + (lane >> 2);
    int cbase = n0 + wn * 32 + (lane & 3) * 2;
#pragma unroll
    for (int mt = 0; mt < 4; mt++) {
#pragma unroll
        for (int nt = 0; nt < 4; nt++) {
            int c = cbase + nt * 8;
            if (c < N) {
                int r = rbase + mt * 16;
                float2* p0 = (float2*)(C + (size_t)r * N + c);
                float2* p1 = (float2*)(C + (size_t)(r + 8) * N + c);
                *p0 = make_float2(acc[mt][nt][0], acc[mt][nt][1]);
                *p1 = make_float2(acc[mt][nt][2], acc[mt][nt][3]);
            }
        }
    }
}

// ------------- skinny GEMM (20 rows, gathered K) -------------
__global__ void sk_gemm20g(const float* __restrict__ TA, const float* __restrict__ B,
                           const int* __restrict__ idx, float* __restrict__ part,
                           int K, int N) {
    __shared__ float sTA[20][128];
    int tid = threadIdx.x;           // 128
    int kb = blockIdx.y;             // 0..15
    int kbase = kb * 128;
    int col0 = blockIdx.x * 256 + tid * 2;
    for (int i2 = tid; i2 < 20 * 128; i2 += 128) {
        int r = i2 >> 7, k = i2 & 127;
        sTA[r][k] = TA[(size_t)r * K + kbase + k];
    }
    __syncthreads();
    if (col0 >= N) return;
    float2 acc[20];
#pragma unroll
    for (int r = 0; r < 20; r++) acc[r] = make_float2(0.f, 0.f);
    for (int k = 0; k < 128; k++) {
        int krow = idx[kbase + k];
        float2 bv = *(const float2*)(B + (size_t)krow * N + col0);
#pragma unroll
        for (int r = 0; r < 20; r++) {
            float sv = sTA[r][k];
            acc[r].x += sv * bv.x;
            acc[r].y += sv * bv.y;
        }
    }
#pragma unroll
    for (int r = 0; r < 20; r++)
        *(float2*)(part + (size_t)(kb * 20 + r) * N + col0) = acc[r];
}

__global__ void sk_reduce20(const float* __restrict__ part, float* __restrict__ C, int N) {
    int i = blockIdx.x * blockDim.x + threadIdx.x;
    if (i >= 20 * N) return;
    int r = i / N, c = i - r * N;
    float s = 0.f;
#pragma unroll
    for (int ks = 0; ks < 16; ks++) s += part[(size_t)(ks * 20 + r) * N + c];
    C[(size_t)r * N + c] = s;
}

__global__ void assemble_k(const float* __restrict__ z, const float* __restrict__ low,
                           const float* __restrict__ high, float* __restrict__ out) {
    int i = threadIdx.x;
    if (i < FCOUT) {
        out[i]      = z[i];
        out[10 + i] = low[i];
        out[20 + i] = high[i];
    }
}

// =======================================================================
extern "C" void kernel_launch(void* const* d_in, const int* in_sizes, int n_in,
                              void* d_out, int out_size) {
    (void)in_sizes; (void)n_in; (void)out_size;
    const float* X  = (const float*)d_in[0];
    const float* LO = (const float*)d_in[1];
    const float* HI = (const float*)d_in[2];
    const float* W[5];
    const float* Bv[5];
    for (int i = 0; i < 5; i++) {
        W[i]  = (const float*)d_in[3 + 2 * i];
        Bv[i] = (const float*)d_in[4 + 2 * i];
    }
    float* out = (float*)d_out;

    float *x0, *l0, *h0, *z, *act, *low, *high, *b2, *P, *sP, *sQ, *sb2, *part;
    float *wlv, *whv, *bhrv;
    int *idxv, *cntv;
    unsigned short *TAh, *TAl;
    unsigned short *Wth[4], *Wtl[4];
    cudaGetSymbolAddress((void**)&x0, g_x0);
    cudaGetSymbolAddress((void**)&l0, g_l0);
    cudaGetSymbolAddress((void**)&h0, g_h0);
    cudaGetSymbolAddress((void**)&z, g_z);
    cudaGetSymbolAddress((void**)&act, g_act);
    cudaGetSymbolAddress((void**)&low, g_low);
    cudaGetSymbolAddress((void**)&high, g_high);
    cudaGetSymbolAddress((void**)&b2, g_b2);
    cudaGetSymbolAddress((void**)&P, g_P);
    cudaGetSymbolAddress((void**)&sP, g_sP);
    cudaGetSymbolAddress((void**)&sQ, g_sQ);
    cudaGetSymbolAddress((void**)&sb2, g_sb2);
    cudaGetSymbolAddress((void**)&part, g_part);
    cudaGetSymbolAddress((void**)&wlv, g_wl);
    cudaGetSymbolAddress((void**)&whv, g_wh);
    cudaGetSymbolAddress((void**)&bhrv, g_bhr);
    cudaGetSymbolAddress((void**)&idxv, g_idx);
    cudaGetSymbolAddress((void**)&cntv, g_cnt);
    cudaGetSymbolAddress((void**)&TAh, g_TAh);
    cudaGetSymbolAddress((void**)&TAl, g_TAl);
    cudaGetSymbolAddress((void**)&Wth[0], g_Wt0h);
    cudaGetSymbolAddress((void**)&Wtl[0], g_Wt0l);
    cudaGetSymbolAddress((void**)&Wth[1], g_Wt1h);
    cudaGetSymbolAddress((void**)&Wtl[1], g_Wt1l);
    cudaGetSymbolAddress((void**)&Wth[2], g_Wt2h);
    cudaGetSymbolAddress((void**)&Wtl[2], g_Wt2l);
    cudaGetSymbolAddress((void**)&Wth[3], g_Wt3h);
    cudaGetSymbolAddress((void**)&Wtl[3], g_Wt3l);

    cudaFuncSetAttribute(tc_gemm_g, cudaFuncAttributeMaxDynamicSharedMemorySize, TCG_SMEM);

    // weight bf16 split in natural [K,N] layout (no transpose)
    wt_split_nt<<<(FCH * FC0 / 4 + 255) / 256, 256>>>(W[0], Wth[0], Wtl[0], FCH * FC0 / 4);
    for (int j = 1; j <= 3; j++)
        wt_split_nt<<<(FCH * FCH / 4 + 255) / 256, 256>>>(W[j], Wth[j], Wtl[j], FCH * FCH / 4);

    norm_k<<<4, 256>>>(X, LO, HI, x0, l0, h0);

    // ---- layer 1 ----
    gemv_fwd<<<FCH, 128>>>(W[0], x0, Bv[0], z, FC0);
    bounds_k<<<FCH, 128>>>(W[0], Bv[0], l0, h0, low, FC0, 0);
    bounds_k<<<FCH, 128>>>(W[0], Bv[0], l0, h0, high, FC0, 1);
    relu_scan_k<<<1, 1024>>>(z, low, high, act, wlv, whv, bhrv, idxv, cntv);

    // ---- layers 2..4: stacked low/high chains with compacted K ----
    for (int i = 1; i <= 3; i++) {
        gemv_fwd<<<FCH, 128>>>(W[i], act, Bv[i], z, FCH);
        const float* cur = W[i];
        const float* bL = Bv[i];
        const float* bH = Bv[i];
        int shared = 1;
        for (int j = i - 1; j >= 0; j--) {
            transform_g_k<<<2 * FCH, 128>>>(cur, shared, TAh, TAl,
                                            whv + j * FCH, wlv + j * FCH,
                                            bhrv + j * FCH, Bv[j], bL, bH, b2,
                                            idxv + j * FCH, cntv + 2 * j, FCH);
            int Nn = (j == 0) ? FC0 : FCH;
            dim3 grid((Nn + 127) / 128, 2 * FCH / 128);
            tc_gemm_g<<<grid, 256, TCG_SMEM>>>(TAh, TAl, Wth[j], Wtl[j],
                                               idxv + j * FCH, cntv + 2 * j, P, Nn);
            cur = P; shared = 0; bL = b2; bH = b2 + FCH;
        }
        bounds2_k<<<2 * FCH, 128>>>(P, b2, l0, h0, low, high, FC0, FCH);
        relu_scan_k<<<1, 1024>>>(z, low, high, act, wlv + i * FCH, whv + i * FCH,
                                 bhrv + i * FCH, idxv + i * FCH, cntv + 2 * i);
    }

    // ---- layer 5: stacked 20-row skinny chain (gathered) ----
    gemv_fwd<<<FCOUT, 128>>>(W[4], act, Bv[4], z, FCH);
    {
        const float* cur = W[4];
        const float* bL = Bv[4];
        const float* bH = Bv[4];
        int shared = 1;
        for (int j = 3; j >= 0; j--) {
            transform20g_k<<<20, 128>>>(cur, shared, sQ, whv + j * FCH, wlv + j * FCH,
                                        bhrv + j * FCH, Bv[j], bL, bH, sb2,
                                        idxv + j * FCH, cntv + 2 * j, 10);
            int Nn = (j == 0) ? FC0 : FCH;
            dim3 grid((Nn + 255) / 256, 16);
            sk_gemm20g<<<grid, 128>>>(sQ, W[j], idxv + j * FCH, part, FCH, Nn);
            sk_reduce20<<<(20 * Nn + 255) / 256, 256>>>(part, sP, Nn);
            cur = sP; shared = 0; bL = sb2; bH = sb2 + 10;
        }
        bounds2_k<<<20, 128>>>(sP, sb2, l0, h0, low, high, FC0, 10);
    }

    assemble_k<<<1, 32>>>(z, low, high, out);
}

// round 10
// speedup vs baseline: 2.3276x; 1.0808x over previous
#include <cuda_runtime.h>
#include <cuda_bf16.h>
#include <cstdint>

#define FC0   784
#define FCH   2048
#define FCOUT 10

// ======================= helpers =======================
__device__ __forceinline__ uint32_t smem_u32(const void* p) {
    uint32_t a;
    asm("{ .reg .u64 t; cvta.to.shared.u64 t, %1; cvt.u32.u64 %0, t; }" : "=r"(a) : "l"(p));
    return a;
}

__device__ __forceinline__ void ldmatrix_x4(uint32_t* r, uint32_t addr) {
    asm volatile("ldmatrix.sync.aligned.m8n8.x4.shared.b16 {%0,%1,%2,%3}, [%4];"
                 : "=r"(r[0]), "=r"(r[1]), "=r"(r[2]), "=r"(r[3]) : "r"(addr));
}
__device__ __forceinline__ void ldmatrix_x4_trans(uint32_t* r, uint32_t addr) {
    asm volatile("ldmatrix.sync.aligned.m8n8.x4.trans.shared.b16 {%0,%1,%2,%3}, [%4];"
                 : "=r"(r[0]), "=r"(r[1]), "=r"(r[2]), "=r"(r[3]) : "r"(addr));
}

__device__ __forceinline__ void mma16816(float* d, const uint32_t* a, const uint32_t* b) {
    asm volatile("mma.sync.aligned.m16n8k16.row.col.f32.bf16.bf16.f32 "
                 "{%0,%1,%2,%3}, {%4,%5,%6,%7}, {%8,%9}, {%0,%1,%2,%3};"
                 : "+f"(d[0]), "+f"(d[1]), "+f"(d[2]), "+f"(d[3])
                 : "r"(a[0]), "r"(a[1]), "r"(a[2]), "r"(a[3]), "r"(b[0]), "r"(b[1]));
}

__device__ __forceinline__ void cp_async16(uint32_t dst, const void* src, int sz) {
    asm volatile("cp.async.cg.shared.global [%0], [%1], 16, %2;"
                 :: "r"(dst), "l"(src), "r"(sz) : "memory");
}
#define CP_COMMIT() asm volatile("cp.async.commit_group;" ::: "memory")
#define CP_WAIT1()  asm volatile("cp.async.wait_group 1;" ::: "memory")

// ======================= scratch (static device globals) =======================
__device__ float g_x0[FC0], g_l0[FC0], g_h0[FC0];
__device__ float g_z[FCH], g_act[FCH];
__device__ float g_low[FCH], g_high[FCH];
__device__ float g_wl[4 * FCH], g_wh[4 * FCH], g_bhr[4 * FCH];
__device__ int   g_idx[4 * FCH];
__device__ int   g_cnt[8];                  // per level: [2j]=count, [2j+1]=NCH
__device__ float g_b2[2 * FCH];
__device__ float g_P[2 * FCH * FCH];
__device__ unsigned short g_TAh[2 * FCH * FCH], g_TAl[2 * FCH * FCH];
__device__ unsigned short g_Wt0h[FCH * FC0], g_Wt0l[FCH * FC0];   // [K=2048, N=784]
__device__ unsigned short g_Wt1h[FCH * FCH], g_Wt1l[FCH * FCH];
__device__ unsigned short g_Wt2h[FCH * FCH], g_Wt2l[FCH * FCH];
__device__ unsigned short g_Wt3h[FCH * FCH], g_Wt3l[FCH * FCH];
__device__ float g_sP[20 * FCH], g_sQ[20 * FCH], g_sb2[20];
__device__ float g_part[16 * 20 * FCH];

// ======================= small helper kernels =======================
__device__ __forceinline__ float blockReduceSum(float v) {
    __shared__ float sh[32];
    int lane = threadIdx.x & 31, wid = threadIdx.x >> 5;
#pragma unroll
    for (int o = 16; o > 0; o >>= 1) v += __shfl_down_sync(0xffffffffu, v, o);
    if (lane == 0) sh[wid] = v;
    __syncthreads();
    int nw = blockDim.x >> 5;
    v = (threadIdx.x < nw) ? sh[threadIdx.x] : 0.f;
    if (wid == 0) {
#pragma unroll
        for (int o = 16; o > 0; o >>= 1) v += __shfl_down_sync(0xffffffffu, v, o);
    }
    return v;
}

__global__ void norm_k(const float* __restrict__ x, const float* __restrict__ lo,
                       const float* __restrict__ hi, float* __restrict__ x0,
                       float* __restrict__ l0, float* __restrict__ h0) {
    int i = blockIdx.x * blockDim.x + threadIdx.x;
    if (i < FC0) {
        const float mean = 0.1307f, stdv = 0.3081f;
        x0[i] = (x[i] - mean) / stdv;
        l0[i] = (lo[i] - mean) / stdv;
        h0[i] = (hi[i] - mean) / stdv;
    }
}

__global__ void gemv_fwd(const float* __restrict__ W, const float* __restrict__ xin,
                         const float* __restrict__ b, float* __restrict__ z, int K) {
    int row = blockIdx.x;
    const float4* Wr = (const float4*)(W + (size_t)row * K);
    const float4* X4 = (const float4*)xin;
    float s = 0.f;
    for (int k = threadIdx.x; k < (K >> 2); k += blockDim.x) {
        float4 w = Wr[k], xv = X4[k];
        s += w.x * xv.x + w.y * xv.y + w.z * xv.z + w.w * xv.w;
    }
    s = blockReduceSum(s);
    if (threadIdx.x == 0) z[row] = s + b[row];
}

__global__ void bounds_k(const float* __restrict__ M, const float* __restrict__ bias,
                         const float* __restrict__ l0, const float* __restrict__ h0,
                         float* __restrict__ out, int K, int is_high) {
    int row = blockIdx.x;
    const float* Mr = M + (size_t)row * K;
    float s = 0.f;
    for (int k = threadIdx.x; k < K; k += blockDim.x) {
        float m = Mr[k];
        float mn = fminf(m, 0.f), mp = fmaxf(m, 0.f);
        float lv = l0[k], hv = h0[k];
        s += is_high ? (mn * lv + mp * hv) : (mn * hv + mp * lv);
    }
    s = blockReduceSum(s);
    if (threadIdx.x == 0) out[row] = s + bias[row];
}

// stacked bounds: rows [0,half) -> low, rows [half,2*half) -> high
__global__ void bounds2_k(const float* __restrict__ M, const float* __restrict__ bias,
                          const float* __restrict__ l0, const float* __restrict__ h0,
                          float* __restrict__ lowv, float* __restrict__ highv,
                          int K, int half) {
    int row = blockIdx.x;
    int is_high = row >= half;
    int r = is_high ? row - half : row;
    const float* Mr = M + (size_t)row * K;
    float s = 0.f;
    for (int k = threadIdx.x; k < K; k += blockDim.x) {
        float m = Mr[k];
        float mn = fminf(m, 0.f), mp = fmaxf(m, 0.f);
        float lv = l0[k], hv = h0[k];
        s += is_high ? (mn * lv + mp * hv) : (mn * hv + mp * lv);
    }
    s = blockReduceSum(s);
    if (threadIdx.x == 0) {
        float* dst = is_high ? highv : lowv;
        dst[r] = s + bias[row];
    }
}

// ---- relu relaxation + deterministic column compaction (single block, 1024 thr) ----
__global__ void relu_scan_k(const float* __restrict__ z, const float* __restrict__ low,
                            const float* __restrict__ high, float* __restrict__ act,
                            float* __restrict__ wl, float* __restrict__ wh,
                            float* __restrict__ bhr, int* __restrict__ idx,
                            int* __restrict__ cnt) {
    int tid = threadIdx.x;  // 1024; 2 elements each
    __shared__ int wsum[32];
    __shared__ int stotal;
    int m[2];
#pragma unroll
    for (int e = 0; e < 2; e++) {
        int i = tid * 2 + e;
        float lo = low[i], hi = high[i];
        float w_h, w_l, b_h;
        if (lo < 0.f && hi > 0.f) {
            float d = hi - lo;
            w_h = hi / d;
            b_h = -(lo * hi) / d;
            w_l = (lo * lo > hi * hi) ? 0.f : 1.f;
        } else {
            float keep = (hi <= 0.f) ? 0.f : 1.f;
            w_h = keep; w_l = keep; b_h = 0.f;
        }
        wl[i] = w_l; wh[i] = w_h; bhr[i] = b_h;
        act[i] = fmaxf(z[i], 0.f);
        m[e] = (w_h != 0.f) ? 1 : 0;
    }
    int tsum = m[0] + m[1];
    int lane = tid & 31, wrp = tid >> 5;
    int incl = tsum;
#pragma unroll
    for (int o = 1; o < 32; o <<= 1) {
        int v = __shfl_up_sync(0xffffffffu, incl, o);
        if (lane >= o) incl += v;
    }
    if (lane == 31) wsum[wrp] = incl;
    __syncthreads();
    if (wrp == 0) {
        int v = wsum[lane], iv = v;
#pragma unroll
        for (int o = 1; o < 32; o <<= 1) {
            int u = __shfl_up_sync(0xffffffffu, iv, o);
            if (lane >= o) iv += u;
        }
        wsum[lane] = iv - v;  // exclusive warp bases
    }
    __syncthreads();
    int excl = wsum[wrp] + incl - tsum;
    if (m[0]) idx[excl] = tid * 2;
    if (m[1]) idx[excl + m[0]] = tid * 2 + 1;
    if (tid == 1023) stotal = excl + tsum;
    __syncthreads();
    int total = stotal;
    for (int p = total + tid; p < FCH; p += 1024) idx[p] = 0;  // safe pad rows
    if (tid == 0) { cnt[0] = total; cnt[1] = (total + 31) >> 5; }
}

// elementwise bf16 hi/lo split, NO transpose: W [K,N] fp32 -> same-layout bf16
__global__ void wt_split_nt(const float* __restrict__ W, unsigned short* __restrict__ Bh,
                            unsigned short* __restrict__ Bl, int total4) {
    int i = blockIdx.x * blockDim.x + threadIdx.x;
    if (i >= total4) return;
    float4 v = ((const float4*)W)[i];
    __nv_bfloat16 h0 = __float2bfloat16(v.x), h1 = __float2bfloat16(v.y);
    __nv_bfloat16 h2 = __float2bfloat16(v.z), h3 = __float2bfloat16(v.w);
    __nv_bfloat16 q0 = __float2bfloat16(v.x - __bfloat162float(h0));
    __nv_bfloat16 q1 = __float2bfloat16(v.y - __bfloat162float(h1));
    __nv_bfloat16 q2 = __float2bfloat16(v.z - __bfloat162float(h2));
    __nv_bfloat16 q3 = __float2bfloat16(v.w - __bfloat162float(h3));
    uint2 uh, ul;
    uh.x = (uint32_t)__bfloat16_as_ushort(h0) | ((uint32_t)__bfloat16_as_ushort(h1) << 16);
    uh.y = (uint32_t)__bfloat16_as_ushort(h2) | ((uint32_t)__bfloat16_as_ushort(h3) << 16);
    ul.x = (uint32_t)__bfloat16_as_ushort(q0) | ((uint32_t)__bfloat16_as_ushort(q1) << 16);
    ul.y = (uint32_t)__bfloat16_as_ushort(q2) | ((uint32_t)__bfloat16_as_ushort(q3) << 16);
    ((uint2*)Bh)[i] = uh;
    ((uint2*)Bl)[i] = ul;
}

// ---- gathered stacked transform + bias + bf16 split (compacted K columns) ----
__global__ void transform_g_k(const float* __restrict__ Mraw, int shared_src,
                              unsigned short* __restrict__ TAh, unsigned short* __restrict__ TAl,
                              const float* __restrict__ whv, const float* __restrict__ wlv,
                              const float* __restrict__ bhrv, const float* __restrict__ blin,
                              const float* __restrict__ biasL, const float* __restrict__ biasH,
                              float* __restrict__ bias_out,
                              const int* __restrict__ idx, const int* __restrict__ cnt,
                              int half) {
    int row = blockIdx.x;
    int is_high = row >= half;
    int r = is_high ? row - half : row;
    int srow = shared_src ? r : row;
    const float* Mr = Mraw + (size_t)srow * FCH;
    int Kact = cnt[0], K32 = cnt[1] * 32;
    uint32_t* TH = (uint32_t*)(TAh + (size_t)row * FCH);
    uint32_t* TL = (uint32_t*)(TAl + (size_t)row * FCH);
    float s = 0.f;
    for (int kk = threadIdx.x * 2; kk < K32; kk += 256) {
        float t0 = 0.f, t1 = 0.f;
#pragma unroll
        for (int e = 0; e < 2; e++) {
            int kke = kk + e;
            if (kke < Kact) {
                int k = idx[kke];
                float mm = Mr[k];
                float hh = whv[k], ll = wlv[k];
                float spos = is_high ? hh : ll, sneg = is_high ? ll : hh;
                float tv = (mm > 0.f) ? mm * spos : mm * sneg;
                float p = is_high ? fmaxf(mm, 0.f) : fminf(mm, 0.f);
                s += p * bhrv[k] + tv * blin[k];
                if (e) t1 = tv; else t0 = tv;
            }
        }
        __nv_bfloat16 h0 = __float2bfloat16(t0), h1 = __float2bfloat16(t1);
        __nv_bfloat16 q0 = __float2bfloat16(t0 - __bfloat162float(h0));
        __nv_bfloat16 q1 = __float2bfloat16(t1 - __bfloat162float(h1));
        TH[kk >> 1] = (uint32_t)__bfloat16_as_ushort(h0) | ((uint32_t)__bfloat16_as_ushort(h1) << 16);
        TL[kk >> 1] = (uint32_t)__bfloat16_as_ushort(q0) | ((uint32_t)__bfloat16_as_ushort(q1) << 16);
    }
    s = blockReduceSum(s);
    if (threadIdx.x == 0)
        bias_out[row] = (is_high ? biasH[r] : biasL[r]) + s;
}

// gathered fp32 transform for skinny (20-row) chain; zero-pads full 2048
__global__ void transform20g_k(const float* __restrict__ Mraw, int shared_src,
                               float* __restrict__ TA,
                               const float* __restrict__ whv, const float* __restrict__ wlv,
                               const float* __restrict__ bhrv, const float* __restrict__ blin,
                               const float* __restrict__ biasL, const float* __restrict__ biasH,
                               float* __restrict__ bias_out,
                               const int* __restrict__ idx, const int* __restrict__ cnt,
                               int half) {
    int row = blockIdx.x;
    int is_high = row >= half;
    int r = is_high ? row - half : row;
    int srow = shared_src ? r : row;
    const float* Mr = Mraw + (size_t)srow * FCH;
    int Kact = cnt[0];
    float s = 0.f;
    for (int kk = threadIdx.x; kk < FCH; kk += 128) {
        float tv = 0.f;
        if (kk < Kact) {
            int k = idx[kk];
            float mm = Mr[k];
            float hh = whv[k], ll = wlv[k];
            float spos = is_high ? hh : ll, sneg = is_high ? ll : hh;
            tv = (mm > 0.f) ? mm * spos : mm * sneg;
            float p = is_high ? fmaxf(mm, 0.f) : fminf(mm, 0.f);
            s += p * bhrv[k] + tv * blin[k];
        }
        TA[(size_t)row * FCH + kk] = tv;
    }
    s = blockReduceSum(s);
    if (threadIdx.x == 0)
        bias_out[row] = (is_high ? biasH[r] : biasL[r]) + s;
}

// ======================= dynamic-K gathered bf16-split GEMM =======================
// C[4096,N] += (Ah+Al)[4096,K'] @ gatherRows(Wh+Wl)[K',N]
// 2-stage pipeline, 75.8KB smem -> 2 CTAs/SM (4 warps/SMSP) for stall hiding.
#define ROWB   80
#define A_MATB (128 * ROWB)               // 10240
#define ROWN   272
#define B_MATB (32 * ROWN)                // 8704
#define STAGEB (2 * A_MATB + 2 * B_MATB)  // 37888
#define TCG_SMEM (2 * STAGEB)             // 75776

__global__ __launch_bounds__(256, 2) void tc_gemm_g(
    const unsigned short* __restrict__ Ah, const unsigned short* __restrict__ Al,
    const unsigned short* __restrict__ Wh, const unsigned short* __restrict__ Wl,
    const int* __restrict__ idx, const int* __restrict__ cnt,
    float* __restrict__ C, int N) {
    extern __shared__ char smem[];
    const uint32_t sbase = smem_u32(smem);
    const int tid = threadIdx.x, lane = tid & 31, wid = tid >> 5;
    const int wm = wid & 1, wn = wid >> 1;
    const int m0 = blockIdx.y * 128, n0 = blockIdx.x * 128;
    const int NCH = cnt[1];

    auto fill = [&](int stage, int kc) {
        int k0 = kc * 32;
        uint32_t sb = sbase + stage * STAGEB;
#pragma unroll
        for (int i = 0; i < 8; i++) {
            int c = tid + i * 256;
            if (c < 1024) {  // A: 128 rows x 32 k (x2 mats)
                int mat = c >> 9, rem = c & 511, row = rem >> 2, seg = rem & 3;
                uint32_t dst = sb + mat * A_MATB + row * ROWB + seg * 16;
                const unsigned short* src =
                    (mat ? Al : Ah) + (size_t)(m0 + row) * FCH + k0 + seg * 8;
                cp_async16(dst, src, 16);
            } else {         // B: 32 gathered k-rows x 128 n (x2 mats)
                int d = c - 1024, mat = d >> 9, rem = d & 511, r = rem >> 4, seg = rem & 15;
                uint32_t dst = sb + 2 * A_MATB + mat * B_MATB + r * ROWN + seg * 16;
                int gc = n0 + seg * 8;
                int krow = idx[k0 + r];
                const unsigned short* src = (mat ? Wl : Wh) + (size_t)krow * N + gc;
                cp_async16(dst, src, (gc < N) ? 16 : 0);
            }
        }
    };

    float acc[4][4][4];
#pragma unroll
    for (int a = 0; a < 4; a++)
#pragma unroll
        for (int b = 0; b < 4; b++)
#pragma unroll
            for (int q = 0; q < 4; q++) acc[a][b][q] = 0.f;

    fill(0, 0); CP_COMMIT();
    if (NCH > 1) fill(1, 1);
    CP_COMMIT();

    const int a_r = (lane & 7) + ((lane >> 3) & 1) * 8;
    const int a_s = lane >> 4;
    const int b_g = lane >> 3, b_r = lane & 7;   // trans-ldmatrix group/row

    int st = 0;
    for (int t = 0; t < NCH; t++) {
        CP_WAIT1();
        __syncthreads();
        uint32_t sb = sbase + st * STAGEB;
        uint32_t aH = sb, aL = sb + A_MATB;
        uint32_t bHb = sb + 2 * A_MATB, bLb = bHb + B_MATB;
#pragma unroll
        for (int kk = 0; kk < 2; kk++) {
            uint32_t ah[4][4], al[4][4], bh[4][2], bl[4][2];
#pragma unroll
            for (int mt = 0; mt < 4; mt++) {
                int row = wm * 64 + mt * 16 + a_r;
                uint32_t off = (uint32_t)row * ROWB + (kk * 2 + a_s) * 16;
                ldmatrix_x4(ah[mt], aH + off);
                ldmatrix_x4(al[mt], aL + off);
            }
#pragma unroll
            for (int p = 0; p < 2; p++) {
                int nw = wn * 32 + p * 16;
                uint32_t off = (uint32_t)(kk * 16 + (b_g & 1) * 8 + b_r) * ROWN
                             + (uint32_t)(nw + (b_g >> 1) * 8) * 2;
                uint32_t r4[4];
                ldmatrix_x4_trans(r4, bHb + off);
                bh[2 * p][0] = r4[0]; bh[2 * p][1] = r4[1];
                bh[2 * p + 1][0] = r4[2]; bh[2 * p + 1][1] = r4[3];
                ldmatrix_x4_trans(r4, bLb + off);
                bl[2 * p][0] = r4[0]; bl[2 * p][1] = r4[1];
                bl[2 * p + 1][0] = r4[2]; bl[2 * p + 1][1] = r4[3];
            }
#pragma unroll
            for (int mt = 0; mt < 4; mt++)
#pragma unroll
                for (int nt = 0; nt < 4; nt++) {
                    mma16816(acc[mt][nt], ah[mt], bh[nt]);
                    mma16816(acc[mt][nt], ah[mt], bl[nt]);
                    mma16816(acc[mt][nt], al[mt], bh[nt]);
                }
        }
        __syncthreads();
        if (t + 2 < NCH) fill(st, t + 2);
        CP_COMMIT();
        st ^= 1;
    }

    int rbase = m0 + wm * 64 + (lane >> 2);
    int cbase = n0 + wn * 32 + (lane & 3) * 2;
#pragma unroll
    for (int mt = 0; mt < 4; mt++) {
#pragma unroll
        for (int nt = 0; nt < 4; nt++) {
            int c = cbase + nt * 8;
            if (c < N) {
                int r = rbase + mt * 16;
                float2* p0 = (float2*)(C + (size_t)r * N + c);
                float2* p1 = (float2*)(C + (size_t)(r + 8) * N + c);
                *p0 = make_float2(acc[mt][nt][0], acc[mt][nt][1]);
                *p1 = make_float2(acc[mt][nt][2], acc[mt][nt][3]);
            }
        }
    }
}

// ------------- skinny GEMM (20 rows, gathered K) -------------
__global__ void sk_gemm20g(const float* __restrict__ TA, const float* __restrict__ B,
                           const int* __restrict__ idx, float* __restrict__ part,
                           int K, int N) {
    __shared__ float sTA[20][128];
    int tid = threadIdx.x;           // 128
    int kb = blockIdx.y;             // 0..15
    int kbase = kb * 128;
    int col0 = blockIdx.x * 256 + tid * 2;
    for (int i2 = tid; i2 < 20 * 128; i2 += 128) {
        int r = i2 >> 7, k = i2 & 127;
        sTA[r][k] = TA[(size_t)r * K + kbase + k];
    }
    __syncthreads();
    if (col0 >= N) return;
    float2 acc[20];
#pragma unroll
    for (int r = 0; r < 20; r++) acc[r] = make_float2(0.f, 0.f);
    for (int k = 0; k < 128; k++) {
        int krow = idx[kbase + k];
        float2 bv = *(const float2*)(B + (size_t)krow * N + col0);
#pragma unroll
        for (int r = 0; r < 20; r++) {
            float sv = sTA[r][k];
            acc[r].x += sv * bv.x;
            acc[r].y += sv * bv.y;
        }
    }
#pragma unroll
    for (int r = 0; r < 20; r++)
        *(float2*)(part + (size_t)(kb * 20 + r) * N + col0) = acc[r];
}

__global__ void sk_reduce20(const float* __restrict__ part, float* __restrict__ C, int N) {
    int i = blockIdx.x * blockDim.x + threadIdx.x;
    if (i >= 20 * N) return;
    int r = i / N, c = i - r * N;
    float s = 0.f;
#pragma unroll
    for (int ks = 0; ks < 16; ks++) s += part[(size_t)(ks * 20 + r) * N + c];
    C[(size_t)r * N + c] = s;
}

__global__ void assemble_k(const float* __restrict__ z, const float* __restrict__ low,
                           const float* __restrict__ high, float* __restrict__ out) {
    int i = threadIdx.x;
    if (i < FCOUT) {
        out[i]      = z[i];
        out[10 + i] = low[i];
        out[20 + i] = high[i];
    }
}

// =======================================================================
extern "C" void kernel_launch(void* const* d_in, const int* in_sizes, int n_in,
                              void* d_out, int out_size) {
    (void)in_sizes; (void)n_in; (void)out_size;
    const float* X  = (const float*)d_in[0];
    const float* LO = (const float*)d_in[1];
    const float* HI = (const float*)d_in[2];
    const float* W[5];
    const float* Bv[5];
    for (int i = 0; i < 5; i++) {
        W[i]  = (const float*)d_in[3 + 2 * i];
        Bv[i] = (const float*)d_in[4 + 2 * i];
    }
    float* out = (float*)d_out;

    float *x0, *l0, *h0, *z, *act, *low, *high, *b2, *P, *sP, *sQ, *sb2, *part;
    float *wlv, *whv, *bhrv;
    int *idxv, *cntv;
    unsigned short *TAh, *TAl;
    unsigned short *Wth[4], *Wtl[4];
    cudaGetSymbolAddress((void**)&x0, g_x0);
    cudaGetSymbolAddress((void**)&l0, g_l0);
    cudaGetSymbolAddress((void**)&h0, g_h0);
    cudaGetSymbolAddress((void**)&z, g_z);
    cudaGetSymbolAddress((void**)&act, g_act);
    cudaGetSymbolAddress((void**)&low, g_low);
    cudaGetSymbolAddress((void**)&high, g_high);
    cudaGetSymbolAddress((void**)&b2, g_b2);
    cudaGetSymbolAddress((void**)&P, g_P);
    cudaGetSymbolAddress((void**)&sP, g_sP);
    cudaGetSymbolAddress((void**)&sQ, g_sQ);
    cudaGetSymbolAddress((void**)&sb2, g_sb2);
    cudaGetSymbolAddress((void**)&part, g_part);
    cudaGetSymbolAddress((void**)&wlv, g_wl);
    cudaGetSymbolAddress((void**)&whv, g_wh);
    cudaGetSymbolAddress((void**)&bhrv, g_bhr);
    cudaGetSymbolAddress((void**)&idxv, g_idx);
    cudaGetSymbolAddress((void**)&cntv, g_cnt);
    cudaGetSymbolAddress((void**)&TAh, g_TAh);
    cudaGetSymbolAddress((void**)&TAl, g_TAl);
    cudaGetSymbolAddress((void**)&Wth[0], g_Wt0h);
    cudaGetSymbolAddress((void**)&Wtl[0], g_Wt0l);
    cudaGetSymbolAddress((void**)&Wth[1], g_Wt1h);
    cudaGetSymbolAddress((void**)&Wtl[1], g_Wt1l);
    cudaGetSymbolAddress((void**)&Wth[2], g_Wt2h);
    cudaGetSymbolAddress((void**)&Wtl[2], g_Wt2l);
    cudaGetSymbolAddress((void**)&Wth[3], g_Wt3h);
    cudaGetSymbolAddress((void**)&Wtl[3], g_Wt3l);

    cudaFuncSetAttribute(tc_gemm_g, cudaFuncAttributeMaxDynamicSharedMemorySize, TCG_SMEM);

    // weight bf16 split in natural [K,N] layout (no transpose)
    wt_split_nt<<<(FCH * FC0 / 4 + 255) / 256, 256>>>(W[0], Wth[0], Wtl[0], FCH * FC0 / 4);
    for (int j = 1; j <= 3; j++)
        wt_split_nt<<<(FCH * FCH / 4 + 255) / 256, 256>>>(W[j], Wth[j], Wtl[j], FCH * FCH / 4);

    norm_k<<<4, 256>>>(X, LO, HI, x0, l0, h0);

    // ---- layer 1 ----
    gemv_fwd<<<FCH, 128>>>(W[0], x0, Bv[0], z, FC0);
    bounds_k<<<FCH, 128>>>(W[0], Bv[0], l0, h0, low, FC0, 0);
    bounds_k<<<FCH, 128>>>(W[0], Bv[0], l0, h0, high, FC0, 1);
    relu_scan_k<<<1, 1024>>>(z, low, high, act, wlv, whv, bhrv, idxv, cntv);

    // ---- layers 2..4: stacked low/high chains with compacted K ----
    for (int i = 1; i <= 3; i++) {
        gemv_fwd<<<FCH, 128>>>(W[i], act, Bv[i], z, FCH);
        const float* cur = W[i];
        const float* bL = Bv[i];
        const float* bH = Bv[i];
        int shared = 1;
        for (int j = i - 1; j >= 0; j--) {
            transform_g_k<<<2 * FCH, 128>>>(cur, shared, TAh, TAl,
                                            whv + j * FCH, wlv + j * FCH,
                                            bhrv + j * FCH, Bv[j], bL, bH, b2,
                                            idxv + j * FCH, cntv + 2 * j, FCH);
            int Nn = (j == 0) ? FC0 : FCH;
            dim3 grid((Nn + 127) / 128, 2 * FCH / 128);
            tc_gemm_g<<<grid, 256, TCG_SMEM>>>(TAh, TAl, Wth[j], Wtl[j],
                                               idxv + j * FCH, cntv + 2 * j, P, Nn);
            cur = P; shared = 0; bL = b2; bH = b2 + FCH;
        }
        bounds2_k<<<2 * FCH, 128>>>(P, b2, l0, h0, low, high, FC0, FCH);
        relu_scan_k<<<1, 1024>>>(z, low, high, act, wlv + i * FCH, whv + i * FCH,
                                 bhrv + i * FCH, idxv + i * FCH, cntv + 2 * i);
    }

    // ---- layer 5: stacked 20-row skinny chain (gathered) ----
    gemv_fwd<<<FCOUT, 128>>>(W[4], act, Bv[4], z, FCH);
    {
        const float* cur = W[4];
        const float* bL = Bv[4];
        const float* bH = Bv[4];
        int shared = 1;
        for (int j = 3; j >= 0; j--) {
            transform20g_k<<<20, 128>>>(cur, shared, sQ, whv + j * FCH, wlv + j * FCH,
                                        bhrv + j * FCH, Bv[j], bL, bH, sb2,
                                        idxv + j * FCH, cntv + 2 * j, 10);
            int Nn = (j == 0) ? FC0 : FCH;
            dim3 grid((Nn + 255) / 256, 16);
            sk_gemm20g<<<grid, 128>>>(sQ, W[j], idxv + j * FCH, part, FCH, Nn);
            sk_reduce20<<<(20 * Nn + 255) / 256, 256>>>(part, sP, Nn);
            cur = sP; shared = 0; bL = sb2; bH = sb2 + 10;
        }
        bounds2_k<<<20, 128>>>(sP, sb2, l0, h0, low, high, FC0, 10);
    }

    assemble_k<<<1, 32>>>(z, low, high, out);
}

// round 11
// speedup vs baseline: 4.0172x; 1.7259x over previous
#include <cuda_runtime.h>
#include <cuda_fp16.h>
#include <cstdint>

#define FC0   784
#define FCH   2048
#define FCOUT 10

// ======================= helpers =======================
__device__ __forceinline__ uint32_t smem_u32(const void* p) {
    uint32_t a;
    asm("{ .reg .u64 t; cvta.to.shared.u64 t, %1; cvt.u32.u64 %0, t; }" : "=r"(a) : "l"(p));
    return a;
}

__device__ __forceinline__ void ldmatrix_x4(uint32_t* r, uint32_t addr) {
    asm volatile("ldmatrix.sync.aligned.m8n8.x4.shared.b16 {%0,%1,%2,%3}, [%4];"
                 : "=r"(r[0]), "=r"(r[1]), "=r"(r[2]), "=r"(r[3]) : "r"(addr));
}
__device__ __forceinline__ void ldmatrix_x4_trans(uint32_t* r, uint32_t addr) {
    asm volatile("ldmatrix.sync.aligned.m8n8.x4.trans.shared.b16 {%0,%1,%2,%3}, [%4];"
                 : "=r"(r[0]), "=r"(r[1]), "=r"(r[2]), "=r"(r[3]) : "r"(addr));
}

__device__ __forceinline__ void mma16816h(float* d, const uint32_t* a, const uint32_t* b) {
    asm volatile("mma.sync.aligned.m16n8k16.row.col.f32.f16.f16.f32 "
                 "{%0,%1,%2,%3}, {%4,%5,%6,%7}, {%8,%9}, {%0,%1,%2,%3};"
                 : "+f"(d[0]), "+f"(d[1]), "+f"(d[2]), "+f"(d[3])
                 : "r"(a[0]), "r"(a[1]), "r"(a[2]), "r"(a[3]), "r"(b[0]), "r"(b[1]));
}

__device__ __forceinline__ void cp_async16(uint32_t dst, const void* src, int sz) {
    asm volatile("cp.async.cg.shared.global [%0], [%1], 16, %2;"
                 :: "r"(dst), "l"(src), "r"(sz) : "memory");
}
#define CP_COMMIT() asm volatile("cp.async.commit_group;" ::: "memory")
#define CP_WAIT1()  asm volatile("cp.async.wait_group 1;" ::: "memory")

// ======================= scratch (static device globals) =======================
__device__ float g_x0[FC0], g_l0[FC0], g_h0[FC0];
__device__ float g_z[FCH], g_act[FCH];
__device__ float g_low[FCH], g_high[FCH];
__device__ float g_wl[4 * FCH], g_wh[4 * FCH], g_bhr[4 * FCH];
__device__ int   g_idx[4 * FCH];
__device__ int   g_cnt[8];                  // per level: [2j]=count, [2j+1]=N 64-chunks
__device__ float g_b2[2 * FCH];
__device__ float g_P[2 * FCH * FCH];
__device__ unsigned short g_TA[2 * FCH * FCH];                 // fp16 transform output
__device__ unsigned short g_Wf0[FCH * FC0];                    // fp16 weights [K,N]
__device__ unsigned short g_Wf1[FCH * FCH];
__device__ unsigned short g_Wf2[FCH * FCH];
__device__ unsigned short g_Wf3[FCH * FCH];
__device__ float g_sP[20 * FCH], g_sQ[20 * FCH], g_sb2[20];
__device__ float g_part[16 * 20 * FCH];

// ======================= small helper kernels =======================
__device__ __forceinline__ float blockReduceSum(float v) {
    __shared__ float sh[32];
    int lane = threadIdx.x & 31, wid = threadIdx.x >> 5;
#pragma unroll
    for (int o = 16; o > 0; o >>= 1) v += __shfl_down_sync(0xffffffffu, v, o);
    if (lane == 0) sh[wid] = v;
    __syncthreads();
    int nw = blockDim.x >> 5;
    v = (threadIdx.x < nw) ? sh[threadIdx.x] : 0.f;
    if (wid == 0) {
#pragma unroll
        for (int o = 16; o > 0; o >>= 1) v += __shfl_down_sync(0xffffffffu, v, o);
    }
    return v;
}

__global__ void norm_k(const float* __restrict__ x, const float* __restrict__ lo,
                       const float* __restrict__ hi, float* __restrict__ x0,
                       float* __restrict__ l0, float* __restrict__ h0) {
    int i = blockIdx.x * blockDim.x + threadIdx.x;
    if (i < FC0) {
        const float mean = 0.1307f, stdv = 0.3081f;
        x0[i] = (x[i] - mean) / stdv;
        l0[i] = (lo[i] - mean) / stdv;
        h0[i] = (hi[i] - mean) / stdv;
    }
}

__global__ void gemv_fwd(const float* __restrict__ W, const float* __restrict__ xin,
                         const float* __restrict__ b, float* __restrict__ z, int K) {
    int row = blockIdx.x;
    const float4* Wr = (const float4*)(W + (size_t)row * K);
    const float4* X4 = (const float4*)xin;
    float s = 0.f;
    for (int k = threadIdx.x; k < (K >> 2); k += blockDim.x) {
        float4 w = Wr[k], xv = X4[k];
        s += w.x * xv.x + w.y * xv.y + w.z * xv.z + w.w * xv.w;
    }
    s = blockReduceSum(s);
    if (threadIdx.x == 0) z[row] = s + b[row];
}

__global__ void bounds_k(const float* __restrict__ M, const float* __restrict__ bias,
                         const float* __restrict__ l0, const float* __restrict__ h0,
                         float* __restrict__ out, int K, int is_high) {
    int row = blockIdx.x;
    const float* Mr = M + (size_t)row * K;
    float s = 0.f;
    for (int k = threadIdx.x; k < K; k += blockDim.x) {
        float m = Mr[k];
        float mn = fminf(m, 0.f), mp = fmaxf(m, 0.f);
        float lv = l0[k], hv = h0[k];
        s += is_high ? (mn * lv + mp * hv) : (mn * hv + mp * lv);
    }
    s = blockReduceSum(s);
    if (threadIdx.x == 0) out[row] = s + bias[row];
}

// stacked bounds: rows [0,half) -> low, rows [half,2*half) -> high
__global__ void bounds2_k(const float* __restrict__ M, const float* __restrict__ bias,
                          const float* __restrict__ l0, const float* __restrict__ h0,
                          float* __restrict__ lowv, float* __restrict__ highv,
                          int K, int half) {
    int row = blockIdx.x;
    int is_high = row >= half;
    int r = is_high ? row - half : row;
    const float* Mr = M + (size_t)row * K;
    float s = 0.f;
    for (int k = threadIdx.x; k < K; k += blockDim.x) {
        float m = Mr[k];
        float mn = fminf(m, 0.f), mp = fmaxf(m, 0.f);
        float lv = l0[k], hv = h0[k];
        s += is_high ? (mn * lv + mp * hv) : (mn * hv + mp * lv);
    }
    s = blockReduceSum(s);
    if (threadIdx.x == 0) {
        float* dst = is_high ? highv : lowv;
        dst[r] = s + bias[row];
    }
}

// ---- relu relaxation + deterministic column compaction (single block, 1024 thr) ----
__global__ void relu_scan_k(const float* __restrict__ z, const float* __restrict__ low,
                            const float* __restrict__ high, float* __restrict__ act,
                            float* __restrict__ wl, float* __restrict__ wh,
                            float* __restrict__ bhr, int* __restrict__ idx,
                            int* __restrict__ cnt) {
    int tid = threadIdx.x;  // 1024; 2 elements each
    __shared__ int wsum[32];
    __shared__ int stotal;
    int m[2];
#pragma unroll
    for (int e = 0; e < 2; e++) {
        int i = tid * 2 + e;
        float lo = low[i], hi = high[i];
        float w_h, w_l, b_h;
        if (lo < 0.f && hi > 0.f) {
            float d = hi - lo;
            w_h = hi / d;
            b_h = -(lo * hi) / d;
            w_l = (lo * lo > hi * hi) ? 0.f : 1.f;
        } else {
            float keep = (hi <= 0.f) ? 0.f : 1.f;
            w_h = keep; w_l = keep; b_h = 0.f;
        }
        wl[i] = w_l; wh[i] = w_h; bhr[i] = b_h;
        act[i] = fmaxf(z[i], 0.f);
        m[e] = (w_h != 0.f) ? 1 : 0;
    }
    int tsum = m[0] + m[1];
    int lane = tid & 31, wrp = tid >> 5;
    int incl = tsum;
#pragma unroll
    for (int o = 1; o < 32; o <<= 1) {
        int v = __shfl_up_sync(0xffffffffu, incl, o);
        if (lane >= o) incl += v;
    }
    if (lane == 31) wsum[wrp] = incl;
    __syncthreads();
    if (wrp == 0) {
        int v = wsum[lane], iv = v;
#pragma unroll
        for (int o = 1; o < 32; o <<= 1) {
            int u = __shfl_up_sync(0xffffffffu, iv, o);
            if (lane >= o) iv += u;
        }
        wsum[lane] = iv - v;  // exclusive warp bases
    }
    __syncthreads();
    int excl = wsum[wrp] + incl - tsum;
    if (m[0]) idx[excl] = tid * 2;
    if (m[1]) idx[excl + m[0]] = tid * 2 + 1;
    if (tid == 1023) stotal = excl + tsum;
    __syncthreads();
    int total = stotal;
    for (int p = total + tid; p < FCH; p += 1024) idx[p] = 0;  // safe pad rows
    if (tid == 0) { cnt[0] = total; cnt[1] = (total + 63) >> 6; }
}

// fp16 convert, natural [K,N] layout
__global__ void wt_half(const float* __restrict__ W, unsigned short* __restrict__ Bh,
                        int total4) {
    int i = blockIdx.x * blockDim.x + threadIdx.x;
    if (i >= total4) return;
    float4 v = ((const float4*)W)[i];
    __half h0 = __float2half_rn(v.x), h1 = __float2half_rn(v.y);
    __half h2 = __float2half_rn(v.z), h3 = __float2half_rn(v.w);
    uint2 uh;
    uh.x = (uint32_t)__half_as_ushort(h0) | ((uint32_t)__half_as_ushort(h1) << 16);
    uh.y = (uint32_t)__half_as_ushort(h2) | ((uint32_t)__half_as_ushort(h3) << 16);
    ((uint2*)Bh)[i] = uh;
}

// ---- gathered stacked transform + bias + fp16 output (compacted K columns) ----
__global__ void transform_g_k(const float* __restrict__ Mraw, int shared_src,
                              unsigned short* __restrict__ TAp,
                              const float* __restrict__ whv, const float* __restrict__ wlv,
                              const float* __restrict__ bhrv, const float* __restrict__ blin,
                              const float* __restrict__ biasL, const float* __restrict__ biasH,
                              float* __restrict__ bias_out,
                              const int* __restrict__ idx, const int* __restrict__ cnt,
                              int half) {
    int row = blockIdx.x;
    int is_high = row >= half;
    int r = is_high ? row - half : row;
    int srow = shared_src ? r : row;
    const float* Mr = Mraw + (size_t)srow * FCH;
    int Kact = cnt[0], K64 = cnt[1] * 64;
    uint32_t* TH = (uint32_t*)(TAp + (size_t)row * FCH);
    float s = 0.f;
    for (int kk = threadIdx.x * 2; kk < K64; kk += 256) {
        float t0 = 0.f, t1 = 0.f;
#pragma unroll
        for (int e = 0; e < 2; e++) {
            int kke = kk + e;
            if (kke < Kact) {
                int k = idx[kke];
                float mm = Mr[k];
                float hh = whv[k], ll = wlv[k];
                float spos = is_high ? hh : ll, sneg = is_high ? ll : hh;
                float tv = (mm > 0.f) ? mm * spos : mm * sneg;
                float p = is_high ? fmaxf(mm, 0.f) : fminf(mm, 0.f);
                s += p * bhrv[k] + tv * blin[k];
                if (e) t1 = tv; else t0 = tv;
            }
        }
        __half h0 = __float2half_rn(t0), h1 = __float2half_rn(t1);
        TH[kk >> 1] = (uint32_t)__half_as_ushort(h0) | ((uint32_t)__half_as_ushort(h1) << 16);
    }
    s = blockReduceSum(s);
    if (threadIdx.x == 0)
        bias_out[row] = (is_high ? biasH[r] : biasL[r]) + s;
}

// gathered fp32 transform for skinny (20-row) chain; zero-pads full 2048
__global__ void transform20g_k(const float* __restrict__ Mraw, int shared_src,
                               float* __restrict__ TA,
                               const float* __restrict__ whv, const float* __restrict__ wlv,
                               const float* __restrict__ bhrv, const float* __restrict__ blin,
                               const float* __restrict__ biasL, const float* __restrict__ biasH,
                               float* __restrict__ bias_out,
                               const int* __restrict__ idx, const int* __restrict__ cnt,
                               int half) {
    int row = blockIdx.x;
    int is_high = row >= half;
    int r = is_high ? row - half : row;
    int srow = shared_src ? r : row;
    const float* Mr = Mraw + (size_t)srow * FCH;
    int Kact = cnt[0];
    float s = 0.f;
    for (int kk = threadIdx.x; kk < FCH; kk += 128) {
        float tv = 0.f;
        if (kk < Kact) {
            int k = idx[kk];
            float mm = Mr[k];
            float hh = whv[k], ll = wlv[k];
            float spos = is_high ? hh : ll, sneg = is_high ? ll : hh;
            tv = (mm > 0.f) ? mm * spos : mm * sneg;
            float p = is_high ? fmaxf(mm, 0.f) : fminf(mm, 0.f);
            s += p * bhrv[k] + tv * blin[k];
        }
        TA[(size_t)row * FCH + kk] = tv;
    }
    s = blockReduceSum(s);
    if (threadIdx.x == 0)
        bias_out[row] = (is_high ? biasH[r] : biasL[r]) + s;
}

// ======================= dynamic-K gathered fp16 GEMM =======================
// C[4096,N] = TA[4096,K'] @ gatherRows(Wf)[K',N], single fp16 product, fp32 accum.
// K-chunk 64, 2-stage cp.async, 2 CTAs/SM.
#define ROWB   144                          // 64 halfs (128B) padded to 144
#define A_MATB (128 * ROWB)                 // 18432
#define ROWN   272                          // 128 halfs (256B) padded to 272
#define B_MATB (64 * ROWN)                  // 17408
#define STAGEB (A_MATB + B_MATB)            // 35840
#define TCG_SMEM (2 * STAGEB)               // 71680

__global__ __launch_bounds__(256, 2) void tc_gemm_g(
    const unsigned short* __restrict__ TA, const unsigned short* __restrict__ Wf,
    const int* __restrict__ idx, const int* __restrict__ cnt,
    float* __restrict__ C, int N) {
    extern __shared__ char smem[];
    const uint32_t sbase = smem_u32(smem);
    const int tid = threadIdx.x, lane = tid & 31, wid = tid >> 5;
    const int wm = wid & 1, wn = wid >> 1;   // 2 x 4 warp grid, warp tile 64x32
    const int m0 = blockIdx.y * 128, n0 = blockIdx.x * 128;
    const int NCH = cnt[1];                  // number of 64-wide K chunks

    auto fill = [&](int stage, int kc) {
        int k0 = kc * 64;
        uint32_t sb = sbase + stage * STAGEB;
#pragma unroll
        for (int i = 0; i < 8; i++) {
            int c = tid + i * 256;
            if (c < 1024) {  // A: 128 rows x 64 halfs
                int row = c >> 3, seg = c & 7;
                uint32_t dst = sb + row * ROWB + seg * 16;
                const unsigned short* src = TA + (size_t)(m0 + row) * FCH + k0 + seg * 8;
                cp_async16(dst, src, 16);
            } else {         // B: 64 gathered k-rows x 128 n halfs
                int d = c - 1024;
                int r = d >> 4, seg = d & 15;
                uint32_t dst = sb + A_MATB + r * ROWN + seg * 16;
                int gc = n0 + seg * 8;
                int krow = idx[k0 + r];
                const unsigned short* src = Wf + (size_t)krow * N + gc;
                cp_async16(dst, src, (gc < N) ? 16 : 0);
            }
        }
    };

    float acc[4][4][4];
#pragma unroll
    for (int a = 0; a < 4; a++)
#pragma unroll
        for (int b = 0; b < 4; b++)
#pragma unroll
            for (int q = 0; q < 4; q++) acc[a][b][q] = 0.f;

    fill(0, 0); CP_COMMIT();
    if (NCH > 1) fill(1, 1);
    CP_COMMIT();

    const int a_r = (lane & 7) + ((lane >> 3) & 1) * 8;
    const int a_s = lane >> 4;
    const int b_g = lane >> 3, b_r = lane & 7;   // trans-ldmatrix group/row

    int st = 0;
    for (int t = 0; t < NCH; t++) {
        CP_WAIT1();
        __syncthreads();
        uint32_t sb = sbase + st * STAGEB;
        uint32_t aB = sb, bB = sb + A_MATB;
#pragma unroll
        for (int kk = 0; kk < 4; kk++) {
            uint32_t ah[4][4], bh[4][2];
#pragma unroll
            for (int mt = 0; mt < 4; mt++) {
                int row = wm * 64 + mt * 16 + a_r;
                ldmatrix_x4(ah[mt], aB + (uint32_t)row * ROWB + kk * 32 + a_s * 16);
            }
#pragma unroll
            for (int p = 0; p < 2; p++) {
                int nw = wn * 32 + p * 16;
                uint32_t off = (uint32_t)(kk * 16 + (b_g & 1) * 8 + b_r) * ROWN
                             + (uint32_t)(nw + (b_g >> 1) * 8) * 2;
                uint32_t r4[4];
                ldmatrix_x4_trans(r4, bB + off);
                bh[2 * p][0] = r4[0]; bh[2 * p][1] = r4[1];
                bh[2 * p + 1][0] = r4[2]; bh[2 * p + 1][1] = r4[3];
            }
#pragma unroll
            for (int mt = 0; mt < 4; mt++)
#pragma unroll
                for (int nt = 0; nt < 4; nt++)
                    mma16816h(acc[mt][nt], ah[mt], bh[nt]);
        }
        __syncthreads();
        if (t + 2 < NCH) fill(st, t + 2);
        CP_COMMIT();
        st ^= 1;
    }

    int rbase = m0 + wm * 64 + (lane >> 2);
    int cbase = n0 + wn * 32 + (lane & 3) * 2;
#pragma unroll
    for (int mt = 0; mt < 4; mt++) {
#pragma unroll
        for (int nt = 0; nt < 4; nt++) {
            int c = cbase + nt * 8;
            if (c < N) {
                int r = rbase + mt * 16;
                float2* p0 = (float2*)(C + (size_t)r * N + c);
                float2* p1 = (float2*)(C + (size_t)(r + 8) * N + c);
                *p0 = make_float2(acc[mt][nt][0], acc[mt][nt][1]);
                *p1 = make_float2(acc[mt][nt][2], acc[mt][nt][3]);
            }
        }
    }
}

// ------------- skinny GEMM (20 rows, gathered K) -------------
__global__ void sk_gemm20g(const float* __restrict__ TA, const float* __restrict__ B,
                           const int* __restrict__ idx, float* __restrict__ part,
                           int K, int N) {
    __shared__ float sTA[20][128];
    int tid = threadIdx.x;           // 128
    int kb = blockIdx.y;             // 0..15
    int kbase = kb * 128;
    int col0 = blockIdx.x * 256 + tid * 2;
    for (int i2 = tid; i2 < 20 * 128; i2 += 128) {
        int r = i2 >> 7, k = i2 & 127;
        sTA[r][k] = TA[(size_t)r * K + kbase + k];
    }
    __syncthreads();
    if (col0 >= N) return;
    float2 acc[20];
#pragma unroll
    for (int r = 0; r < 20; r++) acc[r] = make_float2(0.f, 0.f);
    for (int k = 0; k < 128; k++) {
        int krow = idx[kbase + k];
        float2 bv = *(const float2*)(B + (size_t)krow * N + col0);
#pragma unroll
        for (int r = 0; r < 20; r++) {
            float sv = sTA[r][k];
            acc[r].x += sv * bv.x;
            acc[r].y += sv * bv.y;
        }
    }
#pragma unroll
    for (int r = 0; r < 20; r++)
        *(float2*)(part + (size_t)(kb * 20 + r) * N + col0) = acc[r];
}

__global__ void sk_reduce20(const float* __restrict__ part, float* __restrict__ C, int N) {
    int i = blockIdx.x * blockDim.x + threadIdx.x;
    if (i >= 20 * N) return;
    int r = i / N, c = i - r * N;
    float s = 0.f;
#pragma unroll
    for (int ks = 0; ks < 16; ks++) s += part[(size_t)(ks * 20 + r) * N + c];
    C[(size_t)r * N + c] = s;
}

__global__ void assemble_k(const float* __restrict__ z, const float* __restrict__ low,
                           const float* __restrict__ high, float* __restrict__ out) {
    int i = threadIdx.x;
    if (i < FCOUT) {
        out[i]      = z[i];
        out[10 + i] = low[i];
        out[20 + i] = high[i];
    }
}

// =======================================================================
extern "C" void kernel_launch(void* const* d_in, const int* in_sizes, int n_in,
                              void* d_out, int out_size) {
    (void)in_sizes; (void)n_in; (void)out_size;
    const float* X  = (const float*)d_in[0];
    const float* LO = (const float*)d_in[1];
    const float* HI = (const float*)d_in[2];
    const float* W[5];
    const float* Bv[5];
    for (int i = 0; i < 5; i++) {
        W[i]  = (const float*)d_in[3 + 2 * i];
        Bv[i] = (const float*)d_in[4 + 2 * i];
    }
    float* out = (float*)d_out;

    float *x0, *l0, *h0, *z, *act, *low, *high, *b2, *P, *sP, *sQ, *sb2, *part;
    float *wlv, *whv, *bhrv;
    int *idxv, *cntv;
    unsigned short *TA;
    unsigned short *Wf[4];
    cudaGetSymbolAddress((void**)&x0, g_x0);
    cudaGetSymbolAddress((void**)&l0, g_l0);
    cudaGetSymbolAddress((void**)&h0, g_h0);
    cudaGetSymbolAddress((void**)&z, g_z);
    cudaGetSymbolAddress((void**)&act, g_act);
    cudaGetSymbolAddress((void**)&low, g_low);
    cudaGetSymbolAddress((void**)&high, g_high);
    cudaGetSymbolAddress((void**)&b2, g_b2);
    cudaGetSymbolAddress((void**)&P, g_P);
    cudaGetSymbolAddress((void**)&sP, g_sP);
    cudaGetSymbolAddress((void**)&sQ, g_sQ);
    cudaGetSymbolAddress((void**)&sb2, g_sb2);
    cudaGetSymbolAddress((void**)&part, g_part);
    cudaGetSymbolAddress((void**)&wlv, g_wl);
    cudaGetSymbolAddress((void**)&whv, g_wh);
    cudaGetSymbolAddress((void**)&bhrv, g_bhr);
    cudaGetSymbolAddress((void**)&idxv, g_idx);
    cudaGetSymbolAddress((void**)&cntv, g_cnt);
    cudaGetSymbolAddress((void**)&TA, g_TA);
    cudaGetSymbolAddress((void**)&Wf[0], g_Wf0);
    cudaGetSymbolAddress((void**)&Wf[1], g_Wf1);
    cudaGetSymbolAddress((void**)&Wf[2], g_Wf2);
    cudaGetSymbolAddress((void**)&Wf[3], g_Wf3);

    cudaFuncSetAttribute(tc_gemm_g, cudaFuncAttributeMaxDynamicSharedMemorySize, TCG_SMEM);

    // fp16 weight conversion, natural [K,N] layout
    wt_half<<<(FCH * FC0 / 4 + 255) / 256, 256>>>(W[0], Wf[0], FCH * FC0 / 4);
    for (int j = 1; j <= 3; j++)
        wt_half<<<(FCH * FCH / 4 + 255) / 256, 256>>>(W[j], Wf[j], FCH * FCH / 4);

    norm_k<<<4, 256>>>(X, LO, HI, x0, l0, h0);

    // ---- layer 1 ----
    gemv_fwd<<<FCH, 128>>>(W[0], x0, Bv[0], z, FC0);
    bounds_k<<<FCH, 128>>>(W[0], Bv[0], l0, h0, low, FC0, 0);
    bounds_k<<<FCH, 128>>>(W[0], Bv[0], l0, h0, high, FC0, 1);
    relu_scan_k<<<1, 1024>>>(z, low, high, act, wlv, whv, bhrv, idxv, cntv);

    // ---- layers 2..4: stacked low/high chains, single-product fp16 GEMMs ----
    for (int i = 1; i <= 3; i++) {
        gemv_fwd<<<FCH, 128>>>(W[i], act, Bv[i], z, FCH);
        const float* cur = W[i];
        const float* bL = Bv[i];
        const float* bH = Bv[i];
        int shared = 1;
        for (int j = i - 1; j >= 0; j--) {
            transform_g_k<<<2 * FCH, 128>>>(cur, shared, TA,
                                            whv + j * FCH, wlv + j * FCH,
                                            bhrv + j * FCH, Bv[j], bL, bH, b2,
                                            idxv + j * FCH, cntv + 2 * j, FCH);
            int Nn = (j == 0) ? FC0 : FCH;
            dim3 grid((Nn + 127) / 128, 2 * FCH / 128);
            tc_gemm_g<<<grid, 256, TCG_SMEM>>>(TA, Wf[j],
                                               idxv + j * FCH, cntv + 2 * j, P, Nn);
            cur = P; shared = 0; bL = b2; bH = b2 + FCH;
        }
        bounds2_k<<<2 * FCH, 128>>>(P, b2, l0, h0, low, high, FC0, FCH);
        relu_scan_k<<<1, 1024>>>(z, low, high, act, wlv + i * FCH, whv + i * FCH,
                                 bhrv + i * FCH, idxv + i * FCH, cntv + 2 * i);
    }

    // ---- layer 5: stacked 20-row skinny chain (gathered, exact fp32) ----
    gemv_fwd<<<FCOUT, 128>>>(W[4], act, Bv[4], z, FCH);
    {
        const float* cur = W[4];
        const float* bL = Bv[4];
        const float* bH = Bv[4];
        int shared = 1;
        for (int j = 3; j >= 0; j--) {
            transform20g_k<<<20, 128>>>(cur, shared, sQ, whv + j * FCH, wlv + j * FCH,
                                        bhrv + j * FCH, Bv[j], bL, bH, sb2,
                                        idxv + j * FCH, cntv + 2 * j, 10);
            int Nn = (j == 0) ? FC0 : FCH;
            dim3 grid((Nn + 255) / 256, 16);
            sk_gemm20g<<<grid, 128>>>(sQ, W[j], idxv + j * FCH, part, FCH, Nn);
            sk_reduce20<<<(20 * Nn + 255) / 256, 256>>>(part, sP, Nn);
            cur = sP; shared = 0; bL = sb2; bH = sb2 + 10;
        }
        bounds2_k<<<20, 128>>>(sP, sb2, l0, h0, low, high, FC0, 10);
    }

    assemble_k<<<1, 32>>>(z, low, high, out);
}

// round 13
// speedup vs baseline: 4.8974x; 1.2191x over previous
#include <cuda_runtime.h>
#include <cuda_fp16.h>
#include <cstdint>

#define FC0   784
#define FCH   2048
#define FCOUT 10

// ======================= helpers =======================
__device__ __forceinline__ uint32_t smem_u32(const void* p) {
    uint32_t a;
    asm("{ .reg .u64 t; cvta.to.shared.u64 t, %1; cvt.u32.u64 %0, t; }" : "=r"(a) : "l"(p));
    return a;
}

__device__ __forceinline__ void ldmatrix_x4(uint32_t* r, uint32_t addr) {
    asm volatile("ldmatrix.sync.aligned.m8n8.x4.shared.b16 {%0,%1,%2,%3}, [%4];"
                 : "=r"(r[0]), "=r"(r[1]), "=r"(r[2]), "=r"(r[3]) : "r"(addr));
}
__device__ __forceinline__ void ldmatrix_x4_trans(uint32_t* r, uint32_t addr) {
    asm volatile("ldmatrix.sync.aligned.m8n8.x4.trans.shared.b16 {%0,%1,%2,%3}, [%4];"
                 : "=r"(r[0]), "=r"(r[1]), "=r"(r[2]), "=r"(r[3]) : "r"(addr));
}

__device__ __forceinline__ void mma16816h(float* d, const uint32_t* a, const uint32_t* b) {
    asm volatile("mma.sync.aligned.m16n8k16.row.col.f32.f16.f16.f32 "
                 "{%0,%1,%2,%3}, {%4,%5,%6,%7}, {%8,%9}, {%0,%1,%2,%3};"
                 : "+f"(d[0]), "+f"(d[1]), "+f"(d[2]), "+f"(d[3])
                 : "r"(a[0]), "r"(a[1]), "r"(a[2]), "r"(a[3]), "r"(b[0]), "r"(b[1]));
}

__device__ __forceinline__ void cp_async16(uint32_t dst, const void* src, int sz) {
    asm volatile("cp.async.cg.shared.global [%0], [%1], 16, %2;"
                 :: "r"(dst), "l"(src), "r"(sz) : "memory");
}
#define CP_COMMIT() asm volatile("cp.async.commit_group;" ::: "memory")
#define CP_WAIT1()  asm volatile("cp.async.wait_group 1;" ::: "memory")

// ======================= scratch (static device globals) =======================
__device__ float g_x0[FC0], g_l0[FC0], g_h0[FC0];
__device__ float g_z[FCH], g_act[FCH];
__device__ float g_low[FCH], g_high[FCH];
__device__ float g_wl[4 * FCH], g_wh[4 * FCH], g_bhr[4 * FCH];
__device__ float g_b2[2 * FCH];
__device__ unsigned short g_P[2 * FCH * FCH];                  // fp16 intermediate P
__device__ unsigned short g_TA[2 * FCH * FCH];                 // fp16 transform output
__device__ unsigned short g_Wf0[FCH * FC0];                    // fp16 weights [K,N]
__device__ unsigned short g_Wf1[FCH * FCH];
__device__ unsigned short g_Wf2[FCH * FCH];
__device__ unsigned short g_Wf3[FCH * FCH];
__device__ float g_sP[20 * FCH], g_sQ[20 * FCH], g_sb2[20];
__device__ float g_part[16 * 20 * FCH];

// ======================= small helper kernels =======================
__device__ __forceinline__ float blockReduceSum(float v) {
    __shared__ float sh[32];
    int lane = threadIdx.x & 31, wid = threadIdx.x >> 5;
#pragma unroll
    for (int o = 16; o > 0; o >>= 1) v += __shfl_down_sync(0xffffffffu, v, o);
    if (lane == 0) sh[wid] = v;
    __syncthreads();
    int nw = blockDim.x >> 5;
    v = (threadIdx.x < nw) ? sh[threadIdx.x] : 0.f;
    if (wid == 0) {
#pragma unroll
        for (int o = 16; o > 0; o >>= 1) v += __shfl_down_sync(0xffffffffu, v, o);
    }
    __syncthreads();   // allow back-to-back calls
    return v;
}

__global__ void norm_k(const float* __restrict__ x, const float* __restrict__ lo,
                       const float* __restrict__ hi, float* __restrict__ x0,
                       float* __restrict__ l0, float* __restrict__ h0) {
    int i = blockIdx.x * blockDim.x + threadIdx.x;
    if (i < FC0) {
        const float mean = 0.1307f, stdv = 0.3081f;
        x0[i] = (x[i] - mean) / stdv;
        l0[i] = (lo[i] - mean) / stdv;
        h0[i] = (hi[i] - mean) / stdv;
    }
}

__global__ void gemv_fwd(const float* __restrict__ W, const float* __restrict__ xin,
                         const float* __restrict__ b, float* __restrict__ z, int K) {
    int row = blockIdx.x;
    const float4* Wr = (const float4*)(W + (size_t)row * K);
    const float4* X4 = (const float4*)xin;
    float s = 0.f;
    for (int k = threadIdx.x; k < (K >> 2); k += blockDim.x) {
        float4 w = Wr[k], xv = X4[k];
        s += w.x * xv.x + w.y * xv.y + w.z * xv.z + w.w * xv.w;
    }
    s = blockReduceSum(s);
    if (threadIdx.x == 0) z[row] = s + b[row];
}

__device__ __forceinline__ void relu_diag(float lo, float hi, float z,
                                          float* wl, float* wh, float* bhr,
                                          float* act, int i) {
    float w_h, w_l, b_h;
    if (lo < 0.f && hi > 0.f) {
        float d = hi - lo;
        w_h = hi / d;
        b_h = -(lo * hi) / d;
        w_l = (lo * lo > hi * hi) ? 0.f : 1.f;
    } else {
        float keep = (hi <= 0.f) ? 0.f : 1.f;
        w_h = keep; w_l = keep; b_h = 0.f;
    }
    wl[i] = w_l; wh[i] = w_h; bhr[i] = b_h;
    act[i] = fmaxf(z, 0.f);
}

// layer-1 fused: both bounds from W1 row r (single pass) + relu diagonals
__global__ void bounds1_relu_k(const float* __restrict__ W1, const float* __restrict__ b1,
                               const float* __restrict__ l0, const float* __restrict__ h0,
                               const float* __restrict__ z,
                               float* __restrict__ lowv, float* __restrict__ highv,
                               float* __restrict__ act, float* __restrict__ wl,
                               float* __restrict__ wh, float* __restrict__ bhr) {
    int r = blockIdx.x;
    const float* Wr = W1 + (size_t)r * FC0;
    float sl = 0.f, sh = 0.f;
    for (int k = threadIdx.x; k < FC0; k += blockDim.x) {
        float m = Wr[k];
        float mn = fminf(m, 0.f), mp = fmaxf(m, 0.f);
        float lv = l0[k], hv = h0[k];
        sl += mn * hv + mp * lv;
        sh += mn * lv + mp * hv;
    }
    sl = blockReduceSum(sl);
    sh = blockReduceSum(sh);
    if (threadIdx.x == 0) {
        float lo = sl + b1[r], hi = sh + b1[r];
        lowv[r] = lo; highv[r] = hi;
        relu_diag(lo, hi, z[r], wl, wh, bhr, act, r);
    }
}

// big-chain fused: bounds from fp16 P rows (r: low, FCH+r: high, stride FC0) + relu
__global__ void bounds2h_relu_k(const unsigned short* __restrict__ Ph,
                                const float* __restrict__ bias,
                                const float* __restrict__ l0, const float* __restrict__ h0,
                                const float* __restrict__ z,
                                float* __restrict__ lowv, float* __restrict__ highv,
                                float* __restrict__ act, float* __restrict__ wl,
                                float* __restrict__ wh, float* __restrict__ bhr) {
    int r = blockIdx.x;
    const __half* RL = (const __half*)(Ph + (size_t)r * FC0);
    const __half* RH = (const __half*)(Ph + (size_t)(FCH + r) * FC0);
    float sl = 0.f, sh = 0.f;
    for (int k = threadIdx.x; k < FC0; k += blockDim.x) {
        float lv = l0[k], hv = h0[k];
        float ml = __half2float(RL[k]);
        float mh = __half2float(RH[k]);
        sl += fminf(ml, 0.f) * hv + fmaxf(ml, 0.f) * lv;
        sh += fminf(mh, 0.f) * lv + fmaxf(mh, 0.f) * hv;
    }
    sl = blockReduceSum(sl);
    sh = blockReduceSum(sh);
    if (threadIdx.x == 0) {
        float lo = sl + bias[r], hi = sh + bias[FCH + r];
        lowv[r] = lo; highv[r] = hi;
        relu_diag(lo, hi, z[r], wl, wh, bhr, act, r);
    }
}

// skinny final bounds (fp32, 20 rows stacked), no relu
__global__ void bounds2_k(const float* __restrict__ M, const float* __restrict__ bias,
                          const float* __restrict__ l0, const float* __restrict__ h0,
                          float* __restrict__ lowv, float* __restrict__ highv,
                          int K, int half) {
    int row = blockIdx.x;
    int is_high = row >= half;
    int r = is_high ? row - half : row;
    const float* Mr = M + (size_t)row * K;
    float s = 0.f;
    for (int k = threadIdx.x; k < K; k += blockDim.x) {
        float m = Mr[k];
        float mn = fminf(m, 0.f), mp = fmaxf(m, 0.f);
        float lv = l0[k], hv = h0[k];
        s += is_high ? (mn * lv + mp * hv) : (mn * hv + mp * lv);
    }
    s = blockReduceSum(s);
    if (threadIdx.x == 0) {
        float* dst = is_high ? highv : lowv;
        dst[r] = s + bias[row];
    }
}

// fp16 convert, natural [K,N] layout
__global__ void wt_half(const float* __restrict__ W, unsigned short* __restrict__ Bh,
                        int total4) {
    int i = blockIdx.x * blockDim.x + threadIdx.x;
    if (i >= total4) return;
    float4 v = ((const float4*)W)[i];
    __half h0 = __float2half_rn(v.x), h1 = __float2half_rn(v.y);
    __half h2 = __float2half_rn(v.z), h3 = __float2half_rn(v.w);
    uint2 uh;
    uh.x = (uint32_t)__half_as_ushort(h0) | ((uint32_t)__half_as_ushort(h1) << 16);
    uh.y = (uint32_t)__half_as_ushort(h2) | ((uint32_t)__half_as_ushort(h3) << 16);
    ((uint2*)Bh)[i] = uh;
}

// ---- dense stacked transform + bias + fp16 output ----
// src16=0: first chain step, read W_i fp32 (rows shared low/high).
// src16=1: read fp16 P (stride FCH), rows distinct.
__global__ void transform_d_k(const float* __restrict__ Mf,
                              const unsigned short* __restrict__ Mh, int src16,
                              unsigned short* __restrict__ TAp,
                              const float* __restrict__ whv, const float* __restrict__ wlv,
                              const float* __restrict__ bhrv, const float* __restrict__ blin,
                              const float* __restrict__ biasL, const float* __restrict__ biasH,
                              float* __restrict__ bias_out) {
    int row = blockIdx.x;
    int is_high = row >= FCH;
    int r = is_high ? row - FCH : row;
    int srow = src16 ? row : r;
    const float* MrF = Mf + (size_t)srow * FCH;
    const __half2* MrH = (const __half2*)(Mh + (size_t)srow * FCH);
    uint32_t* TH = (uint32_t*)(TAp + (size_t)row * FCH);
    float s = 0.f;
#pragma unroll
    for (int it = 0; it < 8; it++) {
        int kk = threadIdx.x * 2 + it * 256;
        float m0, m1;
        if (src16) {
            float2 mm = __half22float2(MrH[kk >> 1]);
            m0 = mm.x; m1 = mm.y;
        } else {
            float2 mm = *(const float2*)(MrF + kk);
            m0 = mm.x; m1 = mm.y;
        }
        float t0 = 0.f, t1 = 0.f;
        {
            float hh = whv[kk], ll = wlv[kk];
            if (hh != 0.f) {
                float spos = is_high ? hh : ll, sneg = is_high ? ll : hh;
                t0 = (m0 > 0.f) ? m0 * spos : m0 * sneg;
                float p = is_high ? fmaxf(m0, 0.f) : fminf(m0, 0.f);
                s += p * bhrv[kk];
            }
            s += t0 * blin[kk];
        }
        {
            float hh = whv[kk + 1], ll = wlv[kk + 1];
            if (hh != 0.f) {
                float spos = is_high ? hh : ll, sneg = is_high ? ll : hh;
                t1 = (m1 > 0.f) ? m1 * spos : m1 * sneg;
                float p = is_high ? fmaxf(m1, 0.f) : fminf(m1, 0.f);
                s += p * bhrv[kk + 1];
            }
            s += t1 * blin[kk + 1];
        }
        __half h0 = __float2half_rn(t0), h1 = __float2half_rn(t1);
        TH[kk >> 1] = (uint32_t)__half_as_ushort(h0) | ((uint32_t)__half_as_ushort(h1) << 16);
    }
    s = blockReduceSum(s);
    if (threadIdx.x == 0)
        bias_out[row] = (is_high ? biasH[r] : biasL[r]) + s;
}

// dense fp32 transform for skinny (20-row) chain
__global__ void transform20d_k(const float* __restrict__ Mraw, int shared_src,
                               float* __restrict__ TA,
                               const float* __restrict__ whv, const float* __restrict__ wlv,
                               const float* __restrict__ bhrv, const float* __restrict__ blin,
                               const float* __restrict__ biasL, const float* __restrict__ biasH,
                               float* __restrict__ bias_out) {
    int row = blockIdx.x;
    int is_high = row >= 10;
    int r = is_high ? row - 10 : row;
    int srow = shared_src ? r : row;
    const float* Mr = Mraw + (size_t)srow * FCH;
    float s = 0.f;
    for (int k = threadIdx.x; k < FCH; k += 128) {
        float mm = Mr[k];
        float hh = whv[k], ll = wlv[k];
        float tv = 0.f;
        if (hh != 0.f) {
            float spos = is_high ? hh : ll, sneg = is_high ? ll : hh;
            tv = (mm > 0.f) ? mm * spos : mm * sneg;
            float p = is_high ? fmaxf(mm, 0.f) : fminf(mm, 0.f);
            s += p * bhrv[k];
        }
        s += tv * blin[k];
        TA[(size_t)row * FCH + k] = tv;
    }
    s = blockReduceSum(s);
    if (threadIdx.x == 0)
        bias_out[row] = (is_high ? biasH[r] : biasL[r]) + s;
}

// ======================= fp16 GEMM, fp16 output =======================
// Ph[4096,N] = TA[4096,2048] @ Wf[2048,N], fp32 accum, K fixed 2048 (32 chunks of 64)
#define ROWB   144
#define A_MATB (128 * ROWB)
#define ROWN   272
#define B_MATB (64 * ROWN)
#define STAGEB (A_MATB + B_MATB)
#define TCG_SMEM (2 * STAGEB)
#define NCHK   32

__global__ __launch_bounds__(256, 2) void tc_gemm_g(
    const unsigned short* __restrict__ TA, const unsigned short* __restrict__ Wf,
    unsigned short* __restrict__ Ph, int N) {
    extern __shared__ char smem[];
    const uint32_t sbase = smem_u32(smem);
    const int tid = threadIdx.x, lane = tid & 31, wid = tid >> 5;
    const int wm = wid & 1, wn = wid >> 1;
    const int m0 = blockIdx.y * 128, n0 = blockIdx.x * 128;

    auto fill = [&](int stage, int kc) {
        int k0 = kc * 64;
        uint32_t sb = sbase + stage * STAGEB;
#pragma unroll
        for (int i = 0; i < 8; i++) {
            int c = tid + i * 256;
            if (c < 1024) {  // A: 128 rows x 64 halfs
                int row = c >> 3, seg = c & 7;
                uint32_t dst = sb + row * ROWB + seg * 16;
                const unsigned short* src = TA + (size_t)(m0 + row) * FCH + k0 + seg * 8;
                cp_async16(dst, src, 16);
            } else {         // B: 64 k-rows x 128 n halfs
                int d = c - 1024;
                int r = d >> 4, seg = d & 15;
                uint32_t dst = sb + A_MATB + r * ROWN + seg * 16;
                int gc = n0 + seg * 8;
                const unsigned short* src = Wf + (size_t)(k0 + r) * N + gc;
                cp_async16(dst, src, (gc < N) ? 16 : 0);
            }
        }
    };

    float acc[4][4][4];
#pragma unroll
    for (int a = 0; a < 4; a++)
#pragma unroll
        for (int b = 0; b < 4; b++)
#pragma unroll
            for (int q = 0; q < 4; q++) acc[a][b][q] = 0.f;

    fill(0, 0); CP_COMMIT();
    fill(1, 1); CP_COMMIT();

    const int a_r = (lane & 7) + ((lane >> 3) & 1) * 8;
    const int a_s = lane >> 4;
    const int b_g = lane >> 3, b_r = lane & 7;

    int st = 0;
    for (int t = 0; t < NCHK; t++) {
        CP_WAIT1();
        __syncthreads();
        uint32_t sb = sbase + st * STAGEB;
        uint32_t aB = sb, bB = sb + A_MATB;
#pragma unroll
        for (int kk = 0; kk < 4; kk++) {
            uint32_t ah[4][4], bh[4][2];
#pragma unroll
            for (int mt = 0; mt < 4; mt++) {
                int row = wm * 64 + mt * 16 + a_r;
                ldmatrix_x4(ah[mt], aB + (uint32_t)row * ROWB + kk * 32 + a_s * 16);
            }
#pragma unroll
            for (int p = 0; p < 2; p++) {
                int nw = wn * 32 + p * 16;
                uint32_t off = (uint32_t)(kk * 16 + (b_g & 1) * 8 + b_r) * ROWN
                             + (uint32_t)(nw + (b_g >> 1) * 8) * 2;
                uint32_t r4[4];
                ldmatrix_x4_trans(r4, bB + off);
                bh[2 * p][0] = r4[0]; bh[2 * p][1] = r4[1];
                bh[2 * p + 1][0] = r4[2]; bh[2 * p + 1][1] = r4[3];
            }
#pragma unroll
            for (int mt = 0; mt < 4; mt++)
#pragma unroll
                for (int nt = 0; nt < 4; nt++)
                    mma16816h(acc[mt][nt], ah[mt], bh[nt]);
        }
        __syncthreads();
        if (t + 2 < NCHK) fill(st, t + 2);
        CP_COMMIT();
        st ^= 1;
    }

    int rbase = m0 + wm * 64 + (lane >> 2);
    int cbase = n0 + wn * 32 + (lane & 3) * 2;
#pragma unroll
    for (int mt = 0; mt < 4; mt++) {
#pragma unroll
        for (int nt = 0; nt < 4; nt++) {
            int c = cbase + nt * 8;
            if (c < N) {
                int r = rbase + mt * 16;
                __half2 v0 = __floats2half2_rn(acc[mt][nt][0], acc[mt][nt][1]);
                __half2 v1 = __floats2half2_rn(acc[mt][nt][2], acc[mt][nt][3]);
                *(__half2*)(Ph + (size_t)r * N + c) = v0;
                *(__half2*)(Ph + (size_t)(r + 8) * N + c) = v1;
            }
        }
    }
}

// ------------- skinny GEMM (20 rows, fp16 weights) -------------
__global__ void sk_gemm20h(const float* __restrict__ TA, const unsigned short* __restrict__ Bf,
                           float* __restrict__ part, int K, int N) {
    __shared__ float sTA[20][128];
    int tid = threadIdx.x;           // 128
    int kb = blockIdx.y;             // 0..15
    int kbase = kb * 128;
    int col0 = blockIdx.x * 256 + tid * 2;
    for (int i2 = tid; i2 < 20 * 128; i2 += 128) {
        int r = i2 >> 7, k = i2 & 127;
        sTA[r][k] = TA[(size_t)r * K + kbase + k];
    }
    __syncthreads();
    if (col0 >= N) return;
    float2 acc[20];
#pragma unroll
    for (int r = 0; r < 20; r++) acc[r] = make_float2(0.f, 0.f);
    for (int k = 0; k < 128; k++) {
        __half2 bh = *(const __half2*)(Bf + (size_t)(kbase + k) * N + col0);
        float2 bv = __half22float2(bh);
#pragma unroll
        for (int r = 0; r < 20; r++) {
            float sv = sTA[r][k];
            acc[r].x += sv * bv.x;
            acc[r].y += sv * bv.y;
        }
    }
#pragma unroll
    for (int r = 0; r < 20; r++)
        *(float2*)(part + (size_t)(kb * 20 + r) * N + col0) = acc[r];
}

__global__ void sk_reduce20(const float* __restrict__ part, float* __restrict__ C, int N) {
    int i = blockIdx.x * blockDim.x + threadIdx.x;
    if (i >= 20 * N) return;
    int r = i / N, c = i - r * N;
    float s = 0.f;
#pragma unroll
    for (int ks = 0; ks < 16; ks++) s += part[(size_t)(ks * 20 + r) * N + c];
    C[(size_t)r * N + c] = s;
}

__global__ void assemble_k(const float* __restrict__ z, const float* __restrict__ low,
                           const float* __restrict__ high, float* __restrict__ out) {
    int i = threadIdx.x;
    if (i < FCOUT) {
        out[i]      = z[i];
        out[10 + i] = low[i];
        out[20 + i] = high[i];
    }
}

// =======================================================================
extern "C" void kernel_launch(void* const* d_in, const int* in_sizes, int n_in,
                              void* d_out, int out_size) {
    (void)in_sizes; (void)n_in; (void)out_size;
    const float* X  = (const float*)d_in[0];
    const float* LO = (const float*)d_in[1];
    const float* HI = (const float*)d_in[2];
    const float* W[5];
    const float* Bv[5];
    for (int i = 0; i < 5; i++) {
        W[i]  = (const float*)d_in[3 + 2 * i];
        Bv[i] = (const float*)d_in[4 + 2 * i];
    }
    float* out = (float*)d_out;

    float *x0, *l0, *h0, *z, *act, *low, *high, *b2, *sP, *sQ, *sb2, *part;
    float *wlv, *whv, *bhrv;
    unsigned short *TA, *Ph;
    unsigned short *Wf[4];
    cudaGetSymbolAddress((void**)&x0, g_x0);
    cudaGetSymbolAddress((void**)&l0, g_l0);
    cudaGetSymbolAddress((void**)&h0, g_h0);
    cudaGetSymbolAddress((void**)&z, g_z);
    cudaGetSymbolAddress((void**)&act, g_act);
    cudaGetSymbolAddress((void**)&low, g_low);
    cudaGetSymbolAddress((void**)&high, g_high);
    cudaGetSymbolAddress((void**)&b2, g_b2);
    cudaGetSymbolAddress((void**)&Ph, g_P);
    cudaGetSymbolAddress((void**)&sP, g_sP);
    cudaGetSymbolAddress((void**)&sQ, g_sQ);
    cudaGetSymbolAddress((void**)&sb2, g_sb2);
    cudaGetSymbolAddress((void**)&part, g_part);
    cudaGetSymbolAddress((void**)&wlv, g_wl);
    cudaGetSymbolAddress((void**)&whv, g_wh);
    cudaGetSymbolAddress((void**)&bhrv, g_bhr);
    cudaGetSymbolAddress((void**)&TA, g_TA);
    cudaGetSymbolAddress((void**)&Wf[0], g_Wf0);
    cudaGetSymbolAddress((void**)&Wf[1], g_Wf1);
    cudaGetSymbolAddress((void**)&Wf[2], g_Wf2);
    cudaGetSymbolAddress((void**)&Wf[3], g_Wf3);

    cudaFuncSetAttribute(tc_gemm_g, cudaFuncAttributeMaxDynamicSharedMemorySize, TCG_SMEM);

    // fp16 weight conversion, natural [K,N] layout
    wt_half<<<(FCH * FC0 / 4 + 255) / 256, 256>>>(W[0], Wf[0], FCH * FC0 / 4);
    for (int j = 1; j <= 3; j++)
        wt_half<<<(FCH * FCH / 4 + 255) / 256, 256>>>(W[j], Wf[j], FCH * FCH / 4);

    norm_k<<<4, 256>>>(X, LO, HI, x0, l0, h0);

    // ---- layer 1 (fused bounds+relu) ----
    gemv_fwd<<<FCH, 128>>>(W[0], x0, Bv[0], z, FC0);
    bounds1_relu_k<<<FCH, 128>>>(W[0], Bv[0], l0, h0, z, low, high, act, wlv, whv, bhrv);

    // ---- layers 2..4: stacked low/high chains, fp16 GEMMs + fp16 P ----
    for (int i = 1; i <= 3; i++) {
        gemv_fwd<<<FCH, 128>>>(W[i], act, Bv[i], z, FCH);
        const float* bL = Bv[i];
        const float* bH = Bv[i];
        int first = 1;
        for (int j = i - 1; j >= 0; j--) {
            transform_d_k<<<2 * FCH, 128>>>(W[i], Ph, first ? 0 : 1, TA,
                                            whv + j * FCH, wlv + j * FCH,
                                            bhrv + j * FCH, Bv[j], bL, bH, b2);
            int Nn = (j == 0) ? FC0 : FCH;
            dim3 grid((Nn + 127) / 128, 2 * FCH / 128);
            tc_gemm_g<<<grid, 256, TCG_SMEM>>>(TA, Wf[j], Ph, Nn);
            first = 0; bL = b2; bH = b2 + FCH;
        }
        bounds2h_relu_k<<<FCH, 128>>>(Ph, b2, l0, h0, z, low, high, act,
                                      wlv + i * FCH, whv + i * FCH, bhrv + i * FCH);
    }

    // ---- layer 5: stacked 20-row skinny chain (fp32 accum, fp16 weights) ----
    gemv_fwd<<<FCOUT, 128>>>(W[4], act, Bv[4], z, FCH);
    {
        const float* bL = Bv[4];
        const float* bH = Bv[4];
        const float* cur = W[4];
        int shared = 1;
        for (int j = 3; j >= 0; j--) {
            transform20d_k<<<20, 128>>>(cur, shared, sQ, whv + j * FCH, wlv + j * FCH,
                                        bhrv + j * FCH, Bv[j], bL, bH, sb2);
            int Nn = (j == 0) ? FC0 : FCH;
            dim3 grid((Nn + 255) / 256, 16);
            sk_gemm20h<<<grid, 128>>>(sQ, Wf[j], part, FCH, Nn);
            sk_reduce20<<<(20 * Nn + 255) / 256, 256>>>(part, sP, Nn);
            cur = sP; shared = 0; bL = sb2; bH = sb2 + 10;
        }
        bounds2_k<<<20, 128>>>(sP, sb2, l0, h0, low, high, FC0, 10);
    }

    assemble_k<<<1, 32>>>(z, low, high, out);
}

// round 14
// speedup vs baseline: 5.3417x; 1.0907x over previous
#include <cuda_runtime.h>
#include <cuda_fp16.h>
#include <cstdint>

#define FC0   784
#define FCH   2048
#define FCOUT 10

// ======================= helpers =======================
__device__ __forceinline__ uint32_t smem_u32(const void* p) {
    uint32_t a;
    asm("{ .reg .u64 t; cvta.to.shared.u64 t, %1; cvt.u32.u64 %0, t; }" : "=r"(a) : "l"(p));
    return a;
}

__device__ __forceinline__ void ldmatrix_x4(uint32_t* r, uint32_t addr) {
    asm volatile("ldmatrix.sync.aligned.m8n8.x4.shared.b16 {%0,%1,%2,%3}, [%4];"
                 : "=r"(r[0]), "=r"(r[1]), "=r"(r[2]), "=r"(r[3]) : "r"(addr));
}
__device__ __forceinline__ void ldmatrix_x4_trans(uint32_t* r, uint32_t addr) {
    asm volatile("ldmatrix.sync.aligned.m8n8.x4.trans.shared.b16 {%0,%1,%2,%3}, [%4];"
                 : "=r"(r[0]), "=r"(r[1]), "=r"(r[2]), "=r"(r[3]) : "r"(addr));
}

__device__ __forceinline__ void mma16816h(float* d, const uint32_t* a, const uint32_t* b) {
    asm volatile("mma.sync.aligned.m16n8k16.row.col.f32.f16.f16.f32 "
                 "{%0,%1,%2,%3}, {%4,%5,%6,%7}, {%8,%9}, {%0,%1,%2,%3};"
                 : "+f"(d[0]), "+f"(d[1]), "+f"(d[2]), "+f"(d[3])
                 : "r"(a[0]), "r"(a[1]), "r"(a[2]), "r"(a[3]), "r"(b[0]), "r"(b[1]));
}

__device__ __forceinline__ void cp_async16(uint32_t dst, const void* src, int sz) {
    asm volatile("cp.async.cg.shared.global [%0], [%1], 16, %2;"
                 :: "r"(dst), "l"(src), "r"(sz) : "memory");
}
#define CP_COMMIT() asm volatile("cp.async.commit_group;" ::: "memory")
#define CP_WAIT1()  asm volatile("cp.async.wait_group 1;" ::: "memory")

// transform one value; accumulates bias contribution into s
__device__ __forceinline__ float tf(float m, float4 p, int ishigh, float& s) {
    float tv = 0.f;
    if (p.x != 0.f) {
        float spos = ishigh ? p.x : p.y, sneg = ishigh ? p.y : p.x;
        tv = (m > 0.f) ? m * spos : m * sneg;
        s += (ishigh ? fmaxf(m, 0.f) : fminf(m, 0.f)) * p.z;
    }
    s += tv * p.w;
    return tv;
}
// bound contribution of one value
__device__ __forceinline__ void bf(float m, float lv, float hv, int ishigh, float& s) {
    float mn = fminf(m, 0.f), mp = fmaxf(m, 0.f);
    s += ishigh ? (mn * lv + mp * hv) : (mn * hv + mp * lv);
}

// ======================= scratch (static device globals) =======================
__device__ float g_x0[FC0], g_l0[FC0], g_h0[FC0];
__device__ float g_z[FCH], g_act[FCH];
__device__ float g_low[FCH], g_high[FCH];
__device__ float g_wl[4 * FCH], g_wh[4 * FCH], g_bhr[4 * FCH];
__device__ float4 g_pack[4 * FCH];
__device__ float g_b2[2 * FCH];
__device__ float g_gp[16 * 2 * FCH];
__device__ unsigned short g_TA[2 * FCH * FCH], g_TB[2 * FCH * FCH];
__device__ unsigned short g_Wf0[FCH * FC0];
__device__ unsigned short g_Wf1[FCH * FCH];
__device__ unsigned short g_Wf2[FCH * FCH];
__device__ unsigned short g_Wf3[FCH * FCH];
__device__ float g_sP[20 * FCH], g_sQ[20 * FCH], g_sb2[20];
__device__ float g_part[16 * 20 * FCH];

// ======================= small helper kernels =======================
__device__ __forceinline__ float blockReduceSum(float v) {
    __shared__ float sh[32];
    int lane = threadIdx.x & 31, wid = threadIdx.x >> 5;
#pragma unroll
    for (int o = 16; o > 0; o >>= 1) v += __shfl_down_sync(0xffffffffu, v, o);
    if (lane == 0) sh[wid] = v;
    __syncthreads();
    int nw = blockDim.x >> 5;
    v = (threadIdx.x < nw) ? sh[threadIdx.x] : 0.f;
    if (wid == 0) {
#pragma unroll
        for (int o = 16; o > 0; o >>= 1) v += __shfl_down_sync(0xffffffffu, v, o);
    }
    __syncthreads();
    return v;
}

__global__ void norm_k(const float* __restrict__ x, const float* __restrict__ lo,
                       const float* __restrict__ hi, float* __restrict__ x0,
                       float* __restrict__ l0, float* __restrict__ h0) {
    int i = blockIdx.x * blockDim.x + threadIdx.x;
    if (i < FC0) {
        const float mean = 0.1307f, stdv = 0.3081f;
        x0[i] = (x[i] - mean) / stdv;
        l0[i] = (lo[i] - mean) / stdv;
        h0[i] = (hi[i] - mean) / stdv;
    }
}

__global__ void gemv_fwd(const float* __restrict__ W, const float* __restrict__ xin,
                         const float* __restrict__ b, float* __restrict__ z, int K) {
    int row = blockIdx.x;
    const float4* Wr = (const float4*)(W + (size_t)row * K);
    const float4* X4 = (const float4*)xin;
    float s = 0.f;
    for (int k = threadIdx.x; k < (K >> 2); k += blockDim.x) {
        float4 w = Wr[k], xv = X4[k];
        s += w.x * xv.x + w.y * xv.y + w.z * xv.z + w.w * xv.w;
    }
    s = blockReduceSum(s);
    if (threadIdx.x == 0) z[row] = s + b[row];
}

__device__ __forceinline__ void relu_diag(float lo, float hi, float z,
                                          float* wl, float* wh, float* bhr,
                                          float* act, int i) {
    float w_h, w_l, b_h;
    if (lo < 0.f && hi > 0.f) {
        float d = hi - lo;
        w_h = hi / d;
        b_h = -(lo * hi) / d;
        w_l = (lo * lo > hi * hi) ? 0.f : 1.f;
    } else {
        float keep = (hi <= 0.f) ? 0.f : 1.f;
        w_h = keep; w_l = keep; b_h = 0.f;
    }
    wl[i] = w_l; wh[i] = w_h; bhr[i] = b_h;
    act[i] = fmaxf(z, 0.f);
}

// layer-1: both bounds from W1 + relu diag + pack0
__global__ void bounds1_relu_k(const float* __restrict__ W1, const float* __restrict__ b1,
                               const float* __restrict__ l0, const float* __restrict__ h0,
                               const float* __restrict__ z,
                               float* __restrict__ lowv, float* __restrict__ highv,
                               float* __restrict__ act, float* __restrict__ wl,
                               float* __restrict__ wh, float* __restrict__ bhr,
                               float4* __restrict__ packo, const float* __restrict__ blin) {
    int r = blockIdx.x;
    const float* Wr = W1 + (size_t)r * FC0;
    float sl = 0.f, sh = 0.f;
    for (int k = threadIdx.x; k < FC0; k += blockDim.x) {
        float m = Wr[k];
        float mn = fminf(m, 0.f), mp = fmaxf(m, 0.f);
        float lv = l0[k], hv = h0[k];
        sl += mn * hv + mp * lv;
        sh += mn * lv + mp * hv;
    }
    sl = blockReduceSum(sl);
    sh = blockReduceSum(sh);
    if (threadIdx.x == 0) {
        float lo = sl + b1[r], hi = sh + b1[r];
        lowv[r] = lo; highv[r] = hi;
        relu_diag(lo, hi, z[r], wl, wh, bhr, act, r);
        packo[r] = make_float4(wh[r], wl[r], bhr[r], blin[r]);
    }
}

// fused-GEMM follow-ups
__global__ void bias_red_k(float* __restrict__ b2, const float* __restrict__ gp, int nx) {
    int r = blockIdx.x * 256 + threadIdx.x;
    if (r >= 2 * FCH) return;
    float s = b2[r];
    for (int x = 0; x < nx; x++) s += gp[(size_t)x * (2 * FCH) + r];
    b2[r] = s;
}

__global__ void bounds_red_k(const float* __restrict__ b2, const float* __restrict__ gp,
                             int nx, const float* __restrict__ z,
                             float* __restrict__ lowv, float* __restrict__ highv,
                             float* __restrict__ act, float* __restrict__ wl,
                             float* __restrict__ wh, float* __restrict__ bhr,
                             float4* __restrict__ packo, const float* __restrict__ blin) {
    int r = blockIdx.x * 256 + threadIdx.x;
    if (r >= FCH) return;
    float sl = b2[r], sh = b2[FCH + r];
    for (int x = 0; x < nx; x++) {
        sl += gp[(size_t)x * (2 * FCH) + r];
        sh += gp[(size_t)x * (2 * FCH) + FCH + r];
    }
    lowv[r] = sl; highv[r] = sh;
    relu_diag(sl, sh, z[r], wl, wh, bhr, act, r);
    packo[r] = make_float4(wh[r], wl[r], bhr[r], blin[r]);
}

// skinny final bounds (fp32, 20 rows stacked)
__global__ void bounds2_k(const float* __restrict__ M, const float* __restrict__ bias,
                          const float* __restrict__ l0, const float* __restrict__ h0,
                          float* __restrict__ lowv, float* __restrict__ highv,
                          int K, int half) {
    int row = blockIdx.x;
    int is_high = row >= half;
    int r = is_high ? row - half : row;
    const float* Mr = M + (size_t)row * K;
    float s = 0.f;
    for (int k = threadIdx.x; k < K; k += blockDim.x) {
        float m = Mr[k];
        float mn = fminf(m, 0.f), mp = fmaxf(m, 0.f);
        float lv = l0[k], hv = h0[k];
        s += is_high ? (mn * lv + mp * hv) : (mn * hv + mp * lv);
    }
    s = blockReduceSum(s);
    if (threadIdx.x == 0) {
        float* dst = is_high ? highv : lowv;
        dst[r] = s + bias[row];
    }
}

// all four weight conversions in one kernel
#define W0Q (FCH * FC0 / 4)
#define WHQ (FCH * FCH / 4)
__global__ void wt_half_all(const float* __restrict__ W0, const float* __restrict__ W1,
                            const float* __restrict__ W2, const float* __restrict__ W3,
                            unsigned short* __restrict__ F0, unsigned short* __restrict__ F1,
                            unsigned short* __restrict__ F2, unsigned short* __restrict__ F3) {
    int i = blockIdx.x * blockDim.x + threadIdx.x;
    const float* src; unsigned short* dst; int off;
    if (i < W0Q)                { src = W0; dst = F0; off = i; }
    else if (i < W0Q + WHQ)     { src = W1; dst = F1; off = i - W0Q; }
    else if (i < W0Q + 2 * WHQ) { src = W2; dst = F2; off = i - W0Q - WHQ; }
    else if (i < W0Q + 3 * WHQ) { src = W3; dst = F3; off = i - W0Q - 2 * WHQ; }
    else return;
    float4 v = ((const float4*)src)[off];
    __half h0 = __float2half_rn(v.x), h1 = __float2half_rn(v.y);
    __half h2 = __float2half_rn(v.z), h3 = __float2half_rn(v.w);
    uint2 uh;
    uh.x = (uint32_t)__half_as_ushort(h0) | ((uint32_t)__half_as_ushort(h1) << 16);
    uh.y = (uint32_t)__half_as_ushort(h2) | ((uint32_t)__half_as_ushort(h3) << 16);
    ((uint2*)dst)[off] = uh;
}

// standalone transform for the FIRST chain step: reads fp16 Wf[i] (rows shared), pack diag
__global__ void transform_s_k(const unsigned short* __restrict__ Mh,
                              const float4* __restrict__ pack,
                              const float* __restrict__ bIn,
                              unsigned short* __restrict__ TAp, float* __restrict__ b2) {
    int row = blockIdx.x;            // 0..4095
    int is_high = row >= FCH;
    int r = row & (FCH - 1);
    const __half2* Mr = (const __half2*)(Mh + (size_t)r * FCH);
    uint32_t* TH = (uint32_t*)(TAp + (size_t)row * FCH);
    float s = 0.f;
    for (int k2 = threadIdx.x; k2 < FCH / 2; k2 += 128) {
        float2 m = __half22float2(Mr[k2]);
        float4 p0 = pack[k2 * 2], p1 = pack[k2 * 2 + 1];
        float t0 = tf(m.x, p0, is_high, s);
        float t1 = tf(m.y, p1, is_high, s);
        __half h0 = __float2half_rn(t0), h1 = __float2half_rn(t1);
        TH[k2] = (uint32_t)__half_as_ushort(h0) | ((uint32_t)__half_as_ushort(h1) << 16);
    }
    s = blockReduceSum(s);
    if (threadIdx.x == 0) b2[row] = bIn[r] + s;
}

// dense fp32 transform for skinny (20-row) chain
__global__ void transform20d_k(const float* __restrict__ Mraw, int shared_src,
                               float* __restrict__ TA,
                               const float* __restrict__ whv, const float* __restrict__ wlv,
                               const float* __restrict__ bhrv, const float* __restrict__ blin,
                               const float* __restrict__ biasL, const float* __restrict__ biasH,
                               float* __restrict__ bias_out) {
    int row = blockIdx.x;
    int is_high = row >= 10;
    int r = is_high ? row - 10 : row;
    int srow = shared_src ? r : row;
    const float* Mr = Mraw + (size_t)srow * FCH;
    float s = 0.f;
    for (int k = threadIdx.x; k < FCH; k += 128) {
        float mm = Mr[k];
        float hh = whv[k], ll = wlv[k];
        float tv = 0.f;
        if (hh != 0.f) {
            float spos = is_high ? hh : ll, sneg = is_high ? ll : hh;
            tv = (mm > 0.f) ? mm * spos : mm * sneg;
            float p = is_high ? fmaxf(mm, 0.f) : fminf(mm, 0.f);
            s += p * bhrv[k];
        }
        s += tv * blin[k];
        TA[(size_t)row * FCH + k] = tv;
    }
    s = blockReduceSum(s);
    if (threadIdx.x == 0)
        bias_out[row] = (is_high ? biasH[r] : biasL[r]) + s;
}

// ======================= fused fp16 GEMM =======================
// mode 1: epilogue applies next-step transform -> Tout fp16 + bias partials (N==FCH)
// mode 2: epilogue computes bound partials only (N==FC0), no matrix output
#define ROWB   144
#define A_MATB (128 * ROWB)
#define ROWN   272
#define B_MATB (64 * ROWN)
#define STAGEB (A_MATB + B_MATB)
#define TCG_SMEM (2 * STAGEB)
#define NCHK   32

__global__ __launch_bounds__(256, 2) void tc_gemm_f(
    const unsigned short* __restrict__ Ain, const unsigned short* __restrict__ Bf,
    unsigned short* __restrict__ Tout, const float4* __restrict__ pack,
    const float* __restrict__ l0v, const float* __restrict__ h0v,
    float* __restrict__ gpart, int N, int mode) {
    extern __shared__ char smem[];
    const uint32_t sbase = smem_u32(smem);
    const int tid = threadIdx.x, lane = tid & 31, wid = tid >> 5;
    const int wm = wid & 1, wn = wid >> 1;
    const int m0 = blockIdx.y * 128, n0 = blockIdx.x * 128;

    auto fill = [&](int stage, int kc) {
        int k0 = kc * 64;
        uint32_t sb = sbase + stage * STAGEB;
#pragma unroll
        for (int i = 0; i < 8; i++) {
            int c = tid + i * 256;
            if (c < 1024) {
                int row = c >> 3, seg = c & 7;
                uint32_t dst = sb + row * ROWB + seg * 16;
                const unsigned short* src = Ain + (size_t)(m0 + row) * FCH + k0 + seg * 8;
                cp_async16(dst, src, 16);
            } else {
                int d = c - 1024;
                int r = d >> 4, seg = d & 15;
                uint32_t dst = sb + A_MATB + r * ROWN + seg * 16;
                int gc = n0 + seg * 8;
                const unsigned short* src = Bf + (size_t)(k0 + r) * N + gc;
                cp_async16(dst, src, (gc < N) ? 16 : 0);
            }
        }
    };

    float acc[4][4][4];
#pragma unroll
    for (int a = 0; a < 4; a++)
#pragma unroll
        for (int b = 0; b < 4; b++)
#pragma unroll
            for (int q = 0; q < 4; q++) acc[a][b][q] = 0.f;

    fill(0, 0); CP_COMMIT();
    fill(1, 1); CP_COMMIT();

    const int a_r = (lane & 7) + ((lane >> 3) & 1) * 8;
    const int a_s = lane >> 4;
    const int b_g = lane >> 3, b_r = lane & 7;

    int st = 0;
    for (int t = 0; t < NCHK; t++) {
        CP_WAIT1();
        __syncthreads();
        uint32_t sb = sbase + st * STAGEB;
        uint32_t aB = sb, bB = sb + A_MATB;
#pragma unroll
        for (int kk = 0; kk < 4; kk++) {
            uint32_t ah[4][4], bh[4][2];
#pragma unroll
            for (int mt = 0; mt < 4; mt++) {
                int row = wm * 64 + mt * 16 + a_r;
                ldmatrix_x4(ah[mt], aB + (uint32_t)row * ROWB + kk * 32 + a_s * 16);
            }
#pragma unroll
            for (int p = 0; p < 2; p++) {
                int nw = wn * 32 + p * 16;
                uint32_t off = (uint32_t)(kk * 16 + (b_g & 1) * 8 + b_r) * ROWN
                             + (uint32_t)(nw + (b_g >> 1) * 8) * 2;
                uint32_t r4[4];
                ldmatrix_x4_trans(r4, bB + off);
                bh[2 * p][0] = r4[0]; bh[2 * p][1] = r4[1];
                bh[2 * p + 1][0] = r4[2]; bh[2 * p + 1][1] = r4[3];
            }
#pragma unroll
            for (int mt = 0; mt < 4; mt++)
#pragma unroll
                for (int nt = 0; nt < 4; nt++)
                    mma16816h(acc[mt][nt], ah[mt], bh[nt]);
        }
        __syncthreads();
        if (t + 2 < NCHK) fill(st, t + 2);
        CP_COMMIT();
        st ^= 1;
    }

    // ---------------- fused epilogue ----------------
    const int rL = wm * 64 + (lane >> 2);
    const int cb = n0 + wn * 32 + (lane & 3) * 2;
    const int ishigh = (m0 >= FCH);
    float s[8];
#pragma unroll
    for (int q = 0; q < 8; q++) s[q] = 0.f;

    if (mode == 1) {
#pragma unroll
        for (int nt = 0; nt < 4; nt++) {
            int c = cb + nt * 8;
            float4 p0 = pack[c], p1 = pack[c + 1];
#pragma unroll
            for (int mt = 0; mt < 4; mt++) {
                float t0 = tf(acc[mt][nt][0], p0, ishigh, s[mt * 2]);
                float t1 = tf(acc[mt][nt][1], p1, ishigh, s[mt * 2]);
                float t2 = tf(acc[mt][nt][2], p0, ishigh, s[mt * 2 + 1]);
                float t3 = tf(acc[mt][nt][3], p1, ishigh, s[mt * 2 + 1]);
                int r = m0 + rL + mt * 16;
                *(__half2*)(Tout + (size_t)r * FCH + c) = __floats2half2_rn(t0, t1);
                *(__half2*)(Tout + (size_t)(r + 8) * FCH + c) = __floats2half2_rn(t2, t3);
            }
        }
    } else {
#pragma unroll
        for (int nt = 0; nt < 4; nt++) {
            int c = cb + nt * 8;
            if (c + 1 < N) {
                float lv0 = l0v[c], hv0 = h0v[c], lv1 = l0v[c + 1], hv1 = h0v[c + 1];
#pragma unroll
                for (int mt = 0; mt < 4; mt++) {
                    bf(acc[mt][nt][0], lv0, hv0, ishigh, s[mt * 2]);
                    bf(acc[mt][nt][1], lv1, hv1, ishigh, s[mt * 2]);
                    bf(acc[mt][nt][2], lv0, hv0, ishigh, s[mt * 2 + 1]);
                    bf(acc[mt][nt][3], lv1, hv1, ishigh, s[mt * 2 + 1]);
                }
            }
        }
    }
    __syncthreads();
    float* sred = (float*)smem;   // [128][4]
#pragma unroll
    for (int mt = 0; mt < 4; mt++)
#pragma unroll
        for (int h = 0; h < 2; h++) {
            float v = s[mt * 2 + h];
            v += __shfl_xor_sync(0xffffffffu, v, 1);
            v += __shfl_xor_sync(0xffffffffu, v, 2);
            if ((lane & 3) == 0)
                sred[(wm * 64 + mt * 16 + h * 8 + (lane >> 2)) * 4 + wn] = v;
        }
    __syncthreads();
    if (tid < 128)
        gpart[(size_t)blockIdx.x * (2 * FCH) + m0 + tid] =
            sred[tid * 4 + 0] + sred[tid * 4 + 1] + sred[tid * 4 + 2] + sred[tid * 4 + 3];
}

// ------------- skinny GEMM (20 rows, fp16 weights) -------------
__global__ void sk_gemm20h(const float* __restrict__ TA, const unsigned short* __restrict__ Bf,
                           float* __restrict__ part, int K, int N) {
    __shared__ float sTA[20][128];
    int tid = threadIdx.x;
    int kb = blockIdx.y;
    int kbase = kb * 128;
    int col0 = blockIdx.x * 256 + tid * 2;
    for (int i2 = tid; i2 < 20 * 128; i2 += 128) {
        int r = i2 >> 7, k = i2 & 127;
        sTA[r][k] = TA[(size_t)r * K + kbase + k];
    }
    __syncthreads();
    if (col0 >= N) return;
    float2 acc[20];
#pragma unroll
    for (int r = 0; r < 20; r++) acc[r] = make_float2(0.f, 0.f);
    for (int k = 0; k < 128; k++) {
        __half2 bh = *(const __half2*)(Bf + (size_t)(kbase + k) * N + col0);
        float2 bv = __half22float2(bh);
#pragma unroll
        for (int r = 0; r < 20; r++) {
            float sv = sTA[r][k];
            acc[r].x += sv * bv.x;
            acc[r].y += sv * bv.y;
        }
    }
#pragma unroll
    for (int r = 0; r < 20; r++)
        *(float2*)(part + (size_t)(kb * 20 + r) * N + col0) = acc[r];
}

__global__ void sk_reduce20(const float* __restrict__ part, float* __restrict__ C, int N) {
    int i = blockIdx.x * blockDim.x + threadIdx.x;
    if (i >= 20 * N) return;
    int r = i / N, c = i - r * N;
    float s = 0.f;
#pragma unroll
    for (int ks = 0; ks < 16; ks++) s += part[(size_t)(ks * 20 + r) * N + c];
    C[(size_t)r * N + c] = s;
}

__global__ void assemble_k(const float* __restrict__ z, const float* __restrict__ low,
                           const float* __restrict__ high, float* __restrict__ out) {
    int i = threadIdx.x;
    if (i < FCOUT) {
        out[i]      = z[i];
        out[10 + i] = low[i];
        out[20 + i] = high[i];
    }
}

// =======================================================================
extern "C" void kernel_launch(void* const* d_in, const int* in_sizes, int n_in,
                              void* d_out, int out_size) {
    (void)in_sizes; (void)n_in; (void)out_size;
    const float* X  = (const float*)d_in[0];
    const float* LO = (const float*)d_in[1];
    const float* HI = (const float*)d_in[2];
    const float* W[5];
    const float* Bv[5];
    for (int i = 0; i < 5; i++) {
        W[i]  = (const float*)d_in[3 + 2 * i];
        Bv[i] = (const float*)d_in[4 + 2 * i];
    }
    float* out = (float*)d_out;

    float *x0, *l0, *h0, *z, *act, *low, *high, *b2, *gp, *sP, *sQ, *sb2, *part;
    float *wlv, *whv, *bhrv;
    float4* packv;
    unsigned short *TA, *TB;
    unsigned short *Wf[4];
    cudaGetSymbolAddress((void**)&x0, g_x0);
    cudaGetSymbolAddress((void**)&l0, g_l0);
    cudaGetSymbolAddress((void**)&h0, g_h0);
    cudaGetSymbolAddress((void**)&z, g_z);
    cudaGetSymbolAddress((void**)&act, g_act);
    cudaGetSymbolAddress((void**)&low, g_low);
    cudaGetSymbolAddress((void**)&high, g_high);
    cudaGetSymbolAddress((void**)&b2, g_b2);
    cudaGetSymbolAddress((void**)&gp, g_gp);
    cudaGetSymbolAddress((void**)&sP, g_sP);
    cudaGetSymbolAddress((void**)&sQ, g_sQ);
    cudaGetSymbolAddress((void**)&sb2, g_sb2);
    cudaGetSymbolAddress((void**)&part, g_part);
    cudaGetSymbolAddress((void**)&wlv, g_wl);
    cudaGetSymbolAddress((void**)&whv, g_wh);
    cudaGetSymbolAddress((void**)&bhrv, g_bhr);
    cudaGetSymbolAddress((void**)&packv, g_pack);
    cudaGetSymbolAddress((void**)&TA, g_TA);
    cudaGetSymbolAddress((void**)&TB, g_TB);
    cudaGetSymbolAddress((void**)&Wf[0], g_Wf0);
    cudaGetSymbolAddress((void**)&Wf[1], g_Wf1);
    cudaGetSymbolAddress((void**)&Wf[2], g_Wf2);
    cudaGetSymbolAddress((void**)&Wf[3], g_Wf3);

    cudaFuncSetAttribute(tc_gemm_f, cudaFuncAttributeMaxDynamicSharedMemorySize, TCG_SMEM);

    int totQ = W0Q + 3 * WHQ;
    wt_half_all<<<(totQ + 255) / 256, 256>>>(W[0], W[1], W[2], W[3],
                                             Wf[0], Wf[1], Wf[2], Wf[3]);
    norm_k<<<4, 256>>>(X, LO, HI, x0, l0, h0);

    // ---- layer 1 ----
    gemv_fwd<<<FCH, 128>>>(W[0], x0, Bv[0], z, FC0);
    bounds1_relu_k<<<FCH, 128>>>(W[0], Bv[0], l0, h0, z, low, high, act,
                                 wlv, whv, bhrv, packv, Bv[0]);

    // ---- layers 2..4: stacked chains with fused-epilogue GEMMs ----
    for (int i = 1; i <= 3; i++) {
        gemv_fwd<<<FCH, 128>>>(W[i], act, Bv[i], z, FCH);
        transform_s_k<<<2 * FCH, 128>>>(Wf[i], packv + (size_t)(i - 1) * FCH, Bv[i], TA, b2);
        unsigned short* cur = TA;
        unsigned short* oth = TB;
        for (int j = i - 1; j >= 1; j--) {
            dim3 grid(FCH / 128, 2 * FCH / 128);
            tc_gemm_f<<<grid, 256, TCG_SMEM>>>(cur, Wf[j], oth,
                                               packv + (size_t)(j - 1) * FCH,
                                               nullptr, nullptr, gp, FCH, 1);
            bias_red_k<<<2 * FCH / 256, 256>>>(b2, gp, FCH / 128);
            unsigned short* t = cur; cur = oth; oth = t;
        }
        {
            dim3 grid((FC0 + 127) / 128, 2 * FCH / 128);
            tc_gemm_f<<<grid, 256, TCG_SMEM>>>(cur, Wf[0], nullptr, nullptr,
                                               l0, h0, gp, FC0, 2);
        }
        bounds_red_k<<<FCH / 256, 256>>>(b2, gp, (FC0 + 127) / 128, z, low, high, act,
                                         wlv + i * FCH, whv + i * FCH, bhrv + i * FCH,
                                         packv + (size_t)i * FCH, Bv[i]);
    }

    // ---- layer 5: stacked 20-row skinny chain ----
    gemv_fwd<<<FCOUT, 128>>>(W[4], act, Bv[4], z, FCH);
    {
        const float* bL = Bv[4];
        const float* bH = Bv[4];
        const float* cur = W[4];
        int shared = 1;
        for (int j = 3; j >= 0; j--) {
            transform20d_k<<<20, 128>>>(cur, shared, sQ, whv + j * FCH, wlv + j * FCH,
                                        bhrv + j * FCH, Bv[j], bL, bH, sb2);
            int Nn = (j == 0) ? FC0 : FCH;
            dim3 grid((Nn + 255) / 256, 16);
            sk_gemm20h<<<grid, 128>>>(sQ, Wf[j], part, FCH, Nn);
            sk_reduce20<<<(20 * Nn + 255) / 256, 256>>>(part, sP, Nn);
            cur = sP; shared = 0; bL = sb2; bH = sb2 + 10;
        }
        bounds2_k<<<20, 128>>>(sP, sb2, l0, h0, low, high, FC0, 10);
    }

    assemble_k<<<1, 32>>>(z, low, high, out);
}

// round 15
// speedup vs baseline: 5.9838x; 1.1202x over previous
#include <cuda_runtime.h>
#include <cuda_fp16.h>
#include <cstdint>

#define FC0   784
#define FCH   2048
#define FCOUT 10
#define SKSP  32

// ======================= helpers =======================
__device__ __forceinline__ uint32_t smem_u32(const void* p) {
    uint32_t a;
    asm("{ .reg .u64 t; cvta.to.shared.u64 t, %1; cvt.u32.u64 %0, t; }" : "=r"(a) : "l"(p));
    return a;
}

__device__ __forceinline__ void ldmatrix_x4(uint32_t* r, uint32_t addr) {
    asm volatile("ldmatrix.sync.aligned.m8n8.x4.shared.b16 {%0,%1,%2,%3}, [%4];"
                 : "=r"(r[0]), "=r"(r[1]), "=r"(r[2]), "=r"(r[3]) : "r"(addr));
}
__device__ __forceinline__ void ldmatrix_x4_trans(uint32_t* r, uint32_t addr) {
    asm volatile("ldmatrix.sync.aligned.m8n8.x4.trans.shared.b16 {%0,%1,%2,%3}, [%4];"
                 : "=r"(r[0]), "=r"(r[1]), "=r"(r[2]), "=r"(r[3]) : "r"(addr));
}

__device__ __forceinline__ void mma16816h(float* d, const uint32_t* a, const uint32_t* b) {
    asm volatile("mma.sync.aligned.m16n8k16.row.col.f32.f16.f16.f32 "
                 "{%0,%1,%2,%3}, {%4,%5,%6,%7}, {%8,%9}, {%0,%1,%2,%3};"
                 : "+f"(d[0]), "+f"(d[1]), "+f"(d[2]), "+f"(d[3])
                 : "r"(a[0]), "r"(a[1]), "r"(a[2]), "r"(a[3]), "r"(b[0]), "r"(b[1]));
}

__device__ __forceinline__ void cp_async16(uint32_t dst, const void* src, int sz) {
    asm volatile("cp.async.cg.shared.global [%0], [%1], 16, %2;"
                 :: "r"(dst), "l"(src), "r"(sz) : "memory");
}
#define CP_COMMIT() asm volatile("cp.async.commit_group;" ::: "memory")
#define CP_WAIT1()  asm volatile("cp.async.wait_group 1;" ::: "memory")

__device__ __forceinline__ float tf(float m, float4 p, int ishigh, float& s) {
    float tv = 0.f;
    if (p.x != 0.f) {
        float spos = ishigh ? p.x : p.y, sneg = ishigh ? p.y : p.x;
        tv = (m > 0.f) ? m * spos : m * sneg;
        s += (ishigh ? fmaxf(m, 0.f) : fminf(m, 0.f)) * p.z;
    }
    s += tv * p.w;
    return tv;
}
__device__ __forceinline__ void bf(float m, float lv, float hv, int ishigh, float& s) {
    float mn = fminf(m, 0.f), mp = fmaxf(m, 0.f);
    s += ishigh ? (mn * lv + mp * hv) : (mn * hv + mp * lv);
}

// ======================= scratch (static device globals) =======================
__device__ float g_x0[FC0], g_l0[FC0], g_h0[FC0];
__device__ float g_z[FCH], g_act[FCH];
__device__ float g_low[FCH], g_high[FCH];
__device__ float g_wl[4 * FCH], g_wh[4 * FCH], g_bhr[4 * FCH];
__device__ float4 g_pack[4 * FCH];
__device__ float g_b2[2 * FCH];
__device__ float g_gp[3 * 16 * 2 * FCH];      // slots: mode1 step0, step1, final
__device__ unsigned short g_TA[2 * FCH * FCH], g_TB[2 * FCH * FCH];
__device__ unsigned short g_Wf0[FCH * FC0];
__device__ unsigned short g_Wf1[FCH * FCH];
__device__ unsigned short g_Wf2[FCH * FCH];
__device__ unsigned short g_Wf3[FCH * FCH];
__device__ float g_sP[20 * FCH], g_sQ[20 * FCH], g_sb2[20];
__device__ float g_part[SKSP * 20 * FCH];

// ======================= small helper kernels =======================
__device__ __forceinline__ float blockReduceSum(float v) {
    __shared__ float sh[32];
    int lane = threadIdx.x & 31, wid = threadIdx.x >> 5;
#pragma unroll
    for (int o = 16; o > 0; o >>= 1) v += __shfl_down_sync(0xffffffffu, v, o);
    if (lane == 0) sh[wid] = v;
    __syncthreads();
    int nw = blockDim.x >> 5;
    v = (threadIdx.x < nw) ? sh[threadIdx.x] : 0.f;
    if (wid == 0) {
#pragma unroll
        for (int o = 16; o > 0; o >>= 1) v += __shfl_down_sync(0xffffffffu, v, o);
    }
    __syncthreads();
    return v;
}

__global__ void norm_k(const float* __restrict__ x, const float* __restrict__ lo,
                       const float* __restrict__ hi, float* __restrict__ x0,
                       float* __restrict__ l0, float* __restrict__ h0) {
    int i = blockIdx.x * blockDim.x + threadIdx.x;
    if (i < FC0) {
        const float mean = 0.1307f, stdv = 0.3081f;
        x0[i] = (x[i] - mean) / stdv;
        l0[i] = (lo[i] - mean) / stdv;
        h0[i] = (hi[i] - mean) / stdv;
    }
}

__global__ void gemv_fwd(const float* __restrict__ W, const float* __restrict__ xin,
                         const float* __restrict__ b, float* __restrict__ z, int K) {
    int row = blockIdx.x;
    const float4* Wr = (const float4*)(W + (size_t)row * K);
    const float4* X4 = (const float4*)xin;
    float s = 0.f;
    for (int k = threadIdx.x; k < (K >> 2); k += blockDim.x) {
        float4 w = Wr[k], xv = X4[k];
        s += w.x * xv.x + w.y * xv.y + w.z * xv.z + w.w * xv.w;
    }
    s = blockReduceSum(s);
    if (threadIdx.x == 0) z[row] = s + b[row];
}

__device__ __forceinline__ void relu_diag(float lo, float hi, float z,
                                          float* wl, float* wh, float* bhr,
                                          float* act, int i) {
    float w_h, w_l, b_h;
    if (lo < 0.f && hi > 0.f) {
        float d = hi - lo;
        w_h = hi / d;
        b_h = -(lo * hi) / d;
        w_l = (lo * lo > hi * hi) ? 0.f : 1.f;
    } else {
        float keep = (hi <= 0.f) ? 0.f : 1.f;
        w_h = keep; w_l = keep; b_h = 0.f;
    }
    wl[i] = w_l; wh[i] = w_h; bhr[i] = b_h;
    act[i] = fmaxf(z, 0.f);
}

// layer-1: both bounds from W1 + relu diag + pack0
__global__ void bounds1_relu_k(const float* __restrict__ W1, const float* __restrict__ b1,
                               const float* __restrict__ l0, const float* __restrict__ h0,
                               const float* __restrict__ z,
                               float* __restrict__ lowv, float* __restrict__ highv,
                               float* __restrict__ act, float* __restrict__ wl,
                               float* __restrict__ wh, float* __restrict__ bhr,
                               float4* __restrict__ packo, const float* __restrict__ blin) {
    int r = blockIdx.x;
    const float* Wr = W1 + (size_t)r * FC0;
    float sl = 0.f, sh = 0.f;
    for (int k = threadIdx.x; k < FC0; k += blockDim.x) {
        float m = Wr[k];
        float mn = fminf(m, 0.f), mp = fmaxf(m, 0.f);
        float lv = l0[k], hv = h0[k];
        sl += mn * hv + mp * lv;
        sh += mn * lv + mp * hv;
    }
    sl = blockReduceSum(sl);
    sh = blockReduceSum(sh);
    if (threadIdx.x == 0) {
        float lo = sl + b1[r], hi = sh + b1[r];
        lowv[r] = lo; highv[r] = hi;
        relu_diag(lo, hi, z[r], wl, wh, bhr, act, r);
        packo[r] = make_float4(wh[r], wl[r], bhr[r], blin[r]);
    }
}

// final reduction: bias slots + bound partials -> bounds + relu + pack
__global__ void bounds_red_k(const float* __restrict__ b2, const float* __restrict__ gp,
                             int n1, int nxF, const float* __restrict__ z,
                             float* __restrict__ lowv, float* __restrict__ highv,
                             float* __restrict__ act, float* __restrict__ wl,
                             float* __restrict__ wh, float* __restrict__ bhr,
                             float4* __restrict__ packo, const float* __restrict__ blin) {
    int r = blockIdx.x * 256 + threadIdx.x;
    if (r >= FCH) return;
    float sl = b2[r], sh = b2[FCH + r];
    for (int s = 0; s < n1; s++) {
        const float* g = gp + (size_t)s * 16 * 2 * FCH;
        for (int x = 0; x < 16; x++) {
            sl += g[(size_t)x * (2 * FCH) + r];
            sh += g[(size_t)x * (2 * FCH) + FCH + r];
        }
    }
    {
        const float* g = gp + (size_t)2 * 16 * 2 * FCH;
        for (int x = 0; x < nxF; x++) {
            sl += g[(size_t)x * (2 * FCH) + r];
            sh += g[(size_t)x * (2 * FCH) + FCH + r];
        }
    }
    lowv[r] = sl; highv[r] = sh;
    relu_diag(sl, sh, z[r], wl, wh, bhr, act, r);
    packo[r] = make_float4(wh[r], wl[r], bhr[r], blin[r]);
}

// skinny final bounds (fp32, 20 rows stacked)
__global__ void bounds2_k(const float* __restrict__ M, const float* __restrict__ bias,
                          const float* __restrict__ l0, const float* __restrict__ h0,
                          float* __restrict__ lowv, float* __restrict__ highv,
                          int K, int half) {
    int row = blockIdx.x;
    int is_high = row >= half;
    int r = is_high ? row - half : row;
    const float* Mr = M + (size_t)row * K;
    float s = 0.f;
    for (int k = threadIdx.x; k < K; k += blockDim.x) {
        float m = Mr[k];
        float mn = fminf(m, 0.f), mp = fmaxf(m, 0.f);
        float lv = l0[k], hv = h0[k];
        s += is_high ? (mn * lv + mp * hv) : (mn * hv + mp * lv);
    }
    s = blockReduceSum(s);
    if (threadIdx.x == 0) {
        float* dst = is_high ? highv : lowv;
        dst[r] = s + bias[row];
    }
}

// all four weight conversions in one kernel
#define W0Q (FCH * FC0 / 4)
#define WHQ (FCH * FCH / 4)
__global__ void wt_half_all(const float* __restrict__ W0, const float* __restrict__ W1,
                            const float* __restrict__ W2, const float* __restrict__ W3,
                            unsigned short* __restrict__ F0, unsigned short* __restrict__ F1,
                            unsigned short* __restrict__ F2, unsigned short* __restrict__ F3) {
    int i = blockIdx.x * blockDim.x + threadIdx.x;
    const float* src; unsigned short* dst; int off;
    if (i < W0Q)                { src = W0; dst = F0; off = i; }
    else if (i < W0Q + WHQ)     { src = W1; dst = F1; off = i - W0Q; }
    else if (i < W0Q + 2 * WHQ) { src = W2; dst = F2; off = i - W0Q - WHQ; }
    else if (i < W0Q + 3 * WHQ) { src = W3; dst = F3; off = i - W0Q - 2 * WHQ; }
    else return;
    float4 v = ((const float4*)src)[off];
    __half h0 = __float2half_rn(v.x), h1 = __float2half_rn(v.y);
    __half h2 = __float2half_rn(v.z), h3 = __float2half_rn(v.w);
    uint2 uh;
    uh.x = (uint32_t)__half_as_ushort(h0) | ((uint32_t)__half_as_ushort(h1) << 16);
    uh.y = (uint32_t)__half_as_ushort(h2) | ((uint32_t)__half_as_ushort(h3) << 16);
    ((uint2*)dst)[off] = uh;
}

// standalone transform for the FIRST chain step
__global__ void transform_s_k(const unsigned short* __restrict__ Mh,
                              const float4* __restrict__ pack,
                              const float* __restrict__ bIn,
                              unsigned short* __restrict__ TAp, float* __restrict__ b2) {
    int row = blockIdx.x;            // 0..4095
    int is_high = row >= FCH;
    int r = row & (FCH - 1);
    const __half2* Mr = (const __half2*)(Mh + (size_t)r * FCH);
    uint32_t* TH = (uint32_t*)(TAp + (size_t)row * FCH);
    float s = 0.f;
    for (int k2 = threadIdx.x; k2 < FCH / 2; k2 += 128) {
        float2 m = __half22float2(Mr[k2]);
        float4 p0 = pack[k2 * 2], p1 = pack[k2 * 2 + 1];
        float t0 = tf(m.x, p0, is_high, s);
        float t1 = tf(m.y, p1, is_high, s);
        __half h0 = __float2half_rn(t0), h1 = __float2half_rn(t1);
        TH[k2] = (uint32_t)__half_as_ushort(h0) | ((uint32_t)__half_as_ushort(h1) << 16);
    }
    s = blockReduceSum(s);
    if (threadIdx.x == 0) b2[row] = bIn[r] + s;
}

// dense fp32 transform for skinny (20-row) chain
__global__ void transform20d_k(const float* __restrict__ Mraw, int shared_src,
                               float* __restrict__ TA,
                               const float* __restrict__ whv, const float* __restrict__ wlv,
                               const float* __restrict__ bhrv, const float* __restrict__ blin,
                               const float* __restrict__ biasL, const float* __restrict__ biasH,
                               float* __restrict__ bias_out) {
    int row = blockIdx.x;
    int is_high = row >= 10;
    int r = is_high ? row - 10 : row;
    int srow = shared_src ? r : row;
    const float* Mr = Mraw + (size_t)srow * FCH;
    float s = 0.f;
    for (int k = threadIdx.x; k < FCH; k += 128) {
        float mm = Mr[k];
        float hh = whv[k], ll = wlv[k];
        float tv = 0.f;
        if (hh != 0.f) {
            float spos = is_high ? hh : ll, sneg = is_high ? ll : hh;
            tv = (mm > 0.f) ? mm * spos : mm * sneg;
            float p = is_high ? fmaxf(mm, 0.f) : fminf(mm, 0.f);
            s += p * bhrv[k];
        }
        s += tv * blin[k];
        TA[(size_t)row * FCH + k] = tv;
    }
    s = blockReduceSum(s);
    if (threadIdx.x == 0)
        bias_out[row] = (is_high ? biasH[r] : biasL[r]) + s;
}

// ======================= fused fp16 GEMM =======================
#define ROWB   144
#define A_MATB (128 * ROWB)
#define ROWN   272
#define B_MATB (64 * ROWN)
#define STAGEB (A_MATB + B_MATB)
#define TCG_SMEM (2 * STAGEB)
#define NCHK   32

__global__ __launch_bounds__(256, 2) void tc_gemm_f(
    const unsigned short* __restrict__ Ain, const unsigned short* __restrict__ Bf,
    unsigned short* __restrict__ Tout, const float4* __restrict__ pack,
    const float* __restrict__ l0v, const float* __restrict__ h0v,
    float* __restrict__ gpart, int N, int mode) {
    extern __shared__ char smem[];
    const uint32_t sbase = smem_u32(smem);
    const int tid = threadIdx.x, lane = tid & 31, wid = tid >> 5;
    const int wm = wid & 1, wn = wid >> 1;
    const int m0 = blockIdx.y * 128, n0 = blockIdx.x * 128;

    auto fill = [&](int stage, int kc) {
        int k0 = kc * 64;
        uint32_t sb = sbase + stage * STAGEB;
#pragma unroll
        for (int i = 0; i < 8; i++) {
            int c = tid + i * 256;
            if (c < 1024) {
                int row = c >> 3, seg = c & 7;
                uint32_t dst = sb + row * ROWB + seg * 16;
                const unsigned short* src = Ain + (size_t)(m0 + row) * FCH + k0 + seg * 8;
                cp_async16(dst, src, 16);
            } else {
                int d = c - 1024;
                int r = d >> 4, seg = d & 15;
                uint32_t dst = sb + A_MATB + r * ROWN + seg * 16;
                int gc = n0 + seg * 8;
                const unsigned short* src = Bf + (size_t)(k0 + r) * N + gc;
                cp_async16(dst, src, (gc < N) ? 16 : 0);
            }
        }
    };

    float acc[4][4][4];
#pragma unroll
    for (int a = 0; a < 4; a++)
#pragma unroll
        for (int b = 0; b < 4; b++)
#pragma unroll
            for (int q = 0; q < 4; q++) acc[a][b][q] = 0.f;

    fill(0, 0); CP_COMMIT();
    fill(1, 1); CP_COMMIT();

    const int a_r = (lane & 7) + ((lane >> 3) & 1) * 8;
    const int a_s = lane >> 4;
    const int b_g = lane >> 3, b_r = lane & 7;

    int st = 0;
    for (int t = 0; t < NCHK; t++) {
        CP_WAIT1();
        __syncthreads();
        uint32_t sb = sbase + st * STAGEB;
        uint32_t aB = sb, bB = sb + A_MATB;
#pragma unroll
        for (int kk = 0; kk < 4; kk++) {
            uint32_t ah[4][4], bh[4][2];
#pragma unroll
            for (int mt = 0; mt < 4; mt++) {
                int row = wm * 64 + mt * 16 + a_r;
                ldmatrix_x4(ah[mt], aB + (uint32_t)row * ROWB + kk * 32 + a_s * 16);
            }
#pragma unroll
            for (int p = 0; p < 2; p++) {
                int nw = wn * 32 + p * 16;
                uint32_t off = (uint32_t)(kk * 16 + (b_g & 1) * 8 + b_r) * ROWN
                             + (uint32_t)(nw + (b_g >> 1) * 8) * 2;
                uint32_t r4[4];
                ldmatrix_x4_trans(r4, bB + off);
                bh[2 * p][0] = r4[0]; bh[2 * p][1] = r4[1];
                bh[2 * p + 1][0] = r4[2]; bh[2 * p + 1][1] = r4[3];
            }
#pragma unroll
            for (int mt = 0; mt < 4; mt++)
#pragma unroll
                for (int nt = 0; nt < 4; nt++)
                    mma16816h(acc[mt][nt], ah[mt], bh[nt]);
        }
        __syncthreads();
        if (t + 2 < NCHK) fill(st, t + 2);
        CP_COMMIT();
        st ^= 1;
    }

    // ---------------- fused epilogue ----------------
    const int rL = wm * 64 + (lane >> 2);
    const int cb = n0 + wn * 32 + (lane & 3) * 2;
    const int ishigh = (m0 >= FCH);
    float s[8];
#pragma unroll
    for (int q = 0; q < 8; q++) s[q] = 0.f;

    if (mode == 1) {
#pragma unroll
        for (int nt = 0; nt < 4; nt++) {
            int c = cb + nt * 8;
            float4 p0 = pack[c], p1 = pack[c + 1];
#pragma unroll
            for (int mt = 0; mt < 4; mt++) {
                float t0 = tf(acc[mt][nt][0], p0, ishigh, s[mt * 2]);
                float t1 = tf(acc[mt][nt][1], p1, ishigh, s[mt * 2]);
                float t2 = tf(acc[mt][nt][2], p0, ishigh, s[mt * 2 + 1]);
                float t3 = tf(acc[mt][nt][3], p1, ishigh, s[mt * 2 + 1]);
                int r = m0 + rL + mt * 16;
                *(__half2*)(Tout + (size_t)r * FCH + c) = __floats2half2_rn(t0, t1);
                *(__half2*)(Tout + (size_t)(r + 8) * FCH + c) = __floats2half2_rn(t2, t3);
            }
        }
    } else {
#pragma unroll
        for (int nt = 0; nt < 4; nt++) {
            int c = cb + nt * 8;
            if (c + 1 < N) {
                float lv0 = l0v[c], hv0 = h0v[c], lv1 = l0v[c + 1], hv1 = h0v[c + 1];
#pragma unroll
                for (int mt = 0; mt < 4; mt++) {
                    bf(acc[mt][nt][0], lv0, hv0, ishigh, s[mt * 2]);
                    bf(acc[mt][nt][1], lv1, hv1, ishigh, s[mt * 2]);
                    bf(acc[mt][nt][2], lv0, hv0, ishigh, s[mt * 2 + 1]);
                    bf(acc[mt][nt][3], lv1, hv1, ishigh, s[mt * 2 + 1]);
                }
            }
        }
    }
    __syncthreads();
    float* sred = (float*)smem;   // [128][4]
#pragma unroll
    for (int mt = 0; mt < 4; mt++)
#pragma unroll
        for (int h = 0; h < 2; h++) {
            float v = s[mt * 2 + h];
            v += __shfl_xor_sync(0xffffffffu, v, 1);
            v += __shfl_xor_sync(0xffffffffu, v, 2);
            if ((lane & 3) == 0)
                sred[(wm * 64 + mt * 16 + h * 8 + (lane >> 2)) * 4 + wn] = v;
        }
    __syncthreads();
    if (tid < 128)
        gpart[(size_t)blockIdx.x * (2 * FCH) + m0 + tid] =
            sred[tid * 4 + 0] + sred[tid * 4 + 1] + sred[tid * 4 + 2] + sred[tid * 4 + 3];
}

// ------------- skinny GEMM (20 rows, fp16 weights, 32 k-splits, 256 thr) -------------
__global__ void sk_gemm20h(const float* __restrict__ TA, const unsigned short* __restrict__ Bf,
                           float* __restrict__ part, int K, int N) {
    __shared__ float sTA[20][64];
    int tid = threadIdx.x;           // 256
    int kb = blockIdx.y;             // 0..31
    int kbase = kb * 64;
    int col0 = blockIdx.x * 512 + tid * 2;
    for (int i2 = tid; i2 < 20 * 64; i2 += 256) {
        int r = i2 >> 6, k = i2 & 63;
        sTA[r][k] = TA[(size_t)r * K + kbase + k];
    }
    __syncthreads();
    if (col0 >= N) return;
    float2 acc[20];
#pragma unroll
    for (int r = 0; r < 20; r++) acc[r] = make_float2(0.f, 0.f);
#pragma unroll 4
    for (int k = 0; k < 64; k++) {
        __half2 bh = *(const __half2*)(Bf + (size_t)(kbase + k) * N + col0);
        float2 bv = __half22float2(bh);
#pragma unroll
        for (int r = 0; r < 20; r++) {
            float sv = sTA[r][k];
            acc[r].x += sv * bv.x;
            acc[r].y += sv * bv.y;
        }
    }
#pragma unroll
    for (int r = 0; r < 20; r++)
        *(float2*)(part + (size_t)(kb * 20 + r) * N + col0) = acc[r];
}

__global__ void sk_reduce20(const float* __restrict__ part, float* __restrict__ C, int N) {
    int i = blockIdx.x * blockDim.x + threadIdx.x;
    if (i >= 20 * N) return;
    int r = i / N, c = i - r * N;
    float s = 0.f;
#pragma unroll
    for (int ks = 0; ks < SKSP; ks++) s += part[(size_t)(ks * 20 + r) * N + c];
    C[(size_t)r * N + c] = s;
}

__global__ void assemble_k(const float* __restrict__ z, const float* __restrict__ low,
                           const float* __restrict__ high, float* __restrict__ out) {
    int i = threadIdx.x;
    if (i < FCOUT) {
        out[i]      = z[i];
        out[10 + i] = low[i];
        out[20 + i] = high[i];
    }
}

// =======================================================================
extern "C" void kernel_launch(void* const* d_in, const int* in_sizes, int n_in,
                              void* d_out, int out_size) {
    (void)in_sizes; (void)n_in; (void)out_size;
    const float* X  = (const float*)d_in[0];
    const float* LO = (const float*)d_in[1];
    const float* HI = (const float*)d_in[2];
    const float* W[5];
    const float* Bv[5];
    for (int i = 0; i < 5; i++) {
        W[i]  = (const float*)d_in[3 + 2 * i];
        Bv[i] = (const float*)d_in[4 + 2 * i];
    }
    float* out = (float*)d_out;

    float *x0, *l0, *h0, *z, *act, *low, *high, *b2, *gp, *sP, *sQ, *sb2, *part;
    float *wlv, *whv, *bhrv;
    float4* packv;
    unsigned short *TA, *TB;
    unsigned short *Wf[4];
    cudaGetSymbolAddress((void**)&x0, g_x0);
    cudaGetSymbolAddress((void**)&l0, g_l0);
    cudaGetSymbolAddress((void**)&h0, g_h0);
    cudaGetSymbolAddress((void**)&z, g_z);
    cudaGetSymbolAddress((void**)&act, g_act);
    cudaGetSymbolAddress((void**)&low, g_low);
    cudaGetSymbolAddress((void**)&high, g_high);
    cudaGetSymbolAddress((void**)&b2, g_b2);
    cudaGetSymbolAddress((void**)&gp, g_gp);
    cudaGetSymbolAddress((void**)&sP, g_sP);
    cudaGetSymbolAddress((void**)&sQ, g_sQ);
    cudaGetSymbolAddress((void**)&sb2, g_sb2);
    cudaGetSymbolAddress((void**)&part, g_part);
    cudaGetSymbolAddress((void**)&wlv, g_wl);
    cudaGetSymbolAddress((void**)&whv, g_wh);
    cudaGetSymbolAddress((void**)&bhrv, g_bhr);
    cudaGetSymbolAddress((void**)&packv, g_pack);
    cudaGetSymbolAddress((void**)&TA, g_TA);
    cudaGetSymbolAddress((void**)&TB, g_TB);
    cudaGetSymbolAddress((void**)&Wf[0], g_Wf0);
    cudaGetSymbolAddress((void**)&Wf[1], g_Wf1);
    cudaGetSymbolAddress((void**)&Wf[2], g_Wf2);
    cudaGetSymbolAddress((void**)&Wf[3], g_Wf3);

    cudaFuncSetAttribute(tc_gemm_f, cudaFuncAttributeMaxDynamicSharedMemorySize, TCG_SMEM);

    int totQ = W0Q + 3 * WHQ;
    wt_half_all<<<(totQ + 255) / 256, 256>>>(W[0], W[1], W[2], W[3],
                                             Wf[0], Wf[1], Wf[2], Wf[3]);
    norm_k<<<4, 256>>>(X, LO, HI, x0, l0, h0);

    // ---- layer 1 ----
    gemv_fwd<<<FCH, 128>>>(W[0], x0, Bv[0], z, FC0);
    bounds1_relu_k<<<FCH, 128>>>(W[0], Bv[0], l0, h0, z, low, high, act,
                                 wlv, whv, bhrv, packv, Bv[0]);

    // ---- layers 2..4: stacked chains with fused-epilogue GEMMs ----
    const int GPSTEP = 16 * 2 * FCH;
    for (int i = 1; i <= 3; i++) {
        gemv_fwd<<<FCH, 128>>>(W[i], act, Bv[i], z, FCH);
        transform_s_k<<<2 * FCH, 128>>>(Wf[i], packv + (size_t)(i - 1) * FCH, Bv[i], TA, b2);
        unsigned short* cur = TA;
        unsigned short* oth = TB;
        int s = 0;
        for (int j = i - 1; j >= 1; j--) {
            dim3 grid(FCH / 128, 2 * FCH / 128);
            tc_gemm_f<<<grid, 256, TCG_SMEM>>>(cur, Wf[j], oth,
                                               packv + (size_t)(j - 1) * FCH,
                                               nullptr, nullptr, gp + (size_t)s * GPSTEP,
                                               FCH, 1);
            s++;
            unsigned short* t = cur; cur = oth; oth = t;
        }
        {
            dim3 grid((FC0 + 127) / 128, 2 * FCH / 128);
            tc_gemm_f<<<grid, 256, TCG_SMEM>>>(cur, Wf[0], nullptr, nullptr,
                                               l0, h0, gp + (size_t)2 * GPSTEP, FC0, 2);
        }
        bounds_red_k<<<FCH / 256, 256>>>(b2, gp, i - 1, (FC0 + 127) / 128, z,
                                         low, high, act,
                                         wlv + i * FCH, whv + i * FCH, bhrv + i * FCH,
                                         packv + (size_t)i * FCH, Bv[i]);
    }

    // ---- layer 5: stacked 20-row skinny chain ----
    gemv_fwd<<<FCOUT, 128>>>(W[4], act, Bv[4], z, FCH);
    {
        const float* bL = Bv[4];
        const float* bH = Bv[4];
        const float* cur = W[4];
        int shared = 1;
        for (int j = 3; j >= 0; j--) {
            transform20d_k<<<20, 128>>>(cur, shared, sQ, whv + j * FCH, wlv + j * FCH,
                                        bhrv + j * FCH, Bv[j], bL, bH, sb2);
            int Nn = (j == 0) ? FC0 : FCH;
            dim3 grid((Nn + 511) / 512, SKSP);
            sk_gemm20h<<<grid, 256>>>(sQ, Wf[j], part, FCH, Nn);
            sk_reduce20<<<(20 * Nn + 255) / 256, 256>>>(part, sP, Nn);
            cur = sP; shared = 0; bL = sb2; bH = sb2 + 10;
        }
        bounds2_k<<<20, 128>>>(sP, sb2, l0, h0, low, high, FC0, 10);
    }

    assemble_k<<<1, 32>>>(z, low, high, out);
}